// round 10
// baseline (speedup 1.0000x reference)
#include <cuda_runtime.h>
#include <cuda_bf16.h>
#include <cooperative_groups.h>
#include <math.h>

namespace cg = cooperative_groups;

#define B_    32
#define N_IMG 196
#define M_TOK 256
#define D_    1024
#define NM    (N_IMG*M_TOK)
#define KPAD  224

// ---------------- device scratch (allocation-free) ----------------
__device__ __nv_bfloat16 g_xh[B_*N_IMG*D_];
__device__ __nv_bfloat16 g_xl[B_*N_IMG*D_];
__device__ __nv_bfloat16 g_yh[B_*M_TOK*D_];
__device__ __nv_bfloat16 g_yl[B_*M_TOK*D_];
__device__ float g_Cxy[B_*NM];
__device__ float g_Cs [B_*N_IMG*N_IMG];
__device__ float g_Ct [B_*M_TOK*M_TOK];
__device__ __nv_bfloat16 g_Csh[B_*N_IMG*KPAD];
__device__ __nv_bfloat16 g_Csl[B_*N_IMG*KPAD];
__device__ __nv_bfloat16 g_Cth[B_*M_TOK*M_TOK];
__device__ __nv_bfloat16 g_Ctl[B_*M_TOK*M_TOK];
__device__ __nv_bfloat16 g_gamh[B_*NM];
__device__ __nv_bfloat16 g_gaml[B_*NM];
__device__ __nv_bfloat16 g_tmph[B_*NM];
__device__ __nv_bfloat16 g_tmpl[B_*NM];
__device__ float g_Cg[B_*NM];
__device__ float g_cstrow[B_*N_IMG];
__device__ float g_cstcol[B_*M_TOK];
__device__ unsigned g_minmax[6];
__device__ float g_dotwd[B_];
__device__ float g_dotgw[B_];

__device__ __forceinline__ unsigned enc_mono(float f){
    unsigned u = __float_as_uint(f);
    return (u & 0x80000000u) ? ~u : (u | 0x80000000u);
}
__device__ __forceinline__ float dec_mono(unsigned e){
    unsigned u = (e & 0x80000000u) ? (e ^ 0x80000000u) : ~e;
    return __uint_as_float(u);
}
__device__ __forceinline__ uint32_t smem_u32(const void* p){
    uint32_t a;
    asm("{ .reg .u64 t; cvta.to.shared.u64 t, %1; cvt.u32.u64 %0, t; }" : "=r"(a) : "l"(p));
    return a;
}
__device__ __forceinline__ void ldm_x4(unsigned* r, uint32_t addr){
    asm volatile("ldmatrix.sync.aligned.m8n8.x4.shared.b16 {%0,%1,%2,%3}, [%4];"
        : "=r"(r[0]), "=r"(r[1]), "=r"(r[2]), "=r"(r[3]) : "r"(addr));
}
__device__ __forceinline__ void ldm_x4_t(unsigned* r, uint32_t addr){
    asm volatile("ldmatrix.sync.aligned.m8n8.x4.trans.shared.b16 {%0,%1,%2,%3}, [%4];"
        : "=r"(r[0]), "=r"(r[1]), "=r"(r[2]), "=r"(r[3]) : "r"(addr));
}
__device__ __forceinline__ void mma_bf16(float* d, const unsigned* a, unsigned b0, unsigned b1){
    asm volatile("mma.sync.aligned.m16n8k16.row.col.f32.bf16.bf16.f32 "
        "{%0,%1,%2,%3}, {%4,%5,%6,%7}, {%8,%9}, {%0,%1,%2,%3};"
        : "+f"(d[0]), "+f"(d[1]), "+f"(d[2]), "+f"(d[3])
        : "r"(a[0]), "r"(a[1]), "r"(a[2]), "r"(a[3]), "r"(b0), "r"(b1));
}
__device__ __forceinline__ void split_bf16(float v, __nv_bfloat16& h, __nv_bfloat16& l){
    h = __float2bfloat16(v);
    l = __float2bfloat16(v - __bfloat162float(h));
}
__device__ __forceinline__ void cp16(uint32_t d, const void* s, bool v){
    int sz = v ? 16 : 0;
    asm volatile("cp.async.ca.shared.global [%0], [%1], 16, %2;" :: "r"(d), "l"(s), "r"(sz));
}
#define CP_COMMIT() asm volatile("cp.async.commit_group;" ::: "memory")
#define CP_WAIT1()  asm volatile("cp.async.wait_group 1;" ::: "memory")
#define CP_WAIT0()  asm volatile("cp.async.wait_group 0;" ::: "memory")

// ---------------- init ----------------
__global__ void init_kernel(){
    int t = threadIdx.x;
    if (t < 3){ g_minmax[2*t] = 0xFFFFFFFFu; g_minmax[2*t+1] = 0u; }
    if (t < B_) g_dotgw[t] = 0.f;
}

// ---------------- merged normalize: img rows then tok rows ----------------
__global__ void normalize_kernel(const float* __restrict__ img,
                                 const float* __restrict__ tok,
                                 const float* __restrict__ tokmask,
                                 __nv_bfloat16* __restrict__ xh, __nv_bfloat16* __restrict__ xl,
                                 __nv_bfloat16* __restrict__ yh, __nv_bfloat16* __restrict__ yl)
{
    const int gb = blockIdx.x;
    const bool isTok = gb >= B_*N_IMG;
    const int bp = isTok ? (gb - B_*N_IMG) : gb;
    const float* v = (isTok ? tok : img) + (size_t)bp * D_;
    float mk = 1.0f;
    if (isTok) mk = tokmask[bp];
    __nv_bfloat16* oh = isTok ? yh : xh;
    __nv_bfloat16* ol = isTok ? yl : xl;

    float ss = 0.f;
    for (int d = threadIdx.x; d < D_; d += blockDim.x){
        float t = v[d] * mk;
        ss += t*t;
    }
    #pragma unroll
    for (int o = 16; o; o >>= 1) ss += __shfl_xor_sync(0xffffffffu, ss, o);
    __shared__ float sred[8];
    if ((threadIdx.x & 31) == 0) sred[threadIdx.x >> 5] = ss;
    __syncthreads();
    __shared__ float s_inv;
    if (threadIdx.x == 0){
        float t = 0.f;
        for (int w = 0; w < 8; ++w) t += sred[w];
        s_inv = 1.0f / (sqrtf(t) + 1e-12f);
    }
    __syncthreads();
    const float scale = s_inv * mk;
    const size_t base = (size_t)bp * D_;
    for (int d = threadIdx.x; d < D_; d += blockDim.x){
        float t = v[d] * scale;
        __nv_bfloat16 hi, lo; split_bf16(t, hi, lo);
        oh[base + d] = hi;
        ol[base + d] = lo;
    }
}

// ============ merged cosine GEMMs: CTA tile 64x256, warp tile 32x64, 3-stage ============
// grid (12, 1, B_): tile = blockIdx.x; which = tile>>2 (0 Cxy, 1 Cs, 2 Ct); m0 = (tile&3)*64
// per-buffer (51200 B): AH[0,5120) AL[5120,10240) BH[10240,30720) BL[30720,51200)
#define LDT 40
#define COS_DSM (3*51200)

__global__ void __launch_bounds__(256,1)
cosmma_kernel(const __nv_bfloat16* __restrict__ xh, const __nv_bfloat16* __restrict__ xl,
              const __nv_bfloat16* __restrict__ yh, const __nv_bfloat16* __restrict__ yl,
              float* __restrict__ Cxy, float* __restrict__ Cs, float* __restrict__ Ct)
{
    extern __shared__ char dyn[];
    const uint32_t sb = smem_u32(dyn);

    const int tile  = blockIdx.x;
    const int which = tile >> 2;
    const int b     = blockIdx.z;
    const int m0    = (tile & 3) * 64;

    const __nv_bfloat16* Ah = (which == 2) ? yh : xh;
    const __nv_bfloat16* Al = (which == 2) ? yl : xl;
    const __nv_bfloat16* Bh = (which == 1) ? xh : yh;
    const __nv_bfloat16* Bl = (which == 1) ? xl : yl;
    const int Mz = (which == 2) ? M_TOK : N_IMG;
    const int Nz = (which == 1) ? N_IMG : M_TOK;
    float* Cout = (which == 0) ? Cxy : ((which == 1) ? Cs : Ct);

    const int tid  = threadIdx.x;
    const int lane = tid & 31;
    const int wid  = tid >> 5;
    const int wm   = wid >> 2;           // 0..1 (32 rows)
    const int wn   = wid & 3;            // 0..3 (64 cols)

    const size_t abase = (size_t)b * Mz * D_;
    const size_t bbase = (size_t)b * Nz * D_;

    const int a_row = tid >> 2, a_quad = tid & 3;
    const bool avalid = (m0 + a_row) < Mz;
    const uint32_t aoff = (uint32_t)((a_row*LDT + a_quad*8) * 2);

    const int arow_l = lane & 15, ahalf = lane >> 4;
    const int bg = lane >> 3;
    const int b_noff = ((bg >> 1) << 3) + (lane & 7);
    const int b_koff = (bg & 1) << 3;

    float acc[2][8][4];
    #pragma unroll
    for (int mt = 0; mt < 2; ++mt)
        #pragma unroll
        for (int nt = 0; nt < 8; ++nt)
            #pragma unroll
            for (int q = 0; q < 4; ++q) acc[mt][nt][q] = 0.f;

    auto issue_tile = [&](int kc, int buf){
        const uint32_t base = sb + (uint32_t)buf*51200u;
        {
            const size_t go = abase + (size_t)(m0 + a_row)*D_ + kc*32 + a_quad*8;
            const size_t gs = avalid ? go : abase;
            cp16(base + aoff, Ah + gs, avalid);
            cp16(base + 5120u + aoff, Al + gs, avalid);
        }
        #pragma unroll
        for (int p = 0; p < 4; ++p){
            int idx = tid + p*256;
            int row = idx >> 2, quad = idx & 3;
            const bool bv = row < Nz;
            const size_t go = bbase + (size_t)row*D_ + kc*32 + quad*8;
            const size_t gs = bv ? go : bbase;
            const uint32_t so = (uint32_t)((row*LDT + quad*8) * 2);
            cp16(base + 10240u + so, Bh + gs, bv);
            cp16(base + 30720u + so, Bl + gs, bv);
        }
        CP_COMMIT();
    };

    issue_tile(0, 0);
    issue_tile(1, 1);
    for (int kc = 0; kc < 32; ++kc){
        if (kc == 31){ CP_WAIT0(); } else { CP_WAIT1(); }
        __syncthreads();
        if (kc + 2 < 32) issue_tile(kc + 2, (kc + 2) % 3);

        const uint32_t base = sb + (uint32_t)(kc % 3)*51200u;
        const uint32_t baAh = base;
        const uint32_t baAl = base + 5120u;
        const uint32_t baBh = base + 10240u;
        const uint32_t baBl = base + 30720u;

        #pragma unroll
        for (int k16 = 0; k16 < 2; ++k16){
            unsigned ah[2][4], al[2][4], bh[4][4], bl[4][4];
            #pragma unroll
            for (int mt = 0; mt < 2; ++mt){
                uint32_t off = (uint32_t)(((wm*32 + mt*16 + arow_l)*LDT + k16*16 + ahalf*8) * 2);
                ldm_x4(ah[mt], baAh + off);
                ldm_x4(al[mt], baAl + off);
            }
            #pragma unroll
            for (int nt2 = 0; nt2 < 4; ++nt2){
                uint32_t off = (uint32_t)(((wn*64 + nt2*16 + b_noff)*LDT + k16*16 + b_koff) * 2);
                ldm_x4(bh[nt2], baBh + off);
                ldm_x4(bl[nt2], baBl + off);
            }
            #pragma unroll
            for (int mt = 0; mt < 2; ++mt)
                #pragma unroll
                for (int nt = 0; nt < 8; ++nt){
                    const int p2 = nt >> 1, s2 = (nt & 1) * 2;
                    mma_bf16(acc[mt][nt], ah[mt], bh[p2][s2], bh[p2][s2+1]);
                    mma_bf16(acc[mt][nt], ah[mt], bl[p2][s2], bl[p2][s2+1]);
                    mma_bf16(acc[mt][nt], al[mt], bh[p2][s2], bh[p2][s2+1]);
                }
        }
    }

    float lmin =  3.402823466e+38f;
    float lmax = -3.402823466e+38f;
    #pragma unroll
    for (int mt = 0; mt < 2; ++mt){
        #pragma unroll
        for (int nt = 0; nt < 8; ++nt){
            const int ibase = m0 + wm*32 + mt*16 + (lane >> 2);
            const int jbase = wn*64 + nt*8 + (lane & 3)*2;
            #pragma unroll
            for (int rr = 0; rr < 2; ++rr){
                int i = ibase + rr*8;
                if (i >= Mz) continue;
                float* crow = Cout + ((size_t)b*Mz + i)*Nz;
                #pragma unroll
                for (int cc = 0; cc < 2; ++cc){
                    int j = jbase + cc;
                    if (j >= Nz) continue;
                    float v = 1.0f - acc[mt][nt][rr*2 + cc];
                    crow[j] = v;
                    lmin = fminf(lmin, v);
                    lmax = fmaxf(lmax, v);
                }
            }
        }
    }
    #pragma unroll
    for (int o = 16; o; o >>= 1){
        lmin = fminf(lmin, __shfl_xor_sync(0xffffffffu, lmin, o));
        lmax = fmaxf(lmax, __shfl_xor_sync(0xffffffffu, lmax, o));
    }
    if (lane == 0){
        atomicMin(&g_minmax[2*which],   enc_mono(lmin));
        atomicMax(&g_minmax[2*which+1], enc_mono(lmax));
    }
}

// ============ FUSED GW chain: tmp = Cs@gamma (smem), Cg = Cst - 2*tmp@Ct^T ============
#define LDP 264
#define GWF_DSM 155648

__global__ void __launch_bounds__(256,1)
gwfused_kernel(const __nv_bfloat16* __restrict__ Csh, const __nv_bfloat16* __restrict__ Csl,
               const __nv_bfloat16* __restrict__ Gh,  const __nv_bfloat16* __restrict__ Gl,
               const __nv_bfloat16* __restrict__ Cth, const __nv_bfloat16* __restrict__ Ctl,
               float* __restrict__ Cout,
               const float* __restrict__ rowadd, const float* __restrict__ coladd,
               const float* __restrict__ gamF, float* __restrict__ dotOut)
{
    extern __shared__ char dyn[];
    const uint32_t sb = smem_u32(dyn);
    const uint32_t TMPH = sb + 88064u;
    const uint32_t TMPL = sb + 121856u;

    const int tid  = threadIdx.x;
    const int lane = tid & 31;
    const int wid  = tid >> 5;
    const int wm   = wid >> 2;
    const int wn   = wid & 3;
    const int b    = blockIdx.z;
    const int m0   = blockIdx.x * 64;

    const int a_row = tid >> 2, a_quad = tid & 3;
    const bool avalid = (m0 + a_row) < N_IMG;
    const uint32_t aoff = (uint32_t)((a_row*LDT + a_quad*8) * 2);

    const int arow_l = lane & 15, ahalf = lane >> 4;
    const int bg = lane >> 3;
    const int b_noff = ((bg >> 1) << 3) + (lane & 7);
    const int b_koff = (bg & 1) << 3;
    const int ktr = ((lane >> 3) & 1)*8 + (lane & 7);
    const int ntr = (lane >> 4)*8;

    float acc[2][8][4];
    #pragma unroll
    for (int mt = 0; mt < 2; ++mt)
        #pragma unroll
        for (int nt = 0; nt < 8; ++nt)
            #pragma unroll
            for (int q = 0; q < 4; ++q) acc[mt][nt][q] = 0.f;

    auto issue1 = [&](int kc, int buf){
        const int kbase = kc*32;
        {
            const size_t go = ((size_t)b*N_IMG + (m0 + a_row))*KPAD + kbase + a_quad*8;
            const size_t gs = avalid ? go : (size_t)b*N_IMG*KPAD;
            cp16(sb + buf*5120u + aoff, Csh + gs, avalid);
            cp16(sb + 10240u + buf*5120u + aoff, Csl + gs, avalid);
        }
        #pragma unroll
        for (int p = 0; p < 4; ++p){
            int idx = tid + p*256;
            int kk = idx >> 5, nn = (idx & 31)*8;
            const bool bv = (kbase + kk) < N_IMG;
            const size_t go = ((size_t)b*N_IMG + kbase + kk)*M_TOK + nn;
            const size_t gs = bv ? go : (size_t)b*NM;
            const uint32_t so = (uint32_t)((kk*LDP + nn) * 2);
            cp16(sb + 20480u + buf*16896u + so, Gh + gs, bv);
            cp16(sb + 54272u + buf*16896u + so, Gl + gs, bv);
        }
        CP_COMMIT();
    };

    issue1(0, 0);
    for (int kc = 0; kc < 7; ++kc){
        if (kc < 6){ issue1(kc+1, (kc+1)&1); CP_WAIT1(); }
        else       { CP_WAIT0(); }
        __syncthreads();

        const int buf = kc & 1;
        const uint32_t baAh = sb + buf*5120u;
        const uint32_t baAl = sb + 10240u + buf*5120u;
        const uint32_t baBh = sb + 20480u + buf*16896u;
        const uint32_t baBl = sb + 54272u + buf*16896u;

        #pragma unroll
        for (int k16 = 0; k16 < 2; ++k16){
            unsigned ah[2][4], al[2][4], bh[4][4], bl[4][4];
            #pragma unroll
            for (int mt = 0; mt < 2; ++mt){
                uint32_t off = (uint32_t)(((wm*32 + mt*16 + arow_l)*LDT + k16*16 + ahalf*8) * 2);
                ldm_x4(ah[mt], baAh + off);
                ldm_x4(al[mt], baAl + off);
            }
            #pragma unroll
            for (int nt2 = 0; nt2 < 4; ++nt2){
                uint32_t off = (uint32_t)(((k16*16 + ktr)*LDP + wn*64 + nt2*16 + ntr) * 2);
                ldm_x4_t(bh[nt2], baBh + off);
                ldm_x4_t(bl[nt2], baBl + off);
            }
            #pragma unroll
            for (int mt = 0; mt < 2; ++mt)
                #pragma unroll
                for (int nt = 0; nt < 8; ++nt){
                    const int p2 = nt >> 1, s2 = (nt & 1) * 2;
                    mma_bf16(acc[mt][nt], ah[mt], bh[p2][s2], bh[p2][s2+1]);
                    mma_bf16(acc[mt][nt], ah[mt], bl[p2][s2], bl[p2][s2+1]);
                    mma_bf16(acc[mt][nt], al[mt], bh[p2][s2], bh[p2][s2+1]);
                }
        }
        __syncthreads();
    }

    auto issue2 = [&](int kc, int buf){
        #pragma unroll
        for (int p = 0; p < 4; ++p){
            int idx = tid + p*256;
            int row = idx >> 2, quad = idx & 3;
            const size_t go = ((size_t)b*M_TOK + row)*M_TOK + kc*32 + quad*8;
            const uint32_t so = (uint32_t)((row*LDT + quad*8) * 2);
            cp16(sb + buf*20480u + so, Cth + go, true);
            cp16(sb + 40960u + buf*20480u + so, Ctl + go, true);
        }
        CP_COMMIT();
    };
    issue2(0, 0);

    #pragma unroll
    for (int mt = 0; mt < 2; ++mt){
        #pragma unroll
        for (int nt = 0; nt < 8; ++nt){
            const int il = wm*32 + mt*16 + (lane >> 2);
            const int jb = wn*64 + nt*8 + (lane & 3)*2;
            #pragma unroll
            for (int rr = 0; rr < 2; ++rr){
                const int i = il + rr*8;
                #pragma unroll
                for (int cc = 0; cc < 2; ++cc){
                    const int j = jb + cc;
                    __nv_bfloat16 h, l;
                    split_bf16(acc[mt][nt][rr*2 + cc], h, l);
                    *reinterpret_cast<__nv_bfloat16*>((char*)dyn + 88064u + (i*LDP + j)*2) = h;
                    *reinterpret_cast<__nv_bfloat16*>((char*)dyn + 121856u + (i*LDP + j)*2) = l;
                }
            }
        }
    }
    issue2(1, 1);
    __syncthreads();

    #pragma unroll
    for (int mt = 0; mt < 2; ++mt)
        #pragma unroll
        for (int nt = 0; nt < 8; ++nt)
            #pragma unroll
            for (int q = 0; q < 4; ++q) acc[mt][nt][q] = 0.f;

    for (int kc = 0; kc < 8; ++kc){
        if (kc < 7){ issue2(kc+1, (kc+1)&1); CP_WAIT1(); }
        else       { CP_WAIT0(); }
        __syncthreads();

        const int buf = kc & 1;
        const uint32_t baBh = sb + buf*20480u;
        const uint32_t baBl = sb + 40960u + buf*20480u;

        #pragma unroll
        for (int k16 = 0; k16 < 2; ++k16){
            unsigned ah[2][4], al[2][4], bh[4][4], bl[4][4];
            #pragma unroll
            for (int mt = 0; mt < 2; ++mt){
                uint32_t off = (uint32_t)(((wm*32 + mt*16 + arow_l)*LDP + kc*32 + k16*16 + ahalf*8) * 2);
                ldm_x4(ah[mt], TMPH + off);
                ldm_x4(al[mt], TMPL + off);
            }
            #pragma unroll
            for (int nt2 = 0; nt2 < 4; ++nt2){
                uint32_t off = (uint32_t)(((wn*64 + nt2*16 + b_noff)*LDT + k16*16 + b_koff) * 2);
                ldm_x4(bh[nt2], baBh + off);
                ldm_x4(bl[nt2], baBl + off);
            }
            #pragma unroll
            for (int mt = 0; mt < 2; ++mt)
                #pragma unroll
                for (int nt = 0; nt < 8; ++nt){
                    const int p2 = nt >> 1, s2 = (nt & 1) * 2;
                    mma_bf16(acc[mt][nt], ah[mt], bh[p2][s2], bh[p2][s2+1]);
                    mma_bf16(acc[mt][nt], ah[mt], bl[p2][s2], bl[p2][s2+1]);
                    mma_bf16(acc[mt][nt], al[mt], bh[p2][s2], bh[p2][s2+1]);
                }
        }
        __syncthreads();
    }

    float dot = 0.f;
    #pragma unroll
    for (int mt = 0; mt < 2; ++mt){
        #pragma unroll
        for (int nt = 0; nt < 8; ++nt){
            const int ibase = m0 + wm*32 + mt*16 + (lane >> 2);
            const int jbase = wn*64 + nt*8 + (lane & 3)*2;
            #pragma unroll
            for (int rr = 0; rr < 2; ++rr){
                int i = ibase + rr*8;
                if (i >= N_IMG) continue;
                const size_t ro = ((size_t)b*N_IMG + i)*M_TOK;
                const float ra = rowadd[b*N_IMG + i];
                #pragma unroll
                for (int cc = 0; cc < 2; ++cc){
                    int j = jbase + cc;
                    float r = ra + coladd[b*M_TOK + j] - 2.0f*acc[mt][nt][rr*2 + cc];
                    Cout[ro + j] = r;
                    if (gamF) dot += r * gamF[ro + j];
                }
            }
        }
    }
    if (gamF){
        #pragma unroll
        for (int o = 16; o; o >>= 1) dot += __shfl_xor_sync(0xffffffffu, dot, o);
        if (lane == 0) atomicAdd(&dotOut[b], dot);
    }
}

// ============ GW GEMM 2 standalone (iter0) ============
#define GW2_DSM 61440

__global__ void __launch_bounds__(256,1)
gwmma2_kernel(const __nv_bfloat16* __restrict__ Ah, const __nv_bfloat16* __restrict__ Al,
              const __nv_bfloat16* __restrict__ Bh, const __nv_bfloat16* __restrict__ Bl,
              float* __restrict__ Cout,
              const float* __restrict__ rowadd, const float* __restrict__ coladd)
{
    extern __shared__ char dyn[];
    const uint32_t sb = smem_u32(dyn);

    const int tid  = threadIdx.x;
    const int lane = tid & 31;
    const int wid  = tid >> 5;
    const int wm   = wid >> 2;
    const int wn   = wid & 3;
    const int b    = blockIdx.z;
    const int m0   = blockIdx.y * 64;
    const int j0   = blockIdx.x * 128;

    const int a_row = tid >> 2, a_quad = tid & 3;
    const bool avalid = (m0 + a_row) < N_IMG;
    const uint32_t aoff = (uint32_t)((a_row*LDT + a_quad*8) * 2);

    const int arow_l = lane & 15, ahalf = lane >> 4;
    const int bg = lane >> 3;
    const int b_noff = ((bg >> 1) << 3) + (lane & 7);
    const int b_koff = (bg & 1) << 3;

    float acc[2][4][4];
    #pragma unroll
    for (int mt = 0; mt < 2; ++mt)
        #pragma unroll
        for (int nt = 0; nt < 4; ++nt)
            #pragma unroll
            for (int q = 0; q < 4; ++q) acc[mt][nt][q] = 0.f;

    auto issue_tile = [&](int kc, int buf){
        const uint32_t ah = sb + buf*5120u;
        const uint32_t al = sb + 10240u + buf*5120u;
        const uint32_t bh = sb + 20480u + buf*10240u;
        const uint32_t bl = sb + 40960u + buf*10240u;
        {
            const size_t go = ((size_t)b*N_IMG + (m0 + a_row))*M_TOK + kc*32 + a_quad*8;
            const size_t gs = avalid ? go : (size_t)b*NM;
            cp16(ah + aoff, Ah + gs, avalid);
            cp16(al + aoff, Al + gs, avalid);
        }
        #pragma unroll
        for (int p = 0; p < 2; ++p){
            int idx = tid + p*256;
            int row = idx >> 2, quad = idx & 3;
            const size_t go = ((size_t)b*M_TOK + j0 + row)*M_TOK + kc*32 + quad*8;
            const uint32_t so = (uint32_t)((row*LDT + quad*8) * 2);
            cp16(bh + so, Bh + go, true);
            cp16(bl + so, Bl + go, true);
        }
        CP_COMMIT();
    };

    issue_tile(0, 0);
    for (int kc = 0; kc < 8; ++kc){
        if (kc < 7){ issue_tile(kc+1, (kc+1)&1); CP_WAIT1(); }
        else       { CP_WAIT0(); }
        __syncthreads();

        const int buf = kc & 1;
        const uint32_t baAh = sb + buf*5120u;
        const uint32_t baAl = sb + 10240u + buf*5120u;
        const uint32_t baBh = sb + 20480u + buf*10240u;
        const uint32_t baBl = sb + 40960u + buf*10240u;

        #pragma unroll
        for (int k16 = 0; k16 < 2; ++k16){
            unsigned ah[2][4], al[2][4], bh[2][4], bl[2][4];
            #pragma unroll
            for (int mt = 0; mt < 2; ++mt){
                uint32_t off = (uint32_t)(((wm*32 + mt*16 + arow_l)*LDT + k16*16 + ahalf*8) * 2);
                ldm_x4(ah[mt], baAh + off);
                ldm_x4(al[mt], baAl + off);
            }
            #pragma unroll
            for (int nt2 = 0; nt2 < 2; ++nt2){
                uint32_t off = (uint32_t)(((wn*32 + nt2*16 + b_noff)*LDT + k16*16 + b_koff) * 2);
                ldm_x4(bh[nt2], baBh + off);
                ldm_x4(bl[nt2], baBl + off);
            }
            #pragma unroll
            for (int mt = 0; mt < 2; ++mt)
                #pragma unroll
                for (int nt = 0; nt < 4; ++nt){
                    const int p2 = nt >> 1, s2 = (nt & 1) * 2;
                    mma_bf16(acc[mt][nt], ah[mt], bh[p2][s2], bh[p2][s2+1]);
                    mma_bf16(acc[mt][nt], ah[mt], bl[p2][s2], bl[p2][s2+1]);
                    mma_bf16(acc[mt][nt], al[mt], bh[p2][s2], bh[p2][s2+1]);
                }
        }
        __syncthreads();
    }

    #pragma unroll
    for (int mt = 0; mt < 2; ++mt){
        #pragma unroll
        for (int nt = 0; nt < 4; ++nt){
            const int ibase = m0 + wm*32 + mt*16 + (lane >> 2);
            const int jbase = j0 + wn*32 + nt*8 + (lane & 3)*2;
            #pragma unroll
            for (int rr = 0; rr < 2; ++rr){
                int i = ibase + rr*8;
                if (i >= N_IMG) continue;
                const size_t ro = ((size_t)b*N_IMG + i)*M_TOK;
                const float ra = rowadd[b*N_IMG + i];
                #pragma unroll
                for (int cc = 0; cc < 2; ++cc){
                    int j = jbase + cc;
                    Cout[ro + j] = ra + coladd[b*M_TOK + j] - 2.0f*acc[mt][nt][rr*2 + cc];
                }
            }
        }
    }
}

// ---------------- fused Cs: thresh+mask+split(pad) + rowmeansq + rowsum->tmp ----------------
__global__ void fusedCs_kernel(float* __restrict__ Cs, const int* __restrict__ irm,
                               __nv_bfloat16* __restrict__ csh, __nv_bfloat16* __restrict__ csl,
                               float* __restrict__ crow,
                               __nv_bfloat16* __restrict__ tmph, __nv_bfloat16* __restrict__ tmpl)
{
    const float mn = dec_mono(g_minmax[2]);
    const float mx = dec_mono(g_minmax[3]);
    const float thr = mn + 0.1f*(mx - mn);
    const int r = blockIdx.x;
    const int t = threadIdx.x;

    float v = 0.f;
    if (t < N_IMG){
        size_t si = (size_t)r*N_IMG + t;
        v = Cs[si] - thr;
        v = v > 0.f ? v : 0.f;
        v *= (irm[si] == 1 ? 1.0f : 1e-5f);
        Cs[si] = v;
    }
    if (t < KPAD){
        __nv_bfloat16 h, l; split_bf16(v, h, l);
        csh[(size_t)r*KPAD + t] = h;
        csl[(size_t)r*KPAD + t] = l;
    }
    float ss = v*v, s1 = v;
    #pragma unroll
    for (int o = 16; o; o >>= 1){
        ss += __shfl_xor_sync(0xffffffffu, ss, o);
        s1 += __shfl_xor_sync(0xffffffffu, s1, o);
    }
    __shared__ float sq[8], sm[8];
    if ((t & 31) == 0){ sq[t>>5] = ss; sm[t>>5] = s1; }
    __syncthreads();
    __shared__ float s_val;
    if (t == 0){
        float a = 0.f, c = 0.f;
        for (int w = 0; w < 8; ++w){ a += sq[w]; c += sm[w]; }
        crow[r] = a / (float)N_IMG;
        s_val = c / (float)NM;
    }
    __syncthreads();
    __nv_bfloat16 h, l; split_bf16(s_val, h, l);
    tmph[(size_t)r*M_TOK + t] = h;
    tmpl[(size_t)r*M_TOK + t] = l;
}

// ---------------- fused Ct: thresh+mask+split + rowmeansq ----------------
__global__ void fusedCt_kernel(float* __restrict__ Ct, const int* __restrict__ tdm,
                               __nv_bfloat16* __restrict__ cth, __nv_bfloat16* __restrict__ ctl,
                               float* __restrict__ ccol)
{
    const float mn = dec_mono(g_minmax[4]);
    const float mx = dec_mono(g_minmax[5]);
    const float thr = mn + 0.1f*(mx - mn);
    const int r = blockIdx.x;
    const int t = threadIdx.x;

    size_t si = (size_t)r*M_TOK + t;
    float v = Ct[si] - thr;
    v = v > 0.f ? v : 0.f;
    v *= (tdm[si] == 1 ? 1.0f : 1e-5f);
    Ct[si] = v;
    __nv_bfloat16 h, l; split_bf16(v, h, l);
    cth[si] = h;
    ctl[si] = l;

    float ss = v*v;
    #pragma unroll
    for (int o = 16; o; o >>= 1) ss += __shfl_xor_sync(0xffffffffu, ss, o);
    __shared__ float sq[8];
    if ((t & 31) == 0) sq[t>>5] = ss;
    __syncthreads();
    if (t == 0){
        float a = 0.f;
        for (int w = 0; w < 8; ++w) a += sq[w];
        ccol[r] = a / (float)M_TOK;
    }
}

// ---------------- IPOT: 4-CTA cluster; optional inline threshold ----------------
__global__ void __cluster_dims__(4,1,1) __launch_bounds__(256,1)
ipot_kernel(const float* __restrict__ Cmat, int useThresh, float* __restrict__ ToutF,
            __nv_bfloat16* __restrict__ Gh, __nv_bfloat16* __restrict__ Gl,
            float* __restrict__ dotOut)
{
    cg::cluster_group cluster = cg::this_cluster();
    const int rank = blockIdx.x;
    const int b    = blockIdx.y;
    const int tid  = threadIdx.x;
    const int jl   = tid & 63;
    const int rq   = tid >> 6;
    const int lane = tid & 31;
    const int wid  = tid >> 5;
    const int jg   = rank*64 + jl;
    const float* C = Cmat + (size_t)b * NM;

    float thr = 0.f;
    if (useThresh){
        const float mn = dec_mono(g_minmax[0]);
        const float mx = dec_mono(g_minmax[1]);
        thr = mn + 0.1f*(mx - mn);
    }

    __shared__ float s_delta[196];
    __shared__ float s_part[8][49];
    __shared__ float s_rowpart[2][196];
    __shared__ float s_col[4][64];
    __shared__ float s_dred[8];
    __shared__ float s_dotpart;

    float E[49], T[49];
    #pragma unroll
    for (int k = 0; k < 49; ++k){
        float c = fmaxf(C[(rq + 4*k)*M_TOK + jg] - thr, 0.f);
        E[k] = expf(-2.0f * c);
        T[k] = 1.0f;
    }
    float sig = 1.0f/256.0f;
    __syncthreads();

    for (int it = 0; it < 20; ++it){
        const int buf = it & 1;
        #pragma unroll
        for (int k = 0; k < 49; ++k){
            float v = E[k]*T[k]*sig;
            v += __shfl_xor_sync(0xffffffffu, v, 16);
            v += __shfl_xor_sync(0xffffffffu, v, 8);
            v += __shfl_xor_sync(0xffffffffu, v, 4);
            v += __shfl_xor_sync(0xffffffffu, v, 2);
            v += __shfl_xor_sync(0xffffffffu, v, 1);
            if (lane == 0) s_part[wid][k] = v;
        }
        __syncthreads();
        if (tid < 196){
            int r2 = tid & 3, k2 = tid >> 2;
            s_rowpart[buf][tid] = s_part[r2*2][k2] + s_part[r2*2+1][k2];
        }
        cluster.sync();
        if (tid < 196){
            float s = 0.f;
            #pragma unroll
            for (int r = 0; r < 4; ++r)
                s += *(cluster.map_shared_rank(&s_rowpart[buf][0], r) + tid);
            s_delta[tid] = 1.0f / (196.0f * s);
        }
        __syncthreads();
        float cs = 0.f;
        #pragma unroll
        for (int k = 0; k < 49; ++k)
            cs += E[k]*T[k]*s_delta[rq + 4*k];
        s_col[rq][jl] = cs;
        __syncthreads();
        {
            float c = s_col[0][jl] + s_col[1][jl] + s_col[2][jl] + s_col[3][jl];
            sig = 1.0f / (256.0f * c);
        }
        #pragma unroll
        for (int k = 0; k < 49; ++k)
            T[k] = s_delta[rq + 4*k] * E[k] * T[k] * sig;
    }

    const size_t base = (size_t)b * NM;
    if (ToutF){
        #pragma unroll
        for (int k = 0; k < 49; ++k)
            ToutF[base + (size_t)(rq + 4*k)*M_TOK + jg] = T[k];
    }
    if (Gh){
        #pragma unroll
        for (int k = 0; k < 49; ++k){
            __nv_bfloat16 h, l; split_bf16(T[k], h, l);
            const size_t o = base + (size_t)(rq + 4*k)*M_TOK + jg;
            Gh[o] = h; Gl[o] = l;
        }
    }

    if (dotOut){
        float dot = 0.f;
        #pragma unroll
        for (int k = 0; k < 49; ++k)
            dot += fmaxf(C[(rq + 4*k)*M_TOK + jg] - thr, 0.f) * T[k];
        #pragma unroll
        for (int o = 16; o; o >>= 1) dot += __shfl_xor_sync(0xffffffffu, dot, o);
        if (lane == 0) s_dred[wid] = dot;
        __syncthreads();
        if (tid == 0){
            float t = 0.f;
            for (int w = 0; w < 8; ++w) t += s_dred[w];
            s_dotpart = t;
        }
        cluster.sync();
        if (rank == 0 && tid == 0){
            float t = 0.f;
            #pragma unroll
            for (int r = 0; r < 4; ++r)
                t += *cluster.map_shared_rank(&s_dotpart, r);
            dotOut[b] = t;
        }
    }
    cluster.sync();
}

__global__ void final_kernel(float* __restrict__ outp){
    int t = threadIdx.x;
    float wd = g_dotwd[t];
    float gw = g_dotgw[t];
    #pragma unroll
    for (int o = 16; o; o >>= 1){
        wd += __shfl_xor_sync(0xffffffffu, wd, o);
        gw += __shfl_xor_sync(0xffffffffu, gw, o);
    }
    if (t == 0)
        outp[0] = 0.1f*(gw * (1.0f/B_)) - 0.1f*(wd * (1.0f/B_));
}

// ---------------- host launcher ----------------
extern "C" void kernel_launch(void* const* d_in, const int* in_sizes, int n_in,
                              void* d_out, int out_size)
{
    const float* img     = (const float*)d_in[0];
    const float* tok     = (const float*)d_in[1];
    const float* tokmask = (const float*)d_in[2];
    const int*   tdm     = (const int*)d_in[3];
    const int*   irm     = (const int*)d_in[4];
    float* out = (float*)d_out;                    // [1 | T_wd | T_gwd]
    float* outTwd  = out + 1;
    float* outTgwd = out + 1 + (size_t)B_*NM;

    __nv_bfloat16 *xh, *xl, *yh, *yl, *csh, *csl, *cth, *ctl, *gh, *gl, *th, *tl;
    float *Cxy, *Cs, *Ct, *Cg, *crow, *ccol, *dwd, *dgw;
    cudaGetSymbolAddress((void**)&xh,  g_xh);
    cudaGetSymbolAddress((void**)&xl,  g_xl);
    cudaGetSymbolAddress((void**)&yh,  g_yh);
    cudaGetSymbolAddress((void**)&yl,  g_yl);
    cudaGetSymbolAddress((void**)&csh, g_Csh);
    cudaGetSymbolAddress((void**)&csl, g_Csl);
    cudaGetSymbolAddress((void**)&cth, g_Cth);
    cudaGetSymbolAddress((void**)&ctl, g_Ctl);
    cudaGetSymbolAddress((void**)&gh,  g_gamh);
    cudaGetSymbolAddress((void**)&gl,  g_gaml);
    cudaGetSymbolAddress((void**)&th,  g_tmph);
    cudaGetSymbolAddress((void**)&tl,  g_tmpl);
    cudaGetSymbolAddress((void**)&Cxy, g_Cxy);
    cudaGetSymbolAddress((void**)&Cs,  g_Cs);
    cudaGetSymbolAddress((void**)&Ct,  g_Ct);
    cudaGetSymbolAddress((void**)&Cg,  g_Cg);
    cudaGetSymbolAddress((void**)&crow, g_cstrow);
    cudaGetSymbolAddress((void**)&ccol, g_cstcol);
    cudaGetSymbolAddress((void**)&dwd, g_dotwd);
    cudaGetSymbolAddress((void**)&dgw, g_dotgw);

    cudaFuncSetAttribute(cosmma_kernel,  cudaFuncAttributeMaxDynamicSharedMemorySize, COS_DSM);
    cudaFuncSetAttribute(gwfused_kernel, cudaFuncAttributeMaxDynamicSharedMemorySize, GWF_DSM);
    cudaFuncSetAttribute(gwmma2_kernel,  cudaFuncAttributeMaxDynamicSharedMemorySize, GW2_DSM);

    init_kernel<<<1, 64>>>();
    normalize_kernel<<<B_*(N_IMG+M_TOK), 256>>>(img, tok, tokmask, xh, xl, yh, yl);

    cosmma_kernel<<<dim3(12,1,B_), 256, COS_DSM>>>(xh, xl, yh, yl, Cxy, Cs, Ct);

    fusedCs_kernel<<<B_*N_IMG, 256>>>(Cs, irm, csh, csl, crow, th, tl);
    fusedCt_kernel<<<B_*M_TOK, 256>>>(Ct, tdm, cth, ctl, ccol);

    // Wasserstein IPOT with inline threshold (Cxy stays raw in gmem)
    ipot_kernel<<<dim3(4,B_), 256>>>(Cxy, 1, outTwd, nullptr, nullptr, dwd);

    // iter0: tmp already = rowsum(Cs)/NM (from fusedCs)
    gwmma2_kernel<<<dim3(2,4,B_), 256, GW2_DSM>>>(th, tl, cth, ctl, Cg, crow, ccol);
    ipot_kernel<<<dim3(4,B_), 256>>>(Cg, 0, nullptr, gh, gl, nullptr);

    for (int it = 1; it < 6; ++it){
        const bool last = (it == 5);
        gwfused_kernel<<<dim3(4,1,B_), 256, GWF_DSM>>>(csh, csl, gh, gl, cth, ctl,
                                                       Cg, crow, ccol,
                                                       last ? outTgwd : nullptr, dgw);
        if (it < 5)
            ipot_kernel<<<dim3(4,B_), 256>>>(Cg, 0, (it == 4) ? outTgwd : nullptr, gh, gl, nullptr);
    }

    final_kernel<<<1, 32>>>(out);
}

// round 11
// speedup vs baseline: 1.0079x; 1.0079x over previous
#include <cuda_runtime.h>
#include <cuda_bf16.h>
#include <cooperative_groups.h>
#include <math.h>

namespace cg = cooperative_groups;

#define B_    32
#define N_IMG 196
#define M_TOK 256
#define D_    1024
#define NM    (N_IMG*M_TOK)
#define KPAD  224

// ---------------- device scratch (allocation-free) ----------------
__device__ __nv_bfloat16 g_xh[B_*N_IMG*D_];
__device__ __nv_bfloat16 g_xl[B_*N_IMG*D_];
__device__ __nv_bfloat16 g_yh[B_*M_TOK*D_];
__device__ __nv_bfloat16 g_yl[B_*M_TOK*D_];
__device__ float g_Cxy[B_*NM];
__device__ float g_Cs [B_*N_IMG*N_IMG];
__device__ float g_Ct [B_*M_TOK*M_TOK];
__device__ __nv_bfloat16 g_Csh[B_*N_IMG*KPAD];
__device__ __nv_bfloat16 g_Csl[B_*N_IMG*KPAD];
__device__ __nv_bfloat16 g_Cth[B_*M_TOK*M_TOK];
__device__ __nv_bfloat16 g_Ctl[B_*M_TOK*M_TOK];
__device__ __nv_bfloat16 g_gamh[B_*NM];
__device__ __nv_bfloat16 g_gaml[B_*NM];
__device__ __nv_bfloat16 g_tmph[B_*NM];
__device__ __nv_bfloat16 g_tmpl[B_*NM];
__device__ float g_Cg[B_*NM];
__device__ float g_cstrow[B_*N_IMG];
__device__ float g_cstcol[B_*M_TOK];
__device__ unsigned g_minmax[6];
__device__ float g_dotwd[B_];
__device__ float g_dotgw[B_];

__device__ __forceinline__ unsigned enc_mono(float f){
    unsigned u = __float_as_uint(f);
    return (u & 0x80000000u) ? ~u : (u | 0x80000000u);
}
__device__ __forceinline__ float dec_mono(unsigned e){
    unsigned u = (e & 0x80000000u) ? (e ^ 0x80000000u) : ~e;
    return __uint_as_float(u);
}
__device__ __forceinline__ uint32_t smem_u32(const void* p){
    uint32_t a;
    asm("{ .reg .u64 t; cvta.to.shared.u64 t, %1; cvt.u32.u64 %0, t; }" : "=r"(a) : "l"(p));
    return a;
}
__device__ __forceinline__ void ldm_x4(unsigned* r, uint32_t addr){
    asm volatile("ldmatrix.sync.aligned.m8n8.x4.shared.b16 {%0,%1,%2,%3}, [%4];"
        : "=r"(r[0]), "=r"(r[1]), "=r"(r[2]), "=r"(r[3]) : "r"(addr));
}
__device__ __forceinline__ void ldm_x4_t(unsigned* r, uint32_t addr){
    asm volatile("ldmatrix.sync.aligned.m8n8.x4.trans.shared.b16 {%0,%1,%2,%3}, [%4];"
        : "=r"(r[0]), "=r"(r[1]), "=r"(r[2]), "=r"(r[3]) : "r"(addr));
}
__device__ __forceinline__ void mma_bf16(float* d, const unsigned* a, unsigned b0, unsigned b1){
    asm volatile("mma.sync.aligned.m16n8k16.row.col.f32.bf16.bf16.f32 "
        "{%0,%1,%2,%3}, {%4,%5,%6,%7}, {%8,%9}, {%0,%1,%2,%3};"
        : "+f"(d[0]), "+f"(d[1]), "+f"(d[2]), "+f"(d[3])
        : "r"(a[0]), "r"(a[1]), "r"(a[2]), "r"(a[3]), "r"(b0), "r"(b1));
}
__device__ __forceinline__ void split_bf16(float v, __nv_bfloat16& h, __nv_bfloat16& l){
    h = __float2bfloat16(v);
    l = __float2bfloat16(v - __bfloat162float(h));
}
__device__ __forceinline__ void cp16(uint32_t d, const void* s, bool v){
    int sz = v ? 16 : 0;
    asm volatile("cp.async.ca.shared.global [%0], [%1], 16, %2;" :: "r"(d), "l"(s), "r"(sz));
}
#define CP_COMMIT() asm volatile("cp.async.commit_group;" ::: "memory")
#define CP_WAIT1()  asm volatile("cp.async.wait_group 1;" ::: "memory")
#define CP_WAIT0()  asm volatile("cp.async.wait_group 0;" ::: "memory")

// ---------------- init ----------------
__global__ void init_kernel(){
    int t = threadIdx.x;
    if (t < 3){ g_minmax[2*t] = 0xFFFFFFFFu; g_minmax[2*t+1] = 0u; }
    if (t < B_) g_dotgw[t] = 0.f;
}

// ---------------- merged normalize: img rows then tok rows ----------------
__global__ void normalize_kernel(const float* __restrict__ img,
                                 const float* __restrict__ tok,
                                 const float* __restrict__ tokmask,
                                 __nv_bfloat16* __restrict__ xh, __nv_bfloat16* __restrict__ xl,
                                 __nv_bfloat16* __restrict__ yh, __nv_bfloat16* __restrict__ yl)
{
    const int gb = blockIdx.x;
    const bool isTok = gb >= B_*N_IMG;
    const int bp = isTok ? (gb - B_*N_IMG) : gb;
    const float* v = (isTok ? tok : img) + (size_t)bp * D_;
    float mk = 1.0f;
    if (isTok) mk = tokmask[bp];
    __nv_bfloat16* oh = isTok ? yh : xh;
    __nv_bfloat16* ol = isTok ? yl : xl;

    float ss = 0.f;
    for (int d = threadIdx.x; d < D_; d += blockDim.x){
        float t = v[d] * mk;
        ss += t*t;
    }
    #pragma unroll
    for (int o = 16; o; o >>= 1) ss += __shfl_xor_sync(0xffffffffu, ss, o);
    __shared__ float sred[8];
    if ((threadIdx.x & 31) == 0) sred[threadIdx.x >> 5] = ss;
    __syncthreads();
    __shared__ float s_inv;
    if (threadIdx.x == 0){
        float t = 0.f;
        for (int w = 0; w < 8; ++w) t += sred[w];
        s_inv = 1.0f / (sqrtf(t) + 1e-12f);
    }
    __syncthreads();
    const float scale = s_inv * mk;
    const size_t base = (size_t)bp * D_;
    for (int d = threadIdx.x; d < D_; d += blockDim.x){
        float t = v[d] * scale;
        __nv_bfloat16 hi, lo; split_bf16(t, hi, lo);
        oh[base + d] = hi;
        ol[base + d] = lo;
    }
}

// ============ merged cosine GEMMs (round-9 shape): CTA 64x128, occ 2, 3-stage ============
// grid (24, 1, B_): tile = blockIdx.x; which = tile>>3 (0 Cxy, 1 Cs, 2 Ct); sub = tile&7
#define LDT 40
#define COS_DSM (3*30720)

__global__ void __launch_bounds__(256,2)
cosmma_kernel(const __nv_bfloat16* __restrict__ xh, const __nv_bfloat16* __restrict__ xl,
              const __nv_bfloat16* __restrict__ yh, const __nv_bfloat16* __restrict__ yl,
              float* __restrict__ Cxy, float* __restrict__ Cs, float* __restrict__ Ct)
{
    extern __shared__ char dyn[];
    const uint32_t sb = smem_u32(dyn);

    const int tile = blockIdx.x;
    const int which = tile >> 3;
    const int sub   = tile & 7;
    const int b     = blockIdx.z;
    const int m0    = (sub >> 1) * 64;
    const int j0    = (sub & 1) * 128;

    const __nv_bfloat16* Ah = (which == 2) ? yh : xh;
    const __nv_bfloat16* Al = (which == 2) ? yl : xl;
    const __nv_bfloat16* Bh = (which == 1) ? xh : yh;
    const __nv_bfloat16* Bl = (which == 1) ? xl : yl;
    const int Mz = (which == 2) ? M_TOK : N_IMG;
    const int Nz = (which == 1) ? N_IMG : M_TOK;
    float* Cout = (which == 0) ? Cxy : ((which == 1) ? Cs : Ct);

    const int tid  = threadIdx.x;
    const int lane = tid & 31;
    const int wid  = tid >> 5;
    const int wm   = wid >> 2;
    const int wn   = wid & 3;

    const size_t abase = (size_t)b * Mz * D_;
    const size_t bbase = (size_t)b * Nz * D_;

    const int a_row = tid >> 2, a_quad = tid & 3;
    const bool avalid = (m0 + a_row) < Mz;
    const uint32_t aoff = (uint32_t)((a_row*LDT + a_quad*8) * 2);

    const int arow_l = lane & 15, ahalf = lane >> 4;
    const int bg = lane >> 3;
    const int b_noff = ((bg >> 1) << 3) + (lane & 7);
    const int b_koff = (bg & 1) << 3;

    float acc[2][4][4];
    #pragma unroll
    for (int mt = 0; mt < 2; ++mt)
        #pragma unroll
        for (int nt = 0; nt < 4; ++nt)
            #pragma unroll
            for (int q = 0; q < 4; ++q) acc[mt][nt][q] = 0.f;

    auto issue_tile = [&](int kc, int buf){
        const uint32_t base = sb + (uint32_t)buf*30720u;
        {
            const size_t go = abase + (size_t)(m0 + a_row)*D_ + kc*32 + a_quad*8;
            const size_t gs = avalid ? go : abase;
            cp16(base + aoff, Ah + gs, avalid);
            cp16(base + 5120u + aoff, Al + gs, avalid);
        }
        #pragma unroll
        for (int p = 0; p < 2; ++p){
            int idx = tid + p*256;
            int row = idx >> 2, quad = idx & 3;
            const bool bv = (j0 + row) < Nz;
            const size_t go = bbase + (size_t)(j0 + row)*D_ + kc*32 + quad*8;
            const size_t gs = bv ? go : bbase;
            const uint32_t so = (uint32_t)((row*LDT + quad*8) * 2);
            cp16(base + 10240u + so, Bh + gs, bv);
            cp16(base + 20480u + so, Bl + gs, bv);
        }
        CP_COMMIT();
    };

    issue_tile(0, 0);
    issue_tile(1, 1);
    for (int kc = 0; kc < 32; ++kc){
        if (kc == 31){ CP_WAIT0(); } else { CP_WAIT1(); }
        __syncthreads();
        if (kc + 2 < 32) issue_tile(kc + 2, (kc + 2) % 3);

        const uint32_t base = sb + (uint32_t)(kc % 3)*30720u;
        const uint32_t baAh = base;
        const uint32_t baAl = base + 5120u;
        const uint32_t baBh = base + 10240u;
        const uint32_t baBl = base + 20480u;

        #pragma unroll
        for (int k16 = 0; k16 < 2; ++k16){
            unsigned ah[2][4], al[2][4], bh[2][4], bl[2][4];
            #pragma unroll
            for (int mt = 0; mt < 2; ++mt){
                uint32_t off = (uint32_t)(((wm*32 + mt*16 + arow_l)*LDT + k16*16 + ahalf*8) * 2);
                ldm_x4(ah[mt], baAh + off);
                ldm_x4(al[mt], baAl + off);
            }
            #pragma unroll
            for (int nt2 = 0; nt2 < 2; ++nt2){
                uint32_t off = (uint32_t)(((wn*32 + nt2*16 + b_noff)*LDT + k16*16 + b_koff) * 2);
                ldm_x4(bh[nt2], baBh + off);
                ldm_x4(bl[nt2], baBl + off);
            }
            #pragma unroll
            for (int mt = 0; mt < 2; ++mt)
                #pragma unroll
                for (int nt = 0; nt < 4; ++nt){
                    const int p2 = nt >> 1, s2 = (nt & 1) * 2;
                    mma_bf16(acc[mt][nt], ah[mt], bh[p2][s2], bh[p2][s2+1]);
                    mma_bf16(acc[mt][nt], ah[mt], bl[p2][s2], bl[p2][s2+1]);
                    mma_bf16(acc[mt][nt], al[mt], bh[p2][s2], bh[p2][s2+1]);
                }
        }
    }

    float lmin =  3.402823466e+38f;
    float lmax = -3.402823466e+38f;
    #pragma unroll
    for (int mt = 0; mt < 2; ++mt){
        #pragma unroll
        for (int nt = 0; nt < 4; ++nt){
            const int ibase = m0 + wm*32 + mt*16 + (lane >> 2);
            const int jbase = j0 + wn*32 + nt*8 + (lane & 3)*2;
            #pragma unroll
            for (int rr = 0; rr < 2; ++rr){
                int i = ibase + rr*8;
                if (i >= Mz) continue;
                float* crow = Cout + ((size_t)b*Mz + i)*Nz;
                #pragma unroll
                for (int cc = 0; cc < 2; ++cc){
                    int j = jbase + cc;
                    if (j >= Nz) continue;
                    float v = 1.0f - acc[mt][nt][rr*2 + cc];
                    crow[j] = v;
                    lmin = fminf(lmin, v);
                    lmax = fmaxf(lmax, v);
                }
            }
        }
    }
    #pragma unroll
    for (int o = 16; o; o >>= 1){
        lmin = fminf(lmin, __shfl_xor_sync(0xffffffffu, lmin, o));
        lmax = fmaxf(lmax, __shfl_xor_sync(0xffffffffu, lmax, o));
    }
    if (lane == 0){
        atomicMin(&g_minmax[2*which],   enc_mono(lmin));
        atomicMax(&g_minmax[2*which+1], enc_mono(lmax));
    }
}

// ============ FUSED GW chain: tmp = Cs@gamma (smem), Cg = Cst - 2*tmp@Ct^T ============
#define LDP 264
#define GWF_DSM 155648

__global__ void __launch_bounds__(256,1)
gwfused_kernel(const __nv_bfloat16* __restrict__ Csh, const __nv_bfloat16* __restrict__ Csl,
               const __nv_bfloat16* __restrict__ Gh,  const __nv_bfloat16* __restrict__ Gl,
               const __nv_bfloat16* __restrict__ Cth, const __nv_bfloat16* __restrict__ Ctl,
               float* __restrict__ Cout,
               const float* __restrict__ rowadd, const float* __restrict__ coladd,
               const float* __restrict__ gamF, float* __restrict__ dotOut)
{
    extern __shared__ char dyn[];
    const uint32_t sb = smem_u32(dyn);
    const uint32_t TMPH = sb + 88064u;
    const uint32_t TMPL = sb + 121856u;

    const int tid  = threadIdx.x;
    const int lane = tid & 31;
    const int wid  = tid >> 5;
    const int wm   = wid >> 2;
    const int wn   = wid & 3;
    const int b    = blockIdx.z;
    const int m0   = blockIdx.x * 64;

    const int a_row = tid >> 2, a_quad = tid & 3;
    const bool avalid = (m0 + a_row) < N_IMG;
    const uint32_t aoff = (uint32_t)((a_row*LDT + a_quad*8) * 2);

    const int arow_l = lane & 15, ahalf = lane >> 4;
    const int bg = lane >> 3;
    const int b_noff = ((bg >> 1) << 3) + (lane & 7);
    const int b_koff = (bg & 1) << 3;
    const int ktr = ((lane >> 3) & 1)*8 + (lane & 7);
    const int ntr = (lane >> 4)*8;

    float acc[2][8][4];
    #pragma unroll
    for (int mt = 0; mt < 2; ++mt)
        #pragma unroll
        for (int nt = 0; nt < 8; ++nt)
            #pragma unroll
            for (int q = 0; q < 4; ++q) acc[mt][nt][q] = 0.f;

    auto issue1 = [&](int kc, int buf){
        const int kbase = kc*32;
        {
            const size_t go = ((size_t)b*N_IMG + (m0 + a_row))*KPAD + kbase + a_quad*8;
            const size_t gs = avalid ? go : (size_t)b*N_IMG*KPAD;
            cp16(sb + buf*5120u + aoff, Csh + gs, avalid);
            cp16(sb + 10240u + buf*5120u + aoff, Csl + gs, avalid);
        }
        #pragma unroll
        for (int p = 0; p < 4; ++p){
            int idx = tid + p*256;
            int kk = idx >> 5, nn = (idx & 31)*8;
            const bool bv = (kbase + kk) < N_IMG;
            const size_t go = ((size_t)b*N_IMG + kbase + kk)*M_TOK + nn;
            const size_t gs = bv ? go : (size_t)b*NM;
            const uint32_t so = (uint32_t)((kk*LDP + nn) * 2);
            cp16(sb + 20480u + buf*16896u + so, Gh + gs, bv);
            cp16(sb + 54272u + buf*16896u + so, Gl + gs, bv);
        }
        CP_COMMIT();
    };

    issue1(0, 0);
    for (int kc = 0; kc < 7; ++kc){
        if (kc < 6){ issue1(kc+1, (kc+1)&1); CP_WAIT1(); }
        else       { CP_WAIT0(); }
        __syncthreads();

        const int buf = kc & 1;
        const uint32_t baAh = sb + buf*5120u;
        const uint32_t baAl = sb + 10240u + buf*5120u;
        const uint32_t baBh = sb + 20480u + buf*16896u;
        const uint32_t baBl = sb + 54272u + buf*16896u;

        #pragma unroll
        for (int k16 = 0; k16 < 2; ++k16){
            unsigned ah[2][4], al[2][4], bh[4][4], bl[4][4];
            #pragma unroll
            for (int mt = 0; mt < 2; ++mt){
                uint32_t off = (uint32_t)(((wm*32 + mt*16 + arow_l)*LDT + k16*16 + ahalf*8) * 2);
                ldm_x4(ah[mt], baAh + off);
                ldm_x4(al[mt], baAl + off);
            }
            #pragma unroll
            for (int nt2 = 0; nt2 < 4; ++nt2){
                uint32_t off = (uint32_t)(((k16*16 + ktr)*LDP + wn*64 + nt2*16 + ntr) * 2);
                ldm_x4_t(bh[nt2], baBh + off);
                ldm_x4_t(bl[nt2], baBl + off);
            }
            #pragma unroll
            for (int mt = 0; mt < 2; ++mt)
                #pragma unroll
                for (int nt = 0; nt < 8; ++nt){
                    const int p2 = nt >> 1, s2 = (nt & 1) * 2;
                    mma_bf16(acc[mt][nt], ah[mt], bh[p2][s2], bh[p2][s2+1]);
                    mma_bf16(acc[mt][nt], ah[mt], bl[p2][s2], bl[p2][s2+1]);
                    mma_bf16(acc[mt][nt], al[mt], bh[p2][s2], bh[p2][s2+1]);
                }
        }
        __syncthreads();
    }

    auto issue2 = [&](int kc, int buf){
        #pragma unroll
        for (int p = 0; p < 4; ++p){
            int idx = tid + p*256;
            int row = idx >> 2, quad = idx & 3;
            const size_t go = ((size_t)b*M_TOK + row)*M_TOK + kc*32 + quad*8;
            const uint32_t so = (uint32_t)((row*LDT + quad*8) * 2);
            cp16(sb + buf*20480u + so, Cth + go, true);
            cp16(sb + 40960u + buf*20480u + so, Ctl + go, true);
        }
        CP_COMMIT();
    };
    issue2(0, 0);

    #pragma unroll
    for (int mt = 0; mt < 2; ++mt){
        #pragma unroll
        for (int nt = 0; nt < 8; ++nt){
            const int il = wm*32 + mt*16 + (lane >> 2);
            const int jb = wn*64 + nt*8 + (lane & 3)*2;
            #pragma unroll
            for (int rr = 0; rr < 2; ++rr){
                const int i = il + rr*8;
                #pragma unroll
                for (int cc = 0; cc < 2; ++cc){
                    const int j = jb + cc;
                    __nv_bfloat16 h, l;
                    split_bf16(acc[mt][nt][rr*2 + cc], h, l);
                    *reinterpret_cast<__nv_bfloat16*>((char*)dyn + 88064u + (i*LDP + j)*2) = h;
                    *reinterpret_cast<__nv_bfloat16*>((char*)dyn + 121856u + (i*LDP + j)*2) = l;
                }
            }
        }
    }
    issue2(1, 1);
    __syncthreads();

    #pragma unroll
    for (int mt = 0; mt < 2; ++mt)
        #pragma unroll
        for (int nt = 0; nt < 8; ++nt)
            #pragma unroll
            for (int q = 0; q < 4; ++q) acc[mt][nt][q] = 0.f;

    for (int kc = 0; kc < 8; ++kc){
        if (kc < 7){ issue2(kc+1, (kc+1)&1); CP_WAIT1(); }
        else       { CP_WAIT0(); }
        __syncthreads();

        const int buf = kc & 1;
        const uint32_t baBh = sb + buf*20480u;
        const uint32_t baBl = sb + 40960u + buf*20480u;

        #pragma unroll
        for (int k16 = 0; k16 < 2; ++k16){
            unsigned ah[2][4], al[2][4], bh[4][4], bl[4][4];
            #pragma unroll
            for (int mt = 0; mt < 2; ++mt){
                uint32_t off = (uint32_t)(((wm*32 + mt*16 + arow_l)*LDP + kc*32 + k16*16 + ahalf*8) * 2);
                ldm_x4(ah[mt], TMPH + off);
                ldm_x4(al[mt], TMPL + off);
            }
            #pragma unroll
            for (int nt2 = 0; nt2 < 4; ++nt2){
                uint32_t off = (uint32_t)(((wn*64 + nt2*16 + b_noff)*LDT + k16*16 + b_koff) * 2);
                ldm_x4(bh[nt2], baBh + off);
                ldm_x4(bl[nt2], baBl + off);
            }
            #pragma unroll
            for (int mt = 0; mt < 2; ++mt)
                #pragma unroll
                for (int nt = 0; nt < 8; ++nt){
                    const int p2 = nt >> 1, s2 = (nt & 1) * 2;
                    mma_bf16(acc[mt][nt], ah[mt], bh[p2][s2], bh[p2][s2+1]);
                    mma_bf16(acc[mt][nt], ah[mt], bl[p2][s2], bl[p2][s2+1]);
                    mma_bf16(acc[mt][nt], al[mt], bh[p2][s2], bh[p2][s2+1]);
                }
        }
        __syncthreads();
    }

    float dot = 0.f;
    #pragma unroll
    for (int mt = 0; mt < 2; ++mt){
        #pragma unroll
        for (int nt = 0; nt < 8; ++nt){
            const int ibase = m0 + wm*32 + mt*16 + (lane >> 2);
            const int jbase = wn*64 + nt*8 + (lane & 3)*2;
            #pragma unroll
            for (int rr = 0; rr < 2; ++rr){
                int i = ibase + rr*8;
                if (i >= N_IMG) continue;
                const size_t ro = ((size_t)b*N_IMG + i)*M_TOK;
                const float ra = rowadd[b*N_IMG + i];
                #pragma unroll
                for (int cc = 0; cc < 2; ++cc){
                    int j = jbase + cc;
                    float r = ra + coladd[b*M_TOK + j] - 2.0f*acc[mt][nt][rr*2 + cc];
                    Cout[ro + j] = r;
                    if (gamF) dot += r * gamF[ro + j];
                }
            }
        }
    }
    if (gamF){
        #pragma unroll
        for (int o = 16; o; o >>= 1) dot += __shfl_xor_sync(0xffffffffu, dot, o);
        if (lane == 0) atomicAdd(&dotOut[b], dot);
    }
}

// ============ GW GEMM 2 standalone (iter0) ============
#define GW2_DSM 61440

__global__ void __launch_bounds__(256,1)
gwmma2_kernel(const __nv_bfloat16* __restrict__ Ah, const __nv_bfloat16* __restrict__ Al,
              const __nv_bfloat16* __restrict__ Bh, const __nv_bfloat16* __restrict__ Bl,
              float* __restrict__ Cout,
              const float* __restrict__ rowadd, const float* __restrict__ coladd)
{
    extern __shared__ char dyn[];
    const uint32_t sb = smem_u32(dyn);

    const int tid  = threadIdx.x;
    const int lane = tid & 31;
    const int wid  = tid >> 5;
    const int wm   = wid >> 2;
    const int wn   = wid & 3;
    const int b    = blockIdx.z;
    const int m0   = blockIdx.y * 64;
    const int j0   = blockIdx.x * 128;

    const int a_row = tid >> 2, a_quad = tid & 3;
    const bool avalid = (m0 + a_row) < N_IMG;
    const uint32_t aoff = (uint32_t)((a_row*LDT + a_quad*8) * 2);

    const int arow_l = lane & 15, ahalf = lane >> 4;
    const int bg = lane >> 3;
    const int b_noff = ((bg >> 1) << 3) + (lane & 7);
    const int b_koff = (bg & 1) << 3;

    float acc[2][4][4];
    #pragma unroll
    for (int mt = 0; mt < 2; ++mt)
        #pragma unroll
        for (int nt = 0; nt < 4; ++nt)
            #pragma unroll
            for (int q = 0; q < 4; ++q) acc[mt][nt][q] = 0.f;

    auto issue_tile = [&](int kc, int buf){
        const uint32_t ah = sb + buf*5120u;
        const uint32_t al = sb + 10240u + buf*5120u;
        const uint32_t bh = sb + 20480u + buf*10240u;
        const uint32_t bl = sb + 40960u + buf*10240u;
        {
            const size_t go = ((size_t)b*N_IMG + (m0 + a_row))*M_TOK + kc*32 + a_quad*8;
            const size_t gs = avalid ? go : (size_t)b*NM;
            cp16(ah + aoff, Ah + gs, avalid);
            cp16(al + aoff, Al + gs, avalid);
        }
        #pragma unroll
        for (int p = 0; p < 2; ++p){
            int idx = tid + p*256;
            int row = idx >> 2, quad = idx & 3;
            const size_t go = ((size_t)b*M_TOK + j0 + row)*M_TOK + kc*32 + quad*8;
            const uint32_t so = (uint32_t)((row*LDT + quad*8) * 2);
            cp16(bh + so, Bh + go, true);
            cp16(bl + so, Bl + go, true);
        }
        CP_COMMIT();
    };

    issue_tile(0, 0);
    for (int kc = 0; kc < 8; ++kc){
        if (kc < 7){ issue_tile(kc+1, (kc+1)&1); CP_WAIT1(); }
        else       { CP_WAIT0(); }
        __syncthreads();

        const int buf = kc & 1;
        const uint32_t baAh = sb + buf*5120u;
        const uint32_t baAl = sb + 10240u + buf*5120u;
        const uint32_t baBh = sb + 20480u + buf*10240u;
        const uint32_t baBl = sb + 40960u + buf*10240u;

        #pragma unroll
        for (int k16 = 0; k16 < 2; ++k16){
            unsigned ah[2][4], al[2][4], bh[2][4], bl[2][4];
            #pragma unroll
            for (int mt = 0; mt < 2; ++mt){
                uint32_t off = (uint32_t)(((wm*32 + mt*16 + arow_l)*LDT + k16*16 + ahalf*8) * 2);
                ldm_x4(ah[mt], baAh + off);
                ldm_x4(al[mt], baAl + off);
            }
            #pragma unroll
            for (int nt2 = 0; nt2 < 2; ++nt2){
                uint32_t off = (uint32_t)(((wn*32 + nt2*16 + b_noff)*LDT + k16*16 + b_koff) * 2);
                ldm_x4(bh[nt2], baBh + off);
                ldm_x4(bl[nt2], baBl + off);
            }
            #pragma unroll
            for (int mt = 0; mt < 2; ++mt)
                #pragma unroll
                for (int nt = 0; nt < 4; ++nt){
                    const int p2 = nt >> 1, s2 = (nt & 1) * 2;
                    mma_bf16(acc[mt][nt], ah[mt], bh[p2][s2], bh[p2][s2+1]);
                    mma_bf16(acc[mt][nt], ah[mt], bl[p2][s2], bl[p2][s2+1]);
                    mma_bf16(acc[mt][nt], al[mt], bh[p2][s2], bh[p2][s2+1]);
                }
        }
        __syncthreads();
    }

    #pragma unroll
    for (int mt = 0; mt < 2; ++mt){
        #pragma unroll
        for (int nt = 0; nt < 4; ++nt){
            const int ibase = m0 + wm*32 + mt*16 + (lane >> 2);
            const int jbase = j0 + wn*32 + nt*8 + (lane & 3)*2;
            #pragma unroll
            for (int rr = 0; rr < 2; ++rr){
                int i = ibase + rr*8;
                if (i >= N_IMG) continue;
                const size_t ro = ((size_t)b*N_IMG + i)*M_TOK;
                const float ra = rowadd[b*N_IMG + i];
                #pragma unroll
                for (int cc = 0; cc < 2; ++cc){
                    int j = jbase + cc;
                    Cout[ro + j] = ra + coladd[b*M_TOK + j] - 2.0f*acc[mt][nt][rr*2 + cc];
                }
            }
        }
    }
}

// ---------------- fused Cs: thresh+mask+split(pad) + rowmeansq + rowsum->tmp ----------------
__global__ void fusedCs_kernel(float* __restrict__ Cs, const int* __restrict__ irm,
                               __nv_bfloat16* __restrict__ csh, __nv_bfloat16* __restrict__ csl,
                               float* __restrict__ crow,
                               __nv_bfloat16* __restrict__ tmph, __nv_bfloat16* __restrict__ tmpl)
{
    const float mn = dec_mono(g_minmax[2]);
    const float mx = dec_mono(g_minmax[3]);
    const float thr = mn + 0.1f*(mx - mn);
    const int r = blockIdx.x;
    const int t = threadIdx.x;

    float v = 0.f;
    if (t < N_IMG){
        size_t si = (size_t)r*N_IMG + t;
        v = Cs[si] - thr;
        v = v > 0.f ? v : 0.f;
        v *= (irm[si] == 1 ? 1.0f : 1e-5f);
        Cs[si] = v;
    }
    if (t < KPAD){
        __nv_bfloat16 h, l; split_bf16(v, h, l);
        csh[(size_t)r*KPAD + t] = h;
        csl[(size_t)r*KPAD + t] = l;
    }
    float ss = v*v, s1 = v;
    #pragma unroll
    for (int o = 16; o; o >>= 1){
        ss += __shfl_xor_sync(0xffffffffu, ss, o);
        s1 += __shfl_xor_sync(0xffffffffu, s1, o);
    }
    __shared__ float sq[8], sm[8];
    if ((t & 31) == 0){ sq[t>>5] = ss; sm[t>>5] = s1; }
    __syncthreads();
    __shared__ float s_val;
    if (t == 0){
        float a = 0.f, c = 0.f;
        for (int w = 0; w < 8; ++w){ a += sq[w]; c += sm[w]; }
        crow[r] = a / (float)N_IMG;
        s_val = c / (float)NM;
    }
    __syncthreads();
    __nv_bfloat16 h, l; split_bf16(s_val, h, l);
    tmph[(size_t)r*M_TOK + t] = h;
    tmpl[(size_t)r*M_TOK + t] = l;
}

// ---------------- fused Ct: thresh+mask+split + rowmeansq ----------------
__global__ void fusedCt_kernel(float* __restrict__ Ct, const int* __restrict__ tdm,
                               __nv_bfloat16* __restrict__ cth, __nv_bfloat16* __restrict__ ctl,
                               float* __restrict__ ccol)
{
    const float mn = dec_mono(g_minmax[4]);
    const float mx = dec_mono(g_minmax[5]);
    const float thr = mn + 0.1f*(mx - mn);
    const int r = blockIdx.x;
    const int t = threadIdx.x;

    size_t si = (size_t)r*M_TOK + t;
    float v = Ct[si] - thr;
    v = v > 0.f ? v : 0.f;
    v *= (tdm[si] == 1 ? 1.0f : 1e-5f);
    Ct[si] = v;
    __nv_bfloat16 h, l; split_bf16(v, h, l);
    cth[si] = h;
    ctl[si] = l;

    float ss = v*v;
    #pragma unroll
    for (int o = 16; o; o >>= 1) ss += __shfl_xor_sync(0xffffffffu, ss, o);
    __shared__ float sq[8];
    if ((t & 31) == 0) sq[t>>5] = ss;
    __syncthreads();
    if (t == 0){
        float a = 0.f;
        for (int w = 0; w < 8; ++w) a += sq[w];
        ccol[r] = a / (float)M_TOK;
    }
}

// ---------------- IPOT: 4-CTA cluster; optional inline threshold ----------------
__global__ void __cluster_dims__(4,1,1) __launch_bounds__(256,1)
ipot_kernel(const float* __restrict__ Cmat, int useThresh, float* __restrict__ ToutF,
            __nv_bfloat16* __restrict__ Gh, __nv_bfloat16* __restrict__ Gl,
            float* __restrict__ dotOut)
{
    cg::cluster_group cluster = cg::this_cluster();
    const int rank = blockIdx.x;
    const int b    = blockIdx.y;
    const int tid  = threadIdx.x;
    const int jl   = tid & 63;
    const int rq   = tid >> 6;
    const int lane = tid & 31;
    const int wid  = tid >> 5;
    const int jg   = rank*64 + jl;
    const float* C = Cmat + (size_t)b * NM;

    float thr = 0.f;
    if (useThresh){
        const float mn = dec_mono(g_minmax[0]);
        const float mx = dec_mono(g_minmax[1]);
        thr = mn + 0.1f*(mx - mn);
    }

    __shared__ float s_delta[196];
    __shared__ float s_part[8][49];
    __shared__ float s_rowpart[2][196];
    __shared__ float s_col[4][64];
    __shared__ float s_dred[8];
    __shared__ float s_dotpart;

    float E[49], T[49];
    #pragma unroll
    for (int k = 0; k < 49; ++k){
        float c = fmaxf(C[(rq + 4*k)*M_TOK + jg] - thr, 0.f);
        E[k] = expf(-2.0f * c);
        T[k] = 1.0f;
    }
    float sig = 1.0f/256.0f;
    __syncthreads();

    for (int it = 0; it < 20; ++it){
        const int buf = it & 1;
        #pragma unroll
        for (int k = 0; k < 49; ++k){
            float v = E[k]*T[k]*sig;
            v += __shfl_xor_sync(0xffffffffu, v, 16);
            v += __shfl_xor_sync(0xffffffffu, v, 8);
            v += __shfl_xor_sync(0xffffffffu, v, 4);
            v += __shfl_xor_sync(0xffffffffu, v, 2);
            v += __shfl_xor_sync(0xffffffffu, v, 1);
            if (lane == 0) s_part[wid][k] = v;
        }
        __syncthreads();
        if (tid < 196){
            int r2 = tid & 3, k2 = tid >> 2;
            s_rowpart[buf][tid] = s_part[r2*2][k2] + s_part[r2*2+1][k2];
        }
        cluster.sync();
        if (tid < 196){
            float s = 0.f;
            #pragma unroll
            for (int r = 0; r < 4; ++r)
                s += *(cluster.map_shared_rank(&s_rowpart[buf][0], r) + tid);
            s_delta[tid] = 1.0f / (196.0f * s);
        }
        __syncthreads();
        float cs = 0.f;
        #pragma unroll
        for (int k = 0; k < 49; ++k)
            cs += E[k]*T[k]*s_delta[rq + 4*k];
        s_col[rq][jl] = cs;
        __syncthreads();
        {
            float c = s_col[0][jl] + s_col[1][jl] + s_col[2][jl] + s_col[3][jl];
            sig = 1.0f / (256.0f * c);
        }
        #pragma unroll
        for (int k = 0; k < 49; ++k)
            T[k] = s_delta[rq + 4*k] * E[k] * T[k] * sig;
    }

    const size_t base = (size_t)b * NM;
    if (ToutF){
        #pragma unroll
        for (int k = 0; k < 49; ++k)
            ToutF[base + (size_t)(rq + 4*k)*M_TOK + jg] = T[k];
    }
    if (Gh){
        #pragma unroll
        for (int k = 0; k < 49; ++k){
            __nv_bfloat16 h, l; split_bf16(T[k], h, l);
            const size_t o = base + (size_t)(rq + 4*k)*M_TOK + jg;
            Gh[o] = h; Gl[o] = l;
        }
    }

    if (dotOut){
        float dot = 0.f;
        #pragma unroll
        for (int k = 0; k < 49; ++k)
            dot += fmaxf(C[(rq + 4*k)*M_TOK + jg] - thr, 0.f) * T[k];
        #pragma unroll
        for (int o = 16; o; o >>= 1) dot += __shfl_xor_sync(0xffffffffu, dot, o);
        if (lane == 0) s_dred[wid] = dot;
        __syncthreads();
        if (tid == 0){
            float t = 0.f;
            for (int w = 0; w < 8; ++w) t += s_dred[w];
            s_dotpart = t;
        }
        cluster.sync();
        if (rank == 0 && tid == 0){
            float t = 0.f;
            #pragma unroll
            for (int r = 0; r < 4; ++r)
                t += *cluster.map_shared_rank(&s_dotpart, r);
            dotOut[b] = t;
        }
    }
    cluster.sync();
}

__global__ void final_kernel(float* __restrict__ outp){
    int t = threadIdx.x;
    float wd = g_dotwd[t];
    float gw = g_dotgw[t];
    #pragma unroll
    for (int o = 16; o; o >>= 1){
        wd += __shfl_xor_sync(0xffffffffu, wd, o);
        gw += __shfl_xor_sync(0xffffffffu, gw, o);
    }
    if (t == 0)
        outp[0] = 0.1f*(gw * (1.0f/B_)) - 0.1f*(wd * (1.0f/B_));
}

// ---------------- host launcher ----------------
extern "C" void kernel_launch(void* const* d_in, const int* in_sizes, int n_in,
                              void* d_out, int out_size)
{
    const float* img     = (const float*)d_in[0];
    const float* tok     = (const float*)d_in[1];
    const float* tokmask = (const float*)d_in[2];
    const int*   tdm     = (const int*)d_in[3];
    const int*   irm     = (const int*)d_in[4];
    float* out = (float*)d_out;                    // [1 | T_wd | T_gwd]
    float* outTwd  = out + 1;
    float* outTgwd = out + 1 + (size_t)B_*NM;

    __nv_bfloat16 *xh, *xl, *yh, *yl, *csh, *csl, *cth, *ctl, *gh, *gl, *th, *tl;
    float *Cxy, *Cs, *Ct, *Cg, *crow, *ccol, *dwd, *dgw;
    cudaGetSymbolAddress((void**)&xh,  g_xh);
    cudaGetSymbolAddress((void**)&xl,  g_xl);
    cudaGetSymbolAddress((void**)&yh,  g_yh);
    cudaGetSymbolAddress((void**)&yl,  g_yl);
    cudaGetSymbolAddress((void**)&csh, g_Csh);
    cudaGetSymbolAddress((void**)&csl, g_Csl);
    cudaGetSymbolAddress((void**)&cth, g_Cth);
    cudaGetSymbolAddress((void**)&ctl, g_Ctl);
    cudaGetSymbolAddress((void**)&gh,  g_gamh);
    cudaGetSymbolAddress((void**)&gl,  g_gaml);
    cudaGetSymbolAddress((void**)&th,  g_tmph);
    cudaGetSymbolAddress((void**)&tl,  g_tmpl);
    cudaGetSymbolAddress((void**)&Cxy, g_Cxy);
    cudaGetSymbolAddress((void**)&Cs,  g_Cs);
    cudaGetSymbolAddress((void**)&Ct,  g_Ct);
    cudaGetSymbolAddress((void**)&Cg,  g_Cg);
    cudaGetSymbolAddress((void**)&crow, g_cstrow);
    cudaGetSymbolAddress((void**)&ccol, g_cstcol);
    cudaGetSymbolAddress((void**)&dwd, g_dotwd);
    cudaGetSymbolAddress((void**)&dgw, g_dotgw);

    cudaFuncSetAttribute(cosmma_kernel,  cudaFuncAttributeMaxDynamicSharedMemorySize, COS_DSM);
    cudaFuncSetAttribute(gwfused_kernel, cudaFuncAttributeMaxDynamicSharedMemorySize, GWF_DSM);
    cudaFuncSetAttribute(gwmma2_kernel,  cudaFuncAttributeMaxDynamicSharedMemorySize, GW2_DSM);

    init_kernel<<<1, 64>>>();
    normalize_kernel<<<B_*(N_IMG+M_TOK), 256>>>(img, tok, tokmask, xh, xl, yh, yl);

    cosmma_kernel<<<dim3(24,1,B_), 256, COS_DSM>>>(xh, xl, yh, yl, Cxy, Cs, Ct);

    fusedCs_kernel<<<B_*N_IMG, 256>>>(Cs, irm, csh, csl, crow, th, tl);
    fusedCt_kernel<<<B_*M_TOK, 256>>>(Ct, tdm, cth, ctl, ccol);

    // Wasserstein IPOT with inline threshold (Cxy stays raw in gmem)
    ipot_kernel<<<dim3(4,B_), 256>>>(Cxy, 1, outTwd, nullptr, nullptr, dwd);

    // iter0: tmp already = rowsum(Cs)/NM (from fusedCs)
    gwmma2_kernel<<<dim3(2,4,B_), 256, GW2_DSM>>>(th, tl, cth, ctl, Cg, crow, ccol);
    ipot_kernel<<<dim3(4,B_), 256>>>(Cg, 0, nullptr, gh, gl, nullptr);

    for (int it = 1; it < 6; ++it){
        const bool last = (it == 5);
        gwfused_kernel<<<dim3(4,1,B_), 256, GWF_DSM>>>(csh, csl, gh, gl, cth, ctl,
                                                       Cg, crow, ccol,
                                                       last ? outTgwd : nullptr, dgw);
        if (it < 5)
            ipot_kernel<<<dim3(4,B_), 256>>>(Cg, 0, (it == 4) ? outTgwd : nullptr, gh, gl, nullptr);
    }

    final_kernel<<<1, 32>>>(out);
}

// round 12
// speedup vs baseline: 1.0189x; 1.0109x over previous
#include <cuda_runtime.h>
#include <cuda_bf16.h>
#include <cooperative_groups.h>
#include <math.h>

namespace cg = cooperative_groups;

#define B_    32
#define N_IMG 196
#define M_TOK 256
#define D_    1024
#define NM    (N_IMG*M_TOK)
#define KPAD  224

// ---------------- device scratch (allocation-free) ----------------
__device__ __nv_bfloat16 g_xh[B_*N_IMG*D_];
__device__ __nv_bfloat16 g_xl[B_*N_IMG*D_];
__device__ __nv_bfloat16 g_yh[B_*M_TOK*D_];
__device__ __nv_bfloat16 g_yl[B_*M_TOK*D_];
__device__ float g_Cxy[B_*NM];
__device__ float g_Cs [B_*N_IMG*N_IMG];
__device__ float g_Ct [B_*M_TOK*M_TOK];
__device__ __nv_bfloat16 g_Csh[B_*N_IMG*KPAD];
__device__ __nv_bfloat16 g_Csl[B_*N_IMG*KPAD];
__device__ __nv_bfloat16 g_Cth[B_*M_TOK*M_TOK];
__device__ __nv_bfloat16 g_Ctl[B_*M_TOK*M_TOK];
__device__ __nv_bfloat16 g_gamh[B_*NM];
__device__ __nv_bfloat16 g_gaml[B_*NM];
__device__ __nv_bfloat16 g_tmph[B_*NM];
__device__ __nv_bfloat16 g_tmpl[B_*NM];
__device__ float g_Cg[B_*NM];
__device__ float g_cstrow[B_*N_IMG];
__device__ float g_cstcol[B_*M_TOK];
__device__ unsigned g_minmax[6];
__device__ float g_dotwd[B_];
__device__ float g_dotgw[B_];

__device__ __forceinline__ unsigned enc_mono(float f){
    unsigned u = __float_as_uint(f);
    return (u & 0x80000000u) ? ~u : (u | 0x80000000u);
}
__device__ __forceinline__ float dec_mono(unsigned e){
    unsigned u = (e & 0x80000000u) ? (e ^ 0x80000000u) : ~e;
    return __uint_as_float(u);
}
__device__ __forceinline__ uint32_t smem_u32(const void* p){
    uint32_t a;
    asm("{ .reg .u64 t; cvta.to.shared.u64 t, %1; cvt.u32.u64 %0, t; }" : "=r"(a) : "l"(p));
    return a;
}
__device__ __forceinline__ void ldm_x4(unsigned* r, uint32_t addr){
    asm volatile("ldmatrix.sync.aligned.m8n8.x4.shared.b16 {%0,%1,%2,%3}, [%4];"
        : "=r"(r[0]), "=r"(r[1]), "=r"(r[2]), "=r"(r[3]) : "r"(addr));
}
__device__ __forceinline__ void ldm_x4_t(unsigned* r, uint32_t addr){
    asm volatile("ldmatrix.sync.aligned.m8n8.x4.trans.shared.b16 {%0,%1,%2,%3}, [%4];"
        : "=r"(r[0]), "=r"(r[1]), "=r"(r[2]), "=r"(r[3]) : "r"(addr));
}
__device__ __forceinline__ void mma_bf16(float* d, const unsigned* a, unsigned b0, unsigned b1){
    asm volatile("mma.sync.aligned.m16n8k16.row.col.f32.bf16.bf16.f32 "
        "{%0,%1,%2,%3}, {%4,%5,%6,%7}, {%8,%9}, {%0,%1,%2,%3};"
        : "+f"(d[0]), "+f"(d[1]), "+f"(d[2]), "+f"(d[3])
        : "r"(a[0]), "r"(a[1]), "r"(a[2]), "r"(a[3]), "r"(b0), "r"(b1));
}
__device__ __forceinline__ void split_bf16(float v, __nv_bfloat16& h, __nv_bfloat16& l){
    h = __float2bfloat16(v);
    l = __float2bfloat16(v - __bfloat162float(h));
}
__device__ __forceinline__ void cp16(uint32_t d, const void* s, bool v){
    int sz = v ? 16 : 0;
    asm volatile("cp.async.ca.shared.global [%0], [%1], 16, %2;" :: "r"(d), "l"(s), "r"(sz));
}
#define CP_COMMIT() asm volatile("cp.async.commit_group;" ::: "memory")
#define CP_WAIT1()  asm volatile("cp.async.wait_group 1;" ::: "memory")
#define CP_WAIT0()  asm volatile("cp.async.wait_group 0;" ::: "memory")

// ---------------- init ----------------
__global__ void init_kernel(){
    int t = threadIdx.x;
    if (t < 3){ g_minmax[2*t] = 0xFFFFFFFFu; g_minmax[2*t+1] = 0u; }
    if (t < B_) g_dotgw[t] = 0.f;
}

// ---------------- merged normalize: img rows then tok rows ----------------
__global__ void normalize_kernel(const float* __restrict__ img,
                                 const float* __restrict__ tok,
                                 const float* __restrict__ tokmask,
                                 __nv_bfloat16* __restrict__ xh, __nv_bfloat16* __restrict__ xl,
                                 __nv_bfloat16* __restrict__ yh, __nv_bfloat16* __restrict__ yl)
{
    const int gb = blockIdx.x;
    const bool isTok = gb >= B_*N_IMG;
    const int bp = isTok ? (gb - B_*N_IMG) : gb;
    const float* v = (isTok ? tok : img) + (size_t)bp * D_;
    float mk = 1.0f;
    if (isTok) mk = tokmask[bp];
    __nv_bfloat16* oh = isTok ? yh : xh;
    __nv_bfloat16* ol = isTok ? yl : xl;

    float ss = 0.f;
    for (int d = threadIdx.x; d < D_; d += blockDim.x){
        float t = v[d] * mk;
        ss += t*t;
    }
    #pragma unroll
    for (int o = 16; o; o >>= 1) ss += __shfl_xor_sync(0xffffffffu, ss, o);
    __shared__ float sred[8];
    if ((threadIdx.x & 31) == 0) sred[threadIdx.x >> 5] = ss;
    __syncthreads();
    __shared__ float s_inv;
    if (threadIdx.x == 0){
        float t = 0.f;
        for (int w = 0; w < 8; ++w) t += sred[w];
        s_inv = 1.0f / (sqrtf(t) + 1e-12f);
    }
    __syncthreads();
    const float scale = s_inv * mk;
    const size_t base = (size_t)bp * D_;
    for (int d = threadIdx.x; d < D_; d += blockDim.x){
        float t = v[d] * scale;
        __nv_bfloat16 hi, lo; split_bf16(t, hi, lo);
        oh[base + d] = hi;
        ol[base + d] = lo;
    }
}

// ============ merged cosine GEMMs: CTA 64x128, occ 2, 3-stage ============
#define LDT 40
#define COS_DSM (3*30720)

__global__ void __launch_bounds__(256,2)
cosmma_kernel(const __nv_bfloat16* __restrict__ xh, const __nv_bfloat16* __restrict__ xl,
              const __nv_bfloat16* __restrict__ yh, const __nv_bfloat16* __restrict__ yl,
              float* __restrict__ Cxy, float* __restrict__ Cs, float* __restrict__ Ct)
{
    extern __shared__ char dyn[];
    const uint32_t sb = smem_u32(dyn);

    const int tile = blockIdx.x;
    const int which = tile >> 3;
    const int sub   = tile & 7;
    const int b     = blockIdx.z;
    const int m0    = (sub >> 1) * 64;
    const int j0    = (sub & 1) * 128;

    const __nv_bfloat16* Ah = (which == 2) ? yh : xh;
    const __nv_bfloat16* Al = (which == 2) ? yl : xl;
    const __nv_bfloat16* Bh = (which == 1) ? xh : yh;
    const __nv_bfloat16* Bl = (which == 1) ? xl : yl;
    const int Mz = (which == 2) ? M_TOK : N_IMG;
    const int Nz = (which == 1) ? N_IMG : M_TOK;
    float* Cout = (which == 0) ? Cxy : ((which == 1) ? Cs : Ct);

    const int tid  = threadIdx.x;
    const int lane = tid & 31;
    const int wid  = tid >> 5;
    const int wm   = wid >> 2;
    const int wn   = wid & 3;

    const size_t abase = (size_t)b * Mz * D_;
    const size_t bbase = (size_t)b * Nz * D_;

    const int a_row = tid >> 2, a_quad = tid & 3;
    const bool avalid = (m0 + a_row) < Mz;
    const uint32_t aoff = (uint32_t)((a_row*LDT + a_quad*8) * 2);

    const int arow_l = lane & 15, ahalf = lane >> 4;
    const int bg = lane >> 3;
    const int b_noff = ((bg >> 1) << 3) + (lane & 7);
    const int b_koff = (bg & 1) << 3;

    float acc[2][4][4];
    #pragma unroll
    for (int mt = 0; mt < 2; ++mt)
        #pragma unroll
        for (int nt = 0; nt < 4; ++nt)
            #pragma unroll
            for (int q = 0; q < 4; ++q) acc[mt][nt][q] = 0.f;

    auto issue_tile = [&](int kc, int buf){
        const uint32_t base = sb + (uint32_t)buf*30720u;
        {
            const size_t go = abase + (size_t)(m0 + a_row)*D_ + kc*32 + a_quad*8;
            const size_t gs = avalid ? go : abase;
            cp16(base + aoff, Ah + gs, avalid);
            cp16(base + 5120u + aoff, Al + gs, avalid);
        }
        #pragma unroll
        for (int p = 0; p < 2; ++p){
            int idx = tid + p*256;
            int row = idx >> 2, quad = idx & 3;
            const bool bv = (j0 + row) < Nz;
            const size_t go = bbase + (size_t)(j0 + row)*D_ + kc*32 + quad*8;
            const size_t gs = bv ? go : bbase;
            const uint32_t so = (uint32_t)((row*LDT + quad*8) * 2);
            cp16(base + 10240u + so, Bh + gs, bv);
            cp16(base + 20480u + so, Bl + gs, bv);
        }
        CP_COMMIT();
    };

    issue_tile(0, 0);
    issue_tile(1, 1);
    for (int kc = 0; kc < 32; ++kc){
        if (kc == 31){ CP_WAIT0(); } else { CP_WAIT1(); }
        __syncthreads();
        if (kc + 2 < 32) issue_tile(kc + 2, (kc + 2) % 3);

        const uint32_t base = sb + (uint32_t)(kc % 3)*30720u;
        const uint32_t baAh = base;
        const uint32_t baAl = base + 5120u;
        const uint32_t baBh = base + 10240u;
        const uint32_t baBl = base + 20480u;

        #pragma unroll
        for (int k16 = 0; k16 < 2; ++k16){
            unsigned ah[2][4], al[2][4], bh[2][4], bl[2][4];
            #pragma unroll
            for (int mt = 0; mt < 2; ++mt){
                uint32_t off = (uint32_t)(((wm*32 + mt*16 + arow_l)*LDT + k16*16 + ahalf*8) * 2);
                ldm_x4(ah[mt], baAh + off);
                ldm_x4(al[mt], baAl + off);
            }
            #pragma unroll
            for (int nt2 = 0; nt2 < 2; ++nt2){
                uint32_t off = (uint32_t)(((wn*32 + nt2*16 + b_noff)*LDT + k16*16 + b_koff) * 2);
                ldm_x4(bh[nt2], baBh + off);
                ldm_x4(bl[nt2], baBl + off);
            }
            #pragma unroll
            for (int mt = 0; mt < 2; ++mt)
                #pragma unroll
                for (int nt = 0; nt < 4; ++nt){
                    const int p2 = nt >> 1, s2 = (nt & 1) * 2;
                    mma_bf16(acc[mt][nt], ah[mt], bh[p2][s2], bh[p2][s2+1]);
                    mma_bf16(acc[mt][nt], ah[mt], bl[p2][s2], bl[p2][s2+1]);
                    mma_bf16(acc[mt][nt], al[mt], bh[p2][s2], bh[p2][s2+1]);
                }
        }
    }

    float lmin =  3.402823466e+38f;
    float lmax = -3.402823466e+38f;
    #pragma unroll
    for (int mt = 0; mt < 2; ++mt){
        #pragma unroll
        for (int nt = 0; nt < 4; ++nt){
            const int ibase = m0 + wm*32 + mt*16 + (lane >> 2);
            const int jbase = j0 + wn*32 + nt*8 + (lane & 3)*2;
            #pragma unroll
            for (int rr = 0; rr < 2; ++rr){
                int i = ibase + rr*8;
                if (i >= Mz) continue;
                float* crow = Cout + ((size_t)b*Mz + i)*Nz;
                #pragma unroll
                for (int cc = 0; cc < 2; ++cc){
                    int j = jbase + cc;
                    if (j >= Nz) continue;
                    float v = 1.0f - acc[mt][nt][rr*2 + cc];
                    crow[j] = v;
                    lmin = fminf(lmin, v);
                    lmax = fmaxf(lmax, v);
                }
            }
        }
    }
    #pragma unroll
    for (int o = 16; o; o >>= 1){
        lmin = fminf(lmin, __shfl_xor_sync(0xffffffffu, lmin, o));
        lmax = fmaxf(lmax, __shfl_xor_sync(0xffffffffu, lmax, o));
    }
    if (lane == 0){
        atomicMin(&g_minmax[2*which],   enc_mono(lmin));
        atomicMax(&g_minmax[2*which+1], enc_mono(lmax));
    }
}

// ============ FUSED GW chain: tmp = Cs@gamma (smem), Cg = Cst - 2*tmp@Ct^T ============
#define LDP 264
#define GWF_DSM 155648

__global__ void __launch_bounds__(256,1)
gwfused_kernel(const __nv_bfloat16* __restrict__ Csh, const __nv_bfloat16* __restrict__ Csl,
               const __nv_bfloat16* __restrict__ Gh,  const __nv_bfloat16* __restrict__ Gl,
               const __nv_bfloat16* __restrict__ Cth, const __nv_bfloat16* __restrict__ Ctl,
               float* __restrict__ Cout,
               const float* __restrict__ rowadd, const float* __restrict__ coladd,
               const float* __restrict__ gamF, float* __restrict__ dotOut)
{
    extern __shared__ char dyn[];
    const uint32_t sb = smem_u32(dyn);
    const uint32_t TMPH = sb + 88064u;
    const uint32_t TMPL = sb + 121856u;

    const int tid  = threadIdx.x;
    const int lane = tid & 31;
    const int wid  = tid >> 5;
    const int wm   = wid >> 2;
    const int wn   = wid & 3;
    const int b    = blockIdx.z;
    const int m0   = blockIdx.x * 64;

    const int a_row = tid >> 2, a_quad = tid & 3;
    const bool avalid = (m0 + a_row) < N_IMG;
    const uint32_t aoff = (uint32_t)((a_row*LDT + a_quad*8) * 2);

    const int arow_l = lane & 15, ahalf = lane >> 4;
    const int bg = lane >> 3;
    const int b_noff = ((bg >> 1) << 3) + (lane & 7);
    const int b_koff = (bg & 1) << 3;
    const int ktr = ((lane >> 3) & 1)*8 + (lane & 7);
    const int ntr = (lane >> 4)*8;

    float acc[2][8][4];
    #pragma unroll
    for (int mt = 0; mt < 2; ++mt)
        #pragma unroll
        for (int nt = 0; nt < 8; ++nt)
            #pragma unroll
            for (int q = 0; q < 4; ++q) acc[mt][nt][q] = 0.f;

    auto issue1 = [&](int kc, int buf){
        const int kbase = kc*32;
        {
            const size_t go = ((size_t)b*N_IMG + (m0 + a_row))*KPAD + kbase + a_quad*8;
            const size_t gs = avalid ? go : (size_t)b*N_IMG*KPAD;
            cp16(sb + buf*5120u + aoff, Csh + gs, avalid);
            cp16(sb + 10240u + buf*5120u + aoff, Csl + gs, avalid);
        }
        #pragma unroll
        for (int p = 0; p < 4; ++p){
            int idx = tid + p*256;
            int kk = idx >> 5, nn = (idx & 31)*8;
            const bool bv = (kbase + kk) < N_IMG;
            const size_t go = ((size_t)b*N_IMG + kbase + kk)*M_TOK + nn;
            const size_t gs = bv ? go : (size_t)b*NM;
            const uint32_t so = (uint32_t)((kk*LDP + nn) * 2);
            cp16(sb + 20480u + buf*16896u + so, Gh + gs, bv);
            cp16(sb + 54272u + buf*16896u + so, Gl + gs, bv);
        }
        CP_COMMIT();
    };

    issue1(0, 0);
    for (int kc = 0; kc < 7; ++kc){
        if (kc < 6){ issue1(kc+1, (kc+1)&1); CP_WAIT1(); }
        else       { CP_WAIT0(); }
        __syncthreads();

        const int buf = kc & 1;
        const uint32_t baAh = sb + buf*5120u;
        const uint32_t baAl = sb + 10240u + buf*5120u;
        const uint32_t baBh = sb + 20480u + buf*16896u;
        const uint32_t baBl = sb + 54272u + buf*16896u;

        #pragma unroll
        for (int k16 = 0; k16 < 2; ++k16){
            unsigned ah[2][4], al[2][4], bh[4][4], bl[4][4];
            #pragma unroll
            for (int mt = 0; mt < 2; ++mt){
                uint32_t off = (uint32_t)(((wm*32 + mt*16 + arow_l)*LDT + k16*16 + ahalf*8) * 2);
                ldm_x4(ah[mt], baAh + off);
                ldm_x4(al[mt], baAl + off);
            }
            #pragma unroll
            for (int nt2 = 0; nt2 < 4; ++nt2){
                uint32_t off = (uint32_t)(((k16*16 + ktr)*LDP + wn*64 + nt2*16 + ntr) * 2);
                ldm_x4_t(bh[nt2], baBh + off);
                ldm_x4_t(bl[nt2], baBl + off);
            }
            #pragma unroll
            for (int mt = 0; mt < 2; ++mt)
                #pragma unroll
                for (int nt = 0; nt < 8; ++nt){
                    const int p2 = nt >> 1, s2 = (nt & 1) * 2;
                    mma_bf16(acc[mt][nt], ah[mt], bh[p2][s2], bh[p2][s2+1]);
                    mma_bf16(acc[mt][nt], ah[mt], bl[p2][s2], bl[p2][s2+1]);
                    mma_bf16(acc[mt][nt], al[mt], bh[p2][s2], bh[p2][s2+1]);
                }
        }
        __syncthreads();
    }

    auto issue2 = [&](int kc, int buf){
        #pragma unroll
        for (int p = 0; p < 4; ++p){
            int idx = tid + p*256;
            int row = idx >> 2, quad = idx & 3;
            const size_t go = ((size_t)b*M_TOK + row)*M_TOK + kc*32 + quad*8;
            const uint32_t so = (uint32_t)((row*LDT + quad*8) * 2);
            cp16(sb + buf*20480u + so, Cth + go, true);
            cp16(sb + 40960u + buf*20480u + so, Ctl + go, true);
        }
        CP_COMMIT();
    };
    issue2(0, 0);

    #pragma unroll
    for (int mt = 0; mt < 2; ++mt){
        #pragma unroll
        for (int nt = 0; nt < 8; ++nt){
            const int il = wm*32 + mt*16 + (lane >> 2);
            const int jb = wn*64 + nt*8 + (lane & 3)*2;
            #pragma unroll
            for (int rr = 0; rr < 2; ++rr){
                const int i = il + rr*8;
                #pragma unroll
                for (int cc = 0; cc < 2; ++cc){
                    const int j = jb + cc;
                    __nv_bfloat16 h, l;
                    split_bf16(acc[mt][nt][rr*2 + cc], h, l);
                    *reinterpret_cast<__nv_bfloat16*>((char*)dyn + 88064u + (i*LDP + j)*2) = h;
                    *reinterpret_cast<__nv_bfloat16*>((char*)dyn + 121856u + (i*LDP + j)*2) = l;
                }
            }
        }
    }
    issue2(1, 1);
    __syncthreads();

    #pragma unroll
    for (int mt = 0; mt < 2; ++mt)
        #pragma unroll
        for (int nt = 0; nt < 8; ++nt)
            #pragma unroll
            for (int q = 0; q < 4; ++q) acc[mt][nt][q] = 0.f;

    for (int kc = 0; kc < 8; ++kc){
        if (kc < 7){ issue2(kc+1, (kc+1)&1); CP_WAIT1(); }
        else       { CP_WAIT0(); }
        __syncthreads();

        const int buf = kc & 1;
        const uint32_t baBh = sb + buf*20480u;
        const uint32_t baBl = sb + 40960u + buf*20480u;

        #pragma unroll
        for (int k16 = 0; k16 < 2; ++k16){
            unsigned ah[2][4], al[2][4], bh[4][4], bl[4][4];
            #pragma unroll
            for (int mt = 0; mt < 2; ++mt){
                uint32_t off = (uint32_t)(((wm*32 + mt*16 + arow_l)*LDP + kc*32 + k16*16 + ahalf*8) * 2);
                ldm_x4(ah[mt], TMPH + off);
                ldm_x4(al[mt], TMPL + off);
            }
            #pragma unroll
            for (int nt2 = 0; nt2 < 4; ++nt2){
                uint32_t off = (uint32_t)(((wn*64 + nt2*16 + b_noff)*LDT + k16*16 + b_koff) * 2);
                ldm_x4(bh[nt2], baBh + off);
                ldm_x4(bl[nt2], baBl + off);
            }
            #pragma unroll
            for (int mt = 0; mt < 2; ++mt)
                #pragma unroll
                for (int nt = 0; nt < 8; ++nt){
                    const int p2 = nt >> 1, s2 = (nt & 1) * 2;
                    mma_bf16(acc[mt][nt], ah[mt], bh[p2][s2], bh[p2][s2+1]);
                    mma_bf16(acc[mt][nt], ah[mt], bl[p2][s2], bl[p2][s2+1]);
                    mma_bf16(acc[mt][nt], al[mt], bh[p2][s2], bh[p2][s2+1]);
                }
        }
        __syncthreads();
    }

    float dot = 0.f;
    #pragma unroll
    for (int mt = 0; mt < 2; ++mt){
        #pragma unroll
        for (int nt = 0; nt < 8; ++nt){
            const int ibase = m0 + wm*32 + mt*16 + (lane >> 2);
            const int jbase = wn*64 + nt*8 + (lane & 3)*2;
            #pragma unroll
            for (int rr = 0; rr < 2; ++rr){
                int i = ibase + rr*8;
                if (i >= N_IMG) continue;
                const size_t ro = ((size_t)b*N_IMG + i)*M_TOK;
                const float ra = rowadd[b*N_IMG + i];
                #pragma unroll
                for (int cc = 0; cc < 2; ++cc){
                    int j = jbase + cc;
                    float r = ra + coladd[b*M_TOK + j] - 2.0f*acc[mt][nt][rr*2 + cc];
                    Cout[ro + j] = r;
                    if (gamF) dot += r * gamF[ro + j];
                }
            }
        }
    }
    if (gamF){
        #pragma unroll
        for (int o = 16; o; o >>= 1) dot += __shfl_xor_sync(0xffffffffu, dot, o);
        if (lane == 0) atomicAdd(&dotOut[b], dot);
    }
}

// ============ GW GEMM 2 standalone (iter0) ============
#define GW2_DSM 61440

__global__ void __launch_bounds__(256,1)
gwmma2_kernel(const __nv_bfloat16* __restrict__ Ah, const __nv_bfloat16* __restrict__ Al,
              const __nv_bfloat16* __restrict__ Bh, const __nv_bfloat16* __restrict__ Bl,
              float* __restrict__ Cout,
              const float* __restrict__ rowadd, const float* __restrict__ coladd)
{
    extern __shared__ char dyn[];
    const uint32_t sb = smem_u32(dyn);

    const int tid  = threadIdx.x;
    const int lane = tid & 31;
    const int wid  = tid >> 5;
    const int wm   = wid >> 2;
    const int wn   = wid & 3;
    const int b    = blockIdx.z;
    const int m0   = blockIdx.y * 64;
    const int j0   = blockIdx.x * 128;

    const int a_row = tid >> 2, a_quad = tid & 3;
    const bool avalid = (m0 + a_row) < N_IMG;
    const uint32_t aoff = (uint32_t)((a_row*LDT + a_quad*8) * 2);

    const int arow_l = lane & 15, ahalf = lane >> 4;
    const int bg = lane >> 3;
    const int b_noff = ((bg >> 1) << 3) + (lane & 7);
    const int b_koff = (bg & 1) << 3;

    float acc[2][4][4];
    #pragma unroll
    for (int mt = 0; mt < 2; ++mt)
        #pragma unroll
        for (int nt = 0; nt < 4; ++nt)
            #pragma unroll
            for (int q = 0; q < 4; ++q) acc[mt][nt][q] = 0.f;

    auto issue_tile = [&](int kc, int buf){
        const uint32_t ah = sb + buf*5120u;
        const uint32_t al = sb + 10240u + buf*5120u;
        const uint32_t bh = sb + 20480u + buf*10240u;
        const uint32_t bl = sb + 40960u + buf*10240u;
        {
            const size_t go = ((size_t)b*N_IMG + (m0 + a_row))*M_TOK + kc*32 + a_quad*8;
            const size_t gs = avalid ? go : (size_t)b*NM;
            cp16(ah + aoff, Ah + gs, avalid);
            cp16(al + aoff, Al + gs, avalid);
        }
        #pragma unroll
        for (int p = 0; p < 2; ++p){
            int idx = tid + p*256;
            int row = idx >> 2, quad = idx & 3;
            const size_t go = ((size_t)b*M_TOK + j0 + row)*M_TOK + kc*32 + quad*8;
            const uint32_t so = (uint32_t)((row*LDT + quad*8) * 2);
            cp16(bh + so, Bh + go, true);
            cp16(bl + so, Bl + go, true);
        }
        CP_COMMIT();
    };

    issue_tile(0, 0);
    for (int kc = 0; kc < 8; ++kc){
        if (kc < 7){ issue_tile(kc+1, (kc+1)&1); CP_WAIT1(); }
        else       { CP_WAIT0(); }
        __syncthreads();

        const int buf = kc & 1;
        const uint32_t baAh = sb + buf*5120u;
        const uint32_t baAl = sb + 10240u + buf*5120u;
        const uint32_t baBh = sb + 20480u + buf*10240u;
        const uint32_t baBl = sb + 40960u + buf*10240u;

        #pragma unroll
        for (int k16 = 0; k16 < 2; ++k16){
            unsigned ah[2][4], al[2][4], bh[2][4], bl[2][4];
            #pragma unroll
            for (int mt = 0; mt < 2; ++mt){
                uint32_t off = (uint32_t)(((wm*32 + mt*16 + arow_l)*LDT + k16*16 + ahalf*8) * 2);
                ldm_x4(ah[mt], baAh + off);
                ldm_x4(al[mt], baAl + off);
            }
            #pragma unroll
            for (int nt2 = 0; nt2 < 2; ++nt2){
                uint32_t off = (uint32_t)(((wn*32 + nt2*16 + b_noff)*LDT + k16*16 + b_koff) * 2);
                ldm_x4(bh[nt2], baBh + off);
                ldm_x4(bl[nt2], baBl + off);
            }
            #pragma unroll
            for (int mt = 0; mt < 2; ++mt)
                #pragma unroll
                for (int nt = 0; nt < 4; ++nt){
                    const int p2 = nt >> 1, s2 = (nt & 1) * 2;
                    mma_bf16(acc[mt][nt], ah[mt], bh[p2][s2], bh[p2][s2+1]);
                    mma_bf16(acc[mt][nt], ah[mt], bl[p2][s2], bl[p2][s2+1]);
                    mma_bf16(acc[mt][nt], al[mt], bh[p2][s2], bh[p2][s2+1]);
                }
        }
        __syncthreads();
    }

    #pragma unroll
    for (int mt = 0; mt < 2; ++mt){
        #pragma unroll
        for (int nt = 0; nt < 4; ++nt){
            const int ibase = m0 + wm*32 + mt*16 + (lane >> 2);
            const int jbase = j0 + wn*32 + nt*8 + (lane & 3)*2;
            #pragma unroll
            for (int rr = 0; rr < 2; ++rr){
                int i = ibase + rr*8;
                if (i >= N_IMG) continue;
                const size_t ro = ((size_t)b*N_IMG + i)*M_TOK;
                const float ra = rowadd[b*N_IMG + i];
                #pragma unroll
                for (int cc = 0; cc < 2; ++cc){
                    int j = jbase + cc;
                    Cout[ro + j] = ra + coladd[b*M_TOK + j] - 2.0f*acc[mt][nt][rr*2 + cc];
                }
            }
        }
    }
}

// ---------------- merged fused Cs + Ct elementwise pass ----------------
__global__ void fusedC_kernel(float* __restrict__ Cs, float* __restrict__ Ct,
                              const int* __restrict__ irm, const int* __restrict__ tdm,
                              __nv_bfloat16* __restrict__ csh, __nv_bfloat16* __restrict__ csl,
                              __nv_bfloat16* __restrict__ cth, __nv_bfloat16* __restrict__ ctl,
                              float* __restrict__ crow, float* __restrict__ ccol,
                              __nv_bfloat16* __restrict__ tmph, __nv_bfloat16* __restrict__ tmpl)
{
    const int gb = blockIdx.x;
    const int t = threadIdx.x;

    if (gb < B_*N_IMG){
        // ---- Cs path: thresh+mask+split(pad) + rowmeansq + rowsum->tmp ----
        const float mn = dec_mono(g_minmax[2]);
        const float mx = dec_mono(g_minmax[3]);
        const float thr = mn + 0.1f*(mx - mn);
        const int r = gb;

        float v = 0.f;
        if (t < N_IMG){
            size_t si = (size_t)r*N_IMG + t;
            v = Cs[si] - thr;
            v = v > 0.f ? v : 0.f;
            v *= (irm[si] == 1 ? 1.0f : 1e-5f);
            Cs[si] = v;
        }
        if (t < KPAD){
            __nv_bfloat16 h, l; split_bf16(v, h, l);
            csh[(size_t)r*KPAD + t] = h;
            csl[(size_t)r*KPAD + t] = l;
        }
        float ss = v*v, s1 = v;
        #pragma unroll
        for (int o = 16; o; o >>= 1){
            ss += __shfl_xor_sync(0xffffffffu, ss, o);
            s1 += __shfl_xor_sync(0xffffffffu, s1, o);
        }
        __shared__ float sq[8], sm[8];
        if ((t & 31) == 0){ sq[t>>5] = ss; sm[t>>5] = s1; }
        __syncthreads();
        __shared__ float s_val;
        if (t == 0){
            float a = 0.f, c = 0.f;
            for (int w = 0; w < 8; ++w){ a += sq[w]; c += sm[w]; }
            crow[r] = a / (float)N_IMG;
            s_val = c / (float)NM;
        }
        __syncthreads();
        __nv_bfloat16 h, l; split_bf16(s_val, h, l);
        tmph[(size_t)r*M_TOK + t] = h;
        tmpl[(size_t)r*M_TOK + t] = l;
    } else {
        // ---- Ct path: thresh+mask+split + rowmeansq ----
        const float mn = dec_mono(g_minmax[4]);
        const float mx = dec_mono(g_minmax[5]);
        const float thr = mn + 0.1f*(mx - mn);
        const int r = gb - B_*N_IMG;

        size_t si = (size_t)r*M_TOK + t;
        float v = Ct[si] - thr;
        v = v > 0.f ? v : 0.f;
        v *= (tdm[si] == 1 ? 1.0f : 1e-5f);
        Ct[si] = v;
        __nv_bfloat16 h, l; split_bf16(v, h, l);
        cth[si] = h;
        ctl[si] = l;

        float ss = v*v;
        #pragma unroll
        for (int o = 16; o; o >>= 1) ss += __shfl_xor_sync(0xffffffffu, ss, o);
        __shared__ float sq2[8];
        if ((t & 31) == 0) sq2[t>>5] = ss;
        __syncthreads();
        if (t == 0){
            float a = 0.f;
            for (int w = 0; w < 8; ++w) a += sq2[w];
            ccol[r] = a / (float)M_TOK;
        }
    }
}

// ---------------- IPOT: 4-CTA cluster; dual-job grid (WD on Cw, gamma on Cg) ----------------
// grid (4, nbW + nbG). blockIdx.y < nbW -> WD job (thresh, ToutW, dotW);
// else gamma job on Cg (Gh/Gl, optional ToutG).
__global__ void __cluster_dims__(4,1,1) __launch_bounds__(256,1)
ipot_kernel(const float* __restrict__ Cw, const float* __restrict__ Cg, int nbW,
            float* __restrict__ ToutW, float* __restrict__ ToutG,
            __nv_bfloat16* __restrict__ Gh, __nv_bfloat16* __restrict__ Gl,
            float* __restrict__ dotW)
{
    cg::cluster_group cluster = cg::this_cluster();
    const int rank = blockIdx.x;
    const int by   = blockIdx.y;
    const bool wdJob = by < nbW;
    const int b    = wdJob ? by : (by - nbW);
    const int tid  = threadIdx.x;
    const int jl   = tid & 63;
    const int rq   = tid >> 6;
    const int lane = tid & 31;
    const int wid  = tid >> 5;
    const int jg   = rank*64 + jl;
    const float* C = (wdJob ? Cw : Cg) + (size_t)b * NM;

    float thr = 0.f;
    if (wdJob){
        const float mn = dec_mono(g_minmax[0]);
        const float mx = dec_mono(g_minmax[1]);
        thr = mn + 0.1f*(mx - mn);
    }
    float* ToutF = wdJob ? (ToutW ? ToutW + (size_t)b*NM : nullptr)
                         : (ToutG ? ToutG + (size_t)b*NM : nullptr);

    __shared__ float s_delta[196];
    __shared__ float s_part[8][49];
    __shared__ float s_rowpart[2][196];
    __shared__ float s_col[4][64];
    __shared__ float s_dred[8];
    __shared__ float s_dotpart;

    float E[49], T[49];
    #pragma unroll
    for (int k = 0; k < 49; ++k){
        float c = fmaxf(C[(rq + 4*k)*M_TOK + jg] - thr, 0.f);
        E[k] = expf(-2.0f * c);
        T[k] = 1.0f;
    }
    float sig = 1.0f/256.0f;
    __syncthreads();

    for (int it = 0; it < 20; ++it){
        const int buf = it & 1;
        #pragma unroll
        for (int k = 0; k < 49; ++k){
            float v = E[k]*T[k]*sig;
            v += __shfl_xor_sync(0xffffffffu, v, 16);
            v += __shfl_xor_sync(0xffffffffu, v, 8);
            v += __shfl_xor_sync(0xffffffffu, v, 4);
            v += __shfl_xor_sync(0xffffffffu, v, 2);
            v += __shfl_xor_sync(0xffffffffu, v, 1);
            if (lane == 0) s_part[wid][k] = v;
        }
        __syncthreads();
        if (tid < 196){
            int r2 = tid & 3, k2 = tid >> 2;
            s_rowpart[buf][tid] = s_part[r2*2][k2] + s_part[r2*2+1][k2];
        }
        cluster.sync();
        if (tid < 196){
            float s = 0.f;
            #pragma unroll
            for (int r = 0; r < 4; ++r)
                s += *(cluster.map_shared_rank(&s_rowpart[buf][0], r) + tid);
            s_delta[tid] = 1.0f / (196.0f * s);
        }
        __syncthreads();
        float cs = 0.f;
        #pragma unroll
        for (int k = 0; k < 49; ++k)
            cs += E[k]*T[k]*s_delta[rq + 4*k];
        s_col[rq][jl] = cs;
        __syncthreads();
        {
            float c = s_col[0][jl] + s_col[1][jl] + s_col[2][jl] + s_col[3][jl];
            sig = 1.0f / (256.0f * c);
        }
        #pragma unroll
        for (int k = 0; k < 49; ++k)
            T[k] = s_delta[rq + 4*k] * E[k] * T[k] * sig;
    }

    if (ToutF){
        #pragma unroll
        for (int k = 0; k < 49; ++k)
            ToutF[(size_t)(rq + 4*k)*M_TOK + jg] = T[k];
    }
    if (!wdJob){
        const size_t base = (size_t)b * NM;
        #pragma unroll
        for (int k = 0; k < 49; ++k){
            __nv_bfloat16 h, l; split_bf16(T[k], h, l);
            const size_t o = base + (size_t)(rq + 4*k)*M_TOK + jg;
            Gh[o] = h; Gl[o] = l;
        }
    }

    if (wdJob && dotW){
        float dot = 0.f;
        #pragma unroll
        for (int k = 0; k < 49; ++k)
            dot += fmaxf(C[(rq + 4*k)*M_TOK + jg] - thr, 0.f) * T[k];
        #pragma unroll
        for (int o = 16; o; o >>= 1) dot += __shfl_xor_sync(0xffffffffu, dot, o);
        if (lane == 0) s_dred[wid] = dot;
        __syncthreads();
        if (tid == 0){
            float t = 0.f;
            for (int w = 0; w < 8; ++w) t += s_dred[w];
            s_dotpart = t;
        }
        cluster.sync();
        if (rank == 0 && tid == 0){
            float t = 0.f;
            #pragma unroll
            for (int r = 0; r < 4; ++r)
                t += *cluster.map_shared_rank(&s_dotpart, r);
            dotW[b] = t;
        }
    }
    cluster.sync();
}

__global__ void final_kernel(float* __restrict__ outp){
    int t = threadIdx.x;
    float wd = g_dotwd[t];
    float gw = g_dotgw[t];
    #pragma unroll
    for (int o = 16; o; o >>= 1){
        wd += __shfl_xor_sync(0xffffffffu, wd, o);
        gw += __shfl_xor_sync(0xffffffffu, gw, o);
    }
    if (t == 0)
        outp[0] = 0.1f*(gw * (1.0f/B_)) - 0.1f*(wd * (1.0f/B_));
}

// ---------------- host launcher ----------------
extern "C" void kernel_launch(void* const* d_in, const int* in_sizes, int n_in,
                              void* d_out, int out_size)
{
    const float* img     = (const float*)d_in[0];
    const float* tok     = (const float*)d_in[1];
    const float* tokmask = (const float*)d_in[2];
    const int*   tdm     = (const int*)d_in[3];
    const int*   irm     = (const int*)d_in[4];
    float* out = (float*)d_out;                    // [1 | T_wd | T_gwd]
    float* outTwd  = out + 1;
    float* outTgwd = out + 1 + (size_t)B_*NM;

    __nv_bfloat16 *xh, *xl, *yh, *yl, *csh, *csl, *cth, *ctl, *gh, *gl, *th, *tl;
    float *Cxy, *Cs, *Ct, *Cg, *crow, *ccol, *dwd, *dgw;
    cudaGetSymbolAddress((void**)&xh,  g_xh);
    cudaGetSymbolAddress((void**)&xl,  g_xl);
    cudaGetSymbolAddress((void**)&yh,  g_yh);
    cudaGetSymbolAddress((void**)&yl,  g_yl);
    cudaGetSymbolAddress((void**)&csh, g_Csh);
    cudaGetSymbolAddress((void**)&csl, g_Csl);
    cudaGetSymbolAddress((void**)&cth, g_Cth);
    cudaGetSymbolAddress((void**)&ctl, g_Ctl);
    cudaGetSymbolAddress((void**)&gh,  g_gamh);
    cudaGetSymbolAddress((void**)&gl,  g_gaml);
    cudaGetSymbolAddress((void**)&th,  g_tmph);
    cudaGetSymbolAddress((void**)&tl,  g_tmpl);
    cudaGetSymbolAddress((void**)&Cxy, g_Cxy);
    cudaGetSymbolAddress((void**)&Cs,  g_Cs);
    cudaGetSymbolAddress((void**)&Ct,  g_Ct);
    cudaGetSymbolAddress((void**)&Cg,  g_Cg);
    cudaGetSymbolAddress((void**)&crow, g_cstrow);
    cudaGetSymbolAddress((void**)&ccol, g_cstcol);
    cudaGetSymbolAddress((void**)&dwd, g_dotwd);
    cudaGetSymbolAddress((void**)&dgw, g_dotgw);

    cudaFuncSetAttribute(cosmma_kernel,  cudaFuncAttributeMaxDynamicSharedMemorySize, COS_DSM);
    cudaFuncSetAttribute(gwfused_kernel, cudaFuncAttributeMaxDynamicSharedMemorySize, GWF_DSM);
    cudaFuncSetAttribute(gwmma2_kernel,  cudaFuncAttributeMaxDynamicSharedMemorySize, GW2_DSM);

    init_kernel<<<1, 64>>>();
    normalize_kernel<<<B_*(N_IMG+M_TOK), 256>>>(img, tok, tokmask, xh, xl, yh, yl);

    cosmma_kernel<<<dim3(24,1,B_), 256, COS_DSM>>>(xh, xl, yh, yl, Cxy, Cs, Ct);

    fusedC_kernel<<<B_*(N_IMG+M_TOK), 256>>>(Cs, Ct, irm, tdm, csh, csl, cth, ctl,
                                             crow, ccol, th, tl);

    // iter0: tmp already = rowsum(Cs)/NM (from fusedC)
    gwmma2_kernel<<<dim3(2,4,B_), 256, GW2_DSM>>>(th, tl, cth, ctl, Cg, crow, ccol);

    // merged: WD ipot on Cxy (inline thresh) + gamma ipot on Cg, one 256-CTA launch
    ipot_kernel<<<dim3(4, 2*B_), 256>>>(Cxy, Cg, B_, outTwd, nullptr, gh, gl, dwd);

    for (int it = 1; it < 6; ++it){
        const bool last = (it == 5);
        gwfused_kernel<<<dim3(4,1,B_), 256, GWF_DSM>>>(csh, csl, gh, gl, cth, ctl,
                                                       Cg, crow, ccol,
                                                       last ? outTgwd : nullptr, dgw);
        if (it < 5)
            ipot_kernel<<<dim3(4,B_), 256>>>(nullptr, Cg, 0, nullptr,
                                             (it == 4) ? outTgwd : nullptr, gh, gl, nullptr);
    }

    final_kernel<<<1, 32>>>(out);
}

// round 13
// speedup vs baseline: 1.1879x; 1.1659x over previous
#include <cuda_runtime.h>
#include <cuda_bf16.h>
#include <cooperative_groups.h>
#include <math.h>

namespace cg = cooperative_groups;

#define B_    32
#define N_IMG 196
#define M_TOK 256
#define D_    1024
#define NM    (N_IMG*M_TOK)
#define KPAD  224

// ---------------- device scratch (allocation-free) ----------------
__device__ __nv_bfloat16 g_xh[B_*N_IMG*D_];
__device__ __nv_bfloat16 g_xl[B_*N_IMG*D_];
__device__ __nv_bfloat16 g_yh[B_*M_TOK*D_];
__device__ __nv_bfloat16 g_yl[B_*M_TOK*D_];
__device__ float g_Cxy[B_*NM];
__device__ float g_Cs [B_*N_IMG*N_IMG];
__device__ float g_Ct [B_*M_TOK*M_TOK];
__device__ __nv_bfloat16 g_Csh[B_*N_IMG*KPAD];
__device__ __nv_bfloat16 g_Csl[B_*N_IMG*KPAD];
__device__ __nv_bfloat16 g_Cth[B_*M_TOK*M_TOK];
__device__ __nv_bfloat16 g_Ctl[B_*M_TOK*M_TOK];
__device__ __nv_bfloat16 g_gamh[B_*NM];
__device__ __nv_bfloat16 g_gaml[B_*NM];
__device__ __nv_bfloat16 g_tmph[B_*NM];
__device__ __nv_bfloat16 g_tmpl[B_*NM];
__device__ float g_Cg[B_*NM];
__device__ float g_cstrow[B_*N_IMG];
__device__ float g_cstcol[B_*M_TOK];
__device__ unsigned g_minmax[6];
__device__ float g_dotwd[B_];
__device__ float g_dotgw[B_];

__device__ __forceinline__ unsigned enc_mono(float f){
    unsigned u = __float_as_uint(f);
    return (u & 0x80000000u) ? ~u : (u | 0x80000000u);
}
__device__ __forceinline__ float dec_mono(unsigned e){
    unsigned u = (e & 0x80000000u) ? (e ^ 0x80000000u) : ~e;
    return __uint_as_float(u);
}
__device__ __forceinline__ uint32_t smem_u32(const void* p){
    uint32_t a;
    asm("{ .reg .u64 t; cvta.to.shared.u64 t, %1; cvt.u32.u64 %0, t; }" : "=r"(a) : "l"(p));
    return a;
}
__device__ __forceinline__ void ldm_x4(unsigned* r, uint32_t addr){
    asm volatile("ldmatrix.sync.aligned.m8n8.x4.shared.b16 {%0,%1,%2,%3}, [%4];"
        : "=r"(r[0]), "=r"(r[1]), "=r"(r[2]), "=r"(r[3]) : "r"(addr));
}
__device__ __forceinline__ void ldm_x4_t(unsigned* r, uint32_t addr){
    asm volatile("ldmatrix.sync.aligned.m8n8.x4.trans.shared.b16 {%0,%1,%2,%3}, [%4];"
        : "=r"(r[0]), "=r"(r[1]), "=r"(r[2]), "=r"(r[3]) : "r"(addr));
}
__device__ __forceinline__ void mma_bf16(float* d, const unsigned* a, unsigned b0, unsigned b1){
    asm volatile("mma.sync.aligned.m16n8k16.row.col.f32.bf16.bf16.f32 "
        "{%0,%1,%2,%3}, {%4,%5,%6,%7}, {%8,%9}, {%0,%1,%2,%3};"
        : "+f"(d[0]), "+f"(d[1]), "+f"(d[2]), "+f"(d[3])
        : "r"(a[0]), "r"(a[1]), "r"(a[2]), "r"(a[3]), "r"(b0), "r"(b1));
}
__device__ __forceinline__ void split_bf16(float v, __nv_bfloat16& h, __nv_bfloat16& l){
    h = __float2bfloat16(v);
    l = __float2bfloat16(v - __bfloat162float(h));
}
__device__ __forceinline__ void cp16(uint32_t d, const void* s, bool v){
    int sz = v ? 16 : 0;
    asm volatile("cp.async.ca.shared.global [%0], [%1], 16, %2;" :: "r"(d), "l"(s), "r"(sz));
}
#define CP_COMMIT() asm volatile("cp.async.commit_group;" ::: "memory")
#define CP_WAIT1()  asm volatile("cp.async.wait_group 1;" ::: "memory")
#define CP_WAIT0()  asm volatile("cp.async.wait_group 0;" ::: "memory")

// ---------------- init ----------------
__global__ void init_kernel(){
    int t = threadIdx.x;
    if (t < 3){ g_minmax[2*t] = 0xFFFFFFFFu; g_minmax[2*t+1] = 0u; }
    if (t < B_) g_dotgw[t] = 0.f;
}

// ---------------- merged normalize ----------------
__global__ void normalize_kernel(const float* __restrict__ img,
                                 const float* __restrict__ tok,
                                 const float* __restrict__ tokmask,
                                 __nv_bfloat16* __restrict__ xh, __nv_bfloat16* __restrict__ xl,
                                 __nv_bfloat16* __restrict__ yh, __nv_bfloat16* __restrict__ yl)
{
    const int gb = blockIdx.x;
    const bool isTok = gb >= B_*N_IMG;
    const int bp = isTok ? (gb - B_*N_IMG) : gb;
    const float* v = (isTok ? tok : img) + (size_t)bp * D_;
    float mk = 1.0f;
    if (isTok) mk = tokmask[bp];
    __nv_bfloat16* oh = isTok ? yh : xh;
    __nv_bfloat16* ol = isTok ? yl : xl;

    float ss = 0.f;
    for (int d = threadIdx.x; d < D_; d += blockDim.x){
        float t = v[d] * mk;
        ss += t*t;
    }
    #pragma unroll
    for (int o = 16; o; o >>= 1) ss += __shfl_xor_sync(0xffffffffu, ss, o);
    __shared__ float sred[8];
    if ((threadIdx.x & 31) == 0) sred[threadIdx.x >> 5] = ss;
    __syncthreads();
    __shared__ float s_inv;
    if (threadIdx.x == 0){
        float t = 0.f;
        for (int w = 0; w < 8; ++w) t += sred[w];
        s_inv = 1.0f / (sqrtf(t) + 1e-12f);
    }
    __syncthreads();
    const float scale = s_inv * mk;
    const size_t base = (size_t)bp * D_;
    for (int d = threadIdx.x; d < D_; d += blockDim.x){
        float t = v[d] * scale;
        __nv_bfloat16 hi, lo; split_bf16(t, hi, lo);
        oh[base + d] = hi;
        ol[base + d] = lo;
    }
}

// ============ merged cosine GEMMs: CTA 64x128, occ 2, 3-stage ============
#define LDT 40
#define COS_DSM (3*30720)

__global__ void __launch_bounds__(256,2)
cosmma_kernel(const __nv_bfloat16* __restrict__ xh, const __nv_bfloat16* __restrict__ xl,
              const __nv_bfloat16* __restrict__ yh, const __nv_bfloat16* __restrict__ yl,
              float* __restrict__ Cxy, float* __restrict__ Cs, float* __restrict__ Ct)
{
    extern __shared__ char dyn[];
    const uint32_t sb = smem_u32(dyn);

    const int tile = blockIdx.x;
    const int which = tile >> 3;
    const int sub   = tile & 7;
    const int b     = blockIdx.z;
    const int m0    = (sub >> 1) * 64;
    const int j0    = (sub & 1) * 128;

    const __nv_bfloat16* Ah = (which == 2) ? yh : xh;
    const __nv_bfloat16* Al = (which == 2) ? yl : xl;
    const __nv_bfloat16* Bh = (which == 1) ? xh : yh;
    const __nv_bfloat16* Bl = (which == 1) ? xl : yl;
    const int Mz = (which == 2) ? M_TOK : N_IMG;
    const int Nz = (which == 1) ? N_IMG : M_TOK;
    float* Cout = (which == 0) ? Cxy : ((which == 1) ? Cs : Ct);

    const int tid  = threadIdx.x;
    const int lane = tid & 31;
    const int wid  = tid >> 5;
    const int wm   = wid >> 2;
    const int wn   = wid & 3;

    const size_t abase = (size_t)b * Mz * D_;
    const size_t bbase = (size_t)b * Nz * D_;

    const int a_row = tid >> 2, a_quad = tid & 3;
    const bool avalid = (m0 + a_row) < Mz;
    const uint32_t aoff = (uint32_t)((a_row*LDT + a_quad*8) * 2);

    const int arow_l = lane & 15, ahalf = lane >> 4;
    const int bg = lane >> 3;
    const int b_noff = ((bg >> 1) << 3) + (lane & 7);
    const int b_koff = (bg & 1) << 3;

    float acc[2][4][4];
    #pragma unroll
    for (int mt = 0; mt < 2; ++mt)
        #pragma unroll
        for (int nt = 0; nt < 4; ++nt)
            #pragma unroll
            for (int q = 0; q < 4; ++q) acc[mt][nt][q] = 0.f;

    auto issue_tile = [&](int kc, int buf){
        const uint32_t base = sb + (uint32_t)buf*30720u;
        {
            const size_t go = abase + (size_t)(m0 + a_row)*D_ + kc*32 + a_quad*8;
            const size_t gs = avalid ? go : abase;
            cp16(base + aoff, Ah + gs, avalid);
            cp16(base + 5120u + aoff, Al + gs, avalid);
        }
        #pragma unroll
        for (int p = 0; p < 2; ++p){
            int idx = tid + p*256;
            int row = idx >> 2, quad = idx & 3;
            const bool bv = (j0 + row) < Nz;
            const size_t go = bbase + (size_t)(j0 + row)*D_ + kc*32 + quad*8;
            const size_t gs = bv ? go : bbase;
            const uint32_t so = (uint32_t)((row*LDT + quad*8) * 2);
            cp16(base + 10240u + so, Bh + gs, bv);
            cp16(base + 20480u + so, Bl + gs, bv);
        }
        CP_COMMIT();
    };

    issue_tile(0, 0);
    issue_tile(1, 1);
    for (int kc = 0; kc < 32; ++kc){
        if (kc == 31){ CP_WAIT0(); } else { CP_WAIT1(); }
        __syncthreads();
        if (kc + 2 < 32) issue_tile(kc + 2, (kc + 2) % 3);

        const uint32_t base = sb + (uint32_t)(kc % 3)*30720u;
        const uint32_t baAh = base;
        const uint32_t baAl = base + 5120u;
        const uint32_t baBh = base + 10240u;
        const uint32_t baBl = base + 20480u;

        #pragma unroll
        for (int k16 = 0; k16 < 2; ++k16){
            unsigned ah[2][4], al[2][4], bh[2][4], bl[2][4];
            #pragma unroll
            for (int mt = 0; mt < 2; ++mt){
                uint32_t off = (uint32_t)(((wm*32 + mt*16 + arow_l)*LDT + k16*16 + ahalf*8) * 2);
                ldm_x4(ah[mt], baAh + off);
                ldm_x4(al[mt], baAl + off);
            }
            #pragma unroll
            for (int nt2 = 0; nt2 < 2; ++nt2){
                uint32_t off = (uint32_t)(((wn*32 + nt2*16 + b_noff)*LDT + k16*16 + b_koff) * 2);
                ldm_x4(bh[nt2], baBh + off);
                ldm_x4(bl[nt2], baBl + off);
            }
            #pragma unroll
            for (int mt = 0; mt < 2; ++mt)
                #pragma unroll
                for (int nt = 0; nt < 4; ++nt){
                    const int p2 = nt >> 1, s2 = (nt & 1) * 2;
                    mma_bf16(acc[mt][nt], ah[mt], bh[p2][s2], bh[p2][s2+1]);
                    mma_bf16(acc[mt][nt], ah[mt], bl[p2][s2], bl[p2][s2+1]);
                    mma_bf16(acc[mt][nt], al[mt], bh[p2][s2], bh[p2][s2+1]);
                }
        }
    }

    float lmin =  3.402823466e+38f;
    float lmax = -3.402823466e+38f;
    #pragma unroll
    for (int mt = 0; mt < 2; ++mt){
        #pragma unroll
        for (int nt = 0; nt < 4; ++nt){
            const int ibase = m0 + wm*32 + mt*16 + (lane >> 2);
            const int jbase = j0 + wn*32 + nt*8 + (lane & 3)*2;
            #pragma unroll
            for (int rr = 0; rr < 2; ++rr){
                int i = ibase + rr*8;
                if (i >= Mz) continue;
                float* crow = Cout + ((size_t)b*Mz + i)*Nz;
                #pragma unroll
                for (int cc = 0; cc < 2; ++cc){
                    int j = jbase + cc;
                    if (j >= Nz) continue;
                    float v = 1.0f - acc[mt][nt][rr*2 + cc];
                    crow[j] = v;
                    lmin = fminf(lmin, v);
                    lmax = fmaxf(lmax, v);
                }
            }
        }
    }
    #pragma unroll
    for (int o = 16; o; o >>= 1){
        lmin = fminf(lmin, __shfl_xor_sync(0xffffffffu, lmin, o));
        lmax = fmaxf(lmax, __shfl_xor_sync(0xffffffffu, lmax, o));
    }
    if (lane == 0){
        atomicMin(&g_minmax[2*which],   enc_mono(lmin));
        atomicMax(&g_minmax[2*which+1], enc_mono(lmax));
    }
}

// ============ FUSED GW chain ============
#define LDP 264
#define GWF_DSM 155648

__global__ void __launch_bounds__(256,1)
gwfused_kernel(const __nv_bfloat16* __restrict__ Csh, const __nv_bfloat16* __restrict__ Csl,
               const __nv_bfloat16* __restrict__ Gh,  const __nv_bfloat16* __restrict__ Gl,
               const __nv_bfloat16* __restrict__ Cth, const __nv_bfloat16* __restrict__ Ctl,
               float* __restrict__ Cout,
               const float* __restrict__ rowadd, const float* __restrict__ coladd,
               const float* __restrict__ gamF, float* __restrict__ dotOut)
{
    extern __shared__ char dyn[];
    const uint32_t sb = smem_u32(dyn);
    const uint32_t TMPH = sb + 88064u;
    const uint32_t TMPL = sb + 121856u;

    const int tid  = threadIdx.x;
    const int lane = tid & 31;
    const int wid  = tid >> 5;
    const int wm   = wid >> 2;
    const int wn   = wid & 3;
    const int b    = blockIdx.z;
    const int m0   = blockIdx.x * 64;

    const int a_row = tid >> 2, a_quad = tid & 3;
    const bool avalid = (m0 + a_row) < N_IMG;
    const uint32_t aoff = (uint32_t)((a_row*LDT + a_quad*8) * 2);

    const int arow_l = lane & 15, ahalf = lane >> 4;
    const int bg = lane >> 3;
    const int b_noff = ((bg >> 1) << 3) + (lane & 7);
    const int b_koff = (bg & 1) << 3;
    const int ktr = ((lane >> 3) & 1)*8 + (lane & 7);
    const int ntr = (lane >> 4)*8;

    float acc[2][8][4];
    #pragma unroll
    for (int mt = 0; mt < 2; ++mt)
        #pragma unroll
        for (int nt = 0; nt < 8; ++nt)
            #pragma unroll
            for (int q = 0; q < 4; ++q) acc[mt][nt][q] = 0.f;

    auto issue1 = [&](int kc, int buf){
        const int kbase = kc*32;
        {
            const size_t go = ((size_t)b*N_IMG + (m0 + a_row))*KPAD + kbase + a_quad*8;
            const size_t gs = avalid ? go : (size_t)b*N_IMG*KPAD;
            cp16(sb + buf*5120u + aoff, Csh + gs, avalid);
            cp16(sb + 10240u + buf*5120u + aoff, Csl + gs, avalid);
        }
        #pragma unroll
        for (int p = 0; p < 4; ++p){
            int idx = tid + p*256;
            int kk = idx >> 5, nn = (idx & 31)*8;
            const bool bv = (kbase + kk) < N_IMG;
            const size_t go = ((size_t)b*N_IMG + kbase + kk)*M_TOK + nn;
            const size_t gs = bv ? go : (size_t)b*NM;
            const uint32_t so = (uint32_t)((kk*LDP + nn) * 2);
            cp16(sb + 20480u + buf*16896u + so, Gh + gs, bv);
            cp16(sb + 54272u + buf*16896u + so, Gl + gs, bv);
        }
        CP_COMMIT();
    };

    issue1(0, 0);
    for (int kc = 0; kc < 7; ++kc){
        if (kc < 6){ issue1(kc+1, (kc+1)&1); CP_WAIT1(); }
        else       { CP_WAIT0(); }
        __syncthreads();

        const int buf = kc & 1;
        const uint32_t baAh = sb + buf*5120u;
        const uint32_t baAl = sb + 10240u + buf*5120u;
        const uint32_t baBh = sb + 20480u + buf*16896u;
        const uint32_t baBl = sb + 54272u + buf*16896u;

        #pragma unroll
        for (int k16 = 0; k16 < 2; ++k16){
            unsigned ah[2][4], al[2][4], bh[4][4], bl[4][4];
            #pragma unroll
            for (int mt = 0; mt < 2; ++mt){
                uint32_t off = (uint32_t)(((wm*32 + mt*16 + arow_l)*LDT + k16*16 + ahalf*8) * 2);
                ldm_x4(ah[mt], baAh + off);
                ldm_x4(al[mt], baAl + off);
            }
            #pragma unroll
            for (int nt2 = 0; nt2 < 4; ++nt2){
                uint32_t off = (uint32_t)(((k16*16 + ktr)*LDP + wn*64 + nt2*16 + ntr) * 2);
                ldm_x4_t(bh[nt2], baBh + off);
                ldm_x4_t(bl[nt2], baBl + off);
            }
            #pragma unroll
            for (int mt = 0; mt < 2; ++mt)
                #pragma unroll
                for (int nt = 0; nt < 8; ++nt){
                    const int p2 = nt >> 1, s2 = (nt & 1) * 2;
                    mma_bf16(acc[mt][nt], ah[mt], bh[p2][s2], bh[p2][s2+1]);
                    mma_bf16(acc[mt][nt], ah[mt], bl[p2][s2], bl[p2][s2+1]);
                    mma_bf16(acc[mt][nt], al[mt], bh[p2][s2], bh[p2][s2+1]);
                }
        }
        __syncthreads();
    }

    auto issue2 = [&](int kc, int buf){
        #pragma unroll
        for (int p = 0; p < 4; ++p){
            int idx = tid + p*256;
            int row = idx >> 2, quad = idx & 3;
            const size_t go = ((size_t)b*M_TOK + row)*M_TOK + kc*32 + quad*8;
            const uint32_t so = (uint32_t)((row*LDT + quad*8) * 2);
            cp16(sb + buf*20480u + so, Cth + go, true);
            cp16(sb + 40960u + buf*20480u + so, Ctl + go, true);
        }
        CP_COMMIT();
    };
    issue2(0, 0);

    #pragma unroll
    for (int mt = 0; mt < 2; ++mt){
        #pragma unroll
        for (int nt = 0; nt < 8; ++nt){
            const int il = wm*32 + mt*16 + (lane >> 2);
            const int jb = wn*64 + nt*8 + (lane & 3)*2;
            #pragma unroll
            for (int rr = 0; rr < 2; ++rr){
                const int i = il + rr*8;
                #pragma unroll
                for (int cc = 0; cc < 2; ++cc){
                    const int j = jb + cc;
                    __nv_bfloat16 h, l;
                    split_bf16(acc[mt][nt][rr*2 + cc], h, l);
                    *reinterpret_cast<__nv_bfloat16*>((char*)dyn + 88064u + (i*LDP + j)*2) = h;
                    *reinterpret_cast<__nv_bfloat16*>((char*)dyn + 121856u + (i*LDP + j)*2) = l;
                }
            }
        }
    }
    issue2(1, 1);
    __syncthreads();

    #pragma unroll
    for (int mt = 0; mt < 2; ++mt)
        #pragma unroll
        for (int nt = 0; nt < 8; ++nt)
            #pragma unroll
            for (int q = 0; q < 4; ++q) acc[mt][nt][q] = 0.f;

    for (int kc = 0; kc < 8; ++kc){
        if (kc < 7){ issue2(kc+1, (kc+1)&1); CP_WAIT1(); }
        else       { CP_WAIT0(); }
        __syncthreads();

        const int buf = kc & 1;
        const uint32_t baBh = sb + buf*20480u;
        const uint32_t baBl = sb + 40960u + buf*20480u;

        #pragma unroll
        for (int k16 = 0; k16 < 2; ++k16){
            unsigned ah[2][4], al[2][4], bh[4][4], bl[4][4];
            #pragma unroll
            for (int mt = 0; mt < 2; ++mt){
                uint32_t off = (uint32_t)(((wm*32 + mt*16 + arow_l)*LDP + kc*32 + k16*16 + ahalf*8) * 2);
                ldm_x4(ah[mt], TMPH + off);
                ldm_x4(al[mt], TMPL + off);
            }
            #pragma unroll
            for (int nt2 = 0; nt2 < 4; ++nt2){
                uint32_t off = (uint32_t)(((wn*64 + nt2*16 + b_noff)*LDT + k16*16 + b_koff) * 2);
                ldm_x4(bh[nt2], baBh + off);
                ldm_x4(bl[nt2], baBl + off);
            }
            #pragma unroll
            for (int mt = 0; mt < 2; ++mt)
                #pragma unroll
                for (int nt = 0; nt < 8; ++nt){
                    const int p2 = nt >> 1, s2 = (nt & 1) * 2;
                    mma_bf16(acc[mt][nt], ah[mt], bh[p2][s2], bh[p2][s2+1]);
                    mma_bf16(acc[mt][nt], ah[mt], bl[p2][s2], bl[p2][s2+1]);
                    mma_bf16(acc[mt][nt], al[mt], bh[p2][s2], bh[p2][s2+1]);
                }
        }
        __syncthreads();
    }

    float dot = 0.f;
    #pragma unroll
    for (int mt = 0; mt < 2; ++mt){
        #pragma unroll
        for (int nt = 0; nt < 8; ++nt){
            const int ibase = m0 + wm*32 + mt*16 + (lane >> 2);
            const int jbase = wn*64 + nt*8 + (lane & 3)*2;
            #pragma unroll
            for (int rr = 0; rr < 2; ++rr){
                int i = ibase + rr*8;
                if (i >= N_IMG) continue;
                const size_t ro = ((size_t)b*N_IMG + i)*M_TOK;
                const float ra = rowadd[b*N_IMG + i];
                #pragma unroll
                for (int cc = 0; cc < 2; ++cc){
                    int j = jbase + cc;
                    float r = ra + coladd[b*M_TOK + j] - 2.0f*acc[mt][nt][rr*2 + cc];
                    Cout[ro + j] = r;
                    if (gamF) dot += r * gamF[ro + j];
                }
            }
        }
    }
    if (gamF){
        #pragma unroll
        for (int o = 16; o; o >>= 1) dot += __shfl_xor_sync(0xffffffffu, dot, o);
        if (lane == 0) atomicAdd(&dotOut[b], dot);
    }
}

// ============ GW GEMM 2 standalone (iter0) ============
#define GW2_DSM 61440

__global__ void __launch_bounds__(256,1)
gwmma2_kernel(const __nv_bfloat16* __restrict__ Ah, const __nv_bfloat16* __restrict__ Al,
              const __nv_bfloat16* __restrict__ Bh, const __nv_bfloat16* __restrict__ Bl,
              float* __restrict__ Cout,
              const float* __restrict__ rowadd, const float* __restrict__ coladd)
{
    extern __shared__ char dyn[];
    const uint32_t sb = smem_u32(dyn);

    const int tid  = threadIdx.x;
    const int lane = tid & 31;
    const int wid  = tid >> 5;
    const int wm   = wid >> 2;
    const int wn   = wid & 3;
    const int b    = blockIdx.z;
    const int m0   = blockIdx.y * 64;
    const int j0   = blockIdx.x * 128;

    const int a_row = tid >> 2, a_quad = tid & 3;
    const bool avalid = (m0 + a_row) < N_IMG;
    const uint32_t aoff = (uint32_t)((a_row*LDT + a_quad*8) * 2);

    const int arow_l = lane & 15, ahalf = lane >> 4;
    const int bg = lane >> 3;
    const int b_noff = ((bg >> 1) << 3) + (lane & 7);
    const int b_koff = (bg & 1) << 3;

    float acc[2][4][4];
    #pragma unroll
    for (int mt = 0; mt < 2; ++mt)
        #pragma unroll
        for (int nt = 0; nt < 4; ++nt)
            #pragma unroll
            for (int q = 0; q < 4; ++q) acc[mt][nt][q] = 0.f;

    auto issue_tile = [&](int kc, int buf){
        const uint32_t ah = sb + buf*5120u;
        const uint32_t al = sb + 10240u + buf*5120u;
        const uint32_t bh = sb + 20480u + buf*10240u;
        const uint32_t bl = sb + 40960u + buf*10240u;
        {
            const size_t go = ((size_t)b*N_IMG + (m0 + a_row))*M_TOK + kc*32 + a_quad*8;
            const size_t gs = avalid ? go : (size_t)b*NM;
            cp16(ah + aoff, Ah + gs, avalid);
            cp16(al + aoff, Al + gs, avalid);
        }
        #pragma unroll
        for (int p = 0; p < 2; ++p){
            int idx = tid + p*256;
            int row = idx >> 2, quad = idx & 3;
            const size_t go = ((size_t)b*M_TOK + j0 + row)*M_TOK + kc*32 + quad*8;
            const uint32_t so = (uint32_t)((row*LDT + quad*8) * 2);
            cp16(bh + so, Bh + go, true);
            cp16(bl + so, Bl + go, true);
        }
        CP_COMMIT();
    };

    issue_tile(0, 0);
    for (int kc = 0; kc < 8; ++kc){
        if (kc < 7){ issue_tile(kc+1, (kc+1)&1); CP_WAIT1(); }
        else       { CP_WAIT0(); }
        __syncthreads();

        const int buf = kc & 1;
        const uint32_t baAh = sb + buf*5120u;
        const uint32_t baAl = sb + 10240u + buf*5120u;
        const uint32_t baBh = sb + 20480u + buf*10240u;
        const uint32_t baBl = sb + 40960u + buf*10240u;

        #pragma unroll
        for (int k16 = 0; k16 < 2; ++k16){
            unsigned ah[2][4], al[2][4], bh[2][4], bl[2][4];
            #pragma unroll
            for (int mt = 0; mt < 2; ++mt){
                uint32_t off = (uint32_t)(((wm*32 + mt*16 + arow_l)*LDT + k16*16 + ahalf*8) * 2);
                ldm_x4(ah[mt], baAh + off);
                ldm_x4(al[mt], baAl + off);
            }
            #pragma unroll
            for (int nt2 = 0; nt2 < 2; ++nt2){
                uint32_t off = (uint32_t)(((wn*32 + nt2*16 + b_noff)*LDT + k16*16 + b_koff) * 2);
                ldm_x4(bh[nt2], baBh + off);
                ldm_x4(bl[nt2], baBl + off);
            }
            #pragma unroll
            for (int mt = 0; mt < 2; ++mt)
                #pragma unroll
                for (int nt = 0; nt < 4; ++nt){
                    const int p2 = nt >> 1, s2 = (nt & 1) * 2;
                    mma_bf16(acc[mt][nt], ah[mt], bh[p2][s2], bh[p2][s2+1]);
                    mma_bf16(acc[mt][nt], ah[mt], bl[p2][s2], bl[p2][s2+1]);
                    mma_bf16(acc[mt][nt], al[mt], bh[p2][s2], bh[p2][s2+1]);
                }
        }
        __syncthreads();
    }

    #pragma unroll
    for (int mt = 0; mt < 2; ++mt){
        #pragma unroll
        for (int nt = 0; nt < 4; ++nt){
            const int ibase = m0 + wm*32 + mt*16 + (lane >> 2);
            const int jbase = j0 + wn*32 + nt*8 + (lane & 3)*2;
            #pragma unroll
            for (int rr = 0; rr < 2; ++rr){
                int i = ibase + rr*8;
                if (i >= N_IMG) continue;
                const size_t ro = ((size_t)b*N_IMG + i)*M_TOK;
                const float ra = rowadd[b*N_IMG + i];
                #pragma unroll
                for (int cc = 0; cc < 2; ++cc){
                    int j = jbase + cc;
                    Cout[ro + j] = ra + coladd[b*M_TOK + j] - 2.0f*acc[mt][nt][rr*2 + cc];
                }
            }
        }
    }
}

// ---------------- merged fused Cs + Ct elementwise pass ----------------
__global__ void fusedC_kernel(float* __restrict__ Cs, float* __restrict__ Ct,
                              const int* __restrict__ irm, const int* __restrict__ tdm,
                              __nv_bfloat16* __restrict__ csh, __nv_bfloat16* __restrict__ csl,
                              __nv_bfloat16* __restrict__ cth, __nv_bfloat16* __restrict__ ctl,
                              float* __restrict__ crow, float* __restrict__ ccol,
                              __nv_bfloat16* __restrict__ tmph, __nv_bfloat16* __restrict__ tmpl)
{
    const int gb = blockIdx.x;
    const int t = threadIdx.x;

    if (gb < B_*N_IMG){
        const float mn = dec_mono(g_minmax[2]);
        const float mx = dec_mono(g_minmax[3]);
        const float thr = mn + 0.1f*(mx - mn);
        const int r = gb;

        float v = 0.f;
        if (t < N_IMG){
            size_t si = (size_t)r*N_IMG + t;
            v = Cs[si] - thr;
            v = v > 0.f ? v : 0.f;
            v *= (irm[si] == 1 ? 1.0f : 1e-5f);
            Cs[si] = v;
        }
        if (t < KPAD){
            __nv_bfloat16 h, l; split_bf16(v, h, l);
            csh[(size_t)r*KPAD + t] = h;
            csl[(size_t)r*KPAD + t] = l;
        }
        float ss = v*v, s1 = v;
        #pragma unroll
        for (int o = 16; o; o >>= 1){
            ss += __shfl_xor_sync(0xffffffffu, ss, o);
            s1 += __shfl_xor_sync(0xffffffffu, s1, o);
        }
        __shared__ float sq[8], sm[8];
        if ((t & 31) == 0){ sq[t>>5] = ss; sm[t>>5] = s1; }
        __syncthreads();
        __shared__ float s_val;
        if (t == 0){
            float a = 0.f, c = 0.f;
            for (int w = 0; w < 8; ++w){ a += sq[w]; c += sm[w]; }
            crow[r] = a / (float)N_IMG;
            s_val = c / (float)NM;
        }
        __syncthreads();
        __nv_bfloat16 h, l; split_bf16(s_val, h, l);
        tmph[(size_t)r*M_TOK + t] = h;
        tmpl[(size_t)r*M_TOK + t] = l;
    } else {
        const float mn = dec_mono(g_minmax[4]);
        const float mx = dec_mono(g_minmax[5]);
        const float thr = mn + 0.1f*(mx - mn);
        const int r = gb - B_*N_IMG;

        size_t si = (size_t)r*M_TOK + t;
        float v = Ct[si] - thr;
        v = v > 0.f ? v : 0.f;
        v *= (tdm[si] == 1 ? 1.0f : 1e-5f);
        Ct[si] = v;
        __nv_bfloat16 h, l; split_bf16(v, h, l);
        cth[si] = h;
        ctl[si] = l;

        float ss = v*v;
        #pragma unroll
        for (int o = 16; o; o >>= 1) ss += __shfl_xor_sync(0xffffffffu, ss, o);
        __shared__ float sq2[8];
        if ((t & 31) == 0) sq2[t>>5] = ss;
        __syncthreads();
        if (t == 0){
            float a = 0.f;
            for (int w = 0; w < 8; ++w) a += sq2[w];
            ccol[r] = a / (float)M_TOK;
        }
    }
}

// ---------------- IPOT: 4-CTA cluster; dual-job; smem-transpose row reduction ----------------
// Dynamic smem: s_q[196][65] floats (50960 B). pass1: 49 STS + 64-col sum, no shfl chains.
#define IPOT_DSM (196*65*4)

__global__ void __cluster_dims__(4,1,1) __launch_bounds__(256,1)
ipot_kernel(const float* __restrict__ Cw, const float* __restrict__ Cg, int nbW,
            float* __restrict__ ToutW, float* __restrict__ ToutG,
            __nv_bfloat16* __restrict__ Gh, __nv_bfloat16* __restrict__ Gl,
            float* __restrict__ dotW)
{
    extern __shared__ float s_q[];   // [196][65]
    cg::cluster_group cluster = cg::this_cluster();
    const int rank = blockIdx.x;
    const int by   = blockIdx.y;
    const bool wdJob = by < nbW;
    const int b    = wdJob ? by : (by - nbW);
    const int tid  = threadIdx.x;
    const int jl   = tid & 63;
    const int rq   = tid >> 6;
    const int lane = tid & 31;
    const int wid  = tid >> 5;
    const int jg   = rank*64 + jl;
    const float* C = (wdJob ? Cw : Cg) + (size_t)b * NM;

    float thr = 0.f;
    if (wdJob){
        const float mn = dec_mono(g_minmax[0]);
        const float mx = dec_mono(g_minmax[1]);
        thr = mn + 0.1f*(mx - mn);
    }
    float* ToutF = wdJob ? (ToutW ? ToutW + (size_t)b*NM : nullptr)
                         : (ToutG ? ToutG + (size_t)b*NM : nullptr);

    __shared__ float s_delta[196];
    __shared__ float s_rowpart[2][196];
    __shared__ float s_col[4][64];
    __shared__ float s_dred[8];
    __shared__ float s_dotpart;

    float E[49], T[49];
    #pragma unroll
    for (int k = 0; k < 49; ++k){
        float c = fmaxf(C[(rq + 4*k)*M_TOK + jg] - thr, 0.f);
        E[k] = expf(-2.0f * c);
        T[k] = 1.0f;
    }
    float sig = 1.0f/256.0f;
    __syncthreads();

    for (int it = 0; it < 20; ++it){
        const int buf = it & 1;
        // pass1: scatter q to smem [row][col], then column-sum per row
        #pragma unroll
        for (int k = 0; k < 49; ++k)
            s_q[(rq + 4*k)*65 + jl] = E[k]*T[k]*sig;
        __syncthreads();
        if (tid < 196){
            const float* row = s_q + tid*65;
            float a0 = 0.f, a1 = 0.f, a2 = 0.f, a3 = 0.f;
            #pragma unroll
            for (int c = 0; c < 64; c += 4){
                a0 += row[c];
                a1 += row[c+1];
                a2 += row[c+2];
                a3 += row[c+3];
            }
            s_rowpart[buf][tid] = (a0 + a1) + (a2 + a3);
        }
        cluster.sync();
        if (tid < 196){
            float s = 0.f;
            #pragma unroll
            for (int r = 0; r < 4; ++r)
                s += *(cluster.map_shared_rank(&s_rowpart[buf][0], r) + tid);
            s_delta[tid] = 1.0f / (196.0f * s);
        }
        __syncthreads();
        float cs = 0.f;
        #pragma unroll
        for (int k = 0; k < 49; ++k)
            cs += E[k]*T[k]*s_delta[rq + 4*k];
        s_col[rq][jl] = cs;
        __syncthreads();
        {
            float c = s_col[0][jl] + s_col[1][jl] + s_col[2][jl] + s_col[3][jl];
            sig = 1.0f / (256.0f * c);
        }
        #pragma unroll
        for (int k = 0; k < 49; ++k)
            T[k] = s_delta[rq + 4*k] * E[k] * T[k] * sig;
    }

    if (ToutF){
        #pragma unroll
        for (int k = 0; k < 49; ++k)
            ToutF[(size_t)(rq + 4*k)*M_TOK + jg] = T[k];
    }
    if (!wdJob){
        const size_t base = (size_t)b * NM;
        #pragma unroll
        for (int k = 0; k < 49; ++k){
            __nv_bfloat16 h, l; split_bf16(T[k], h, l);
            const size_t o = base + (size_t)(rq + 4*k)*M_TOK + jg;
            Gh[o] = h; Gl[o] = l;
        }
    }

    if (wdJob && dotW){
        float dot = 0.f;
        #pragma unroll
        for (int k = 0; k < 49; ++k)
            dot += fmaxf(C[(rq + 4*k)*M_TOK + jg] - thr, 0.f) * T[k];
        #pragma unroll
        for (int o = 16; o; o >>= 1) dot += __shfl_xor_sync(0xffffffffu, dot, o);
        if (lane == 0) s_dred[wid] = dot;
        __syncthreads();
        if (tid == 0){
            float t = 0.f;
            for (int w = 0; w < 8; ++w) t += s_dred[w];
            s_dotpart = t;
        }
        cluster.sync();
        if (rank == 0 && tid == 0){
            float t = 0.f;
            #pragma unroll
            for (int r = 0; r < 4; ++r)
                t += *cluster.map_shared_rank(&s_dotpart, r);
            dotW[b] = t;
        }
    }
    cluster.sync();
}

__global__ void final_kernel(float* __restrict__ outp){
    int t = threadIdx.x;
    float wd = g_dotwd[t];
    float gw = g_dotgw[t];
    #pragma unroll
    for (int o = 16; o; o >>= 1){
        wd += __shfl_xor_sync(0xffffffffu, wd, o);
        gw += __shfl_xor_sync(0xffffffffu, gw, o);
    }
    if (t == 0)
        outp[0] = 0.1f*(gw * (1.0f/B_)) - 0.1f*(wd * (1.0f/B_));
}

// ---------------- host launcher ----------------
extern "C" void kernel_launch(void* const* d_in, const int* in_sizes, int n_in,
                              void* d_out, int out_size)
{
    const float* img     = (const float*)d_in[0];
    const float* tok     = (const float*)d_in[1];
    const float* tokmask = (const float*)d_in[2];
    const int*   tdm     = (const int*)d_in[3];
    const int*   irm     = (const int*)d_in[4];
    float* out = (float*)d_out;                    // [1 | T_wd | T_gwd]
    float* outTwd  = out + 1;
    float* outTgwd = out + 1 + (size_t)B_*NM;

    __nv_bfloat16 *xh, *xl, *yh, *yl, *csh, *csl, *cth, *ctl, *gh, *gl, *th, *tl;
    float *Cxy, *Cs, *Ct, *Cg, *crow, *ccol, *dwd, *dgw;
    cudaGetSymbolAddress((void**)&xh,  g_xh);
    cudaGetSymbolAddress((void**)&xl,  g_xl);
    cudaGetSymbolAddress((void**)&yh,  g_yh);
    cudaGetSymbolAddress((void**)&yl,  g_yl);
    cudaGetSymbolAddress((void**)&csh, g_Csh);
    cudaGetSymbolAddress((void**)&csl, g_Csl);
    cudaGetSymbolAddress((void**)&cth, g_Cth);
    cudaGetSymbolAddress((void**)&ctl, g_Ctl);
    cudaGetSymbolAddress((void**)&gh,  g_gamh);
    cudaGetSymbolAddress((void**)&gl,  g_gaml);
    cudaGetSymbolAddress((void**)&th,  g_tmph);
    cudaGetSymbolAddress((void**)&tl,  g_tmpl);
    cudaGetSymbolAddress((void**)&Cxy, g_Cxy);
    cudaGetSymbolAddress((void**)&Cs,  g_Cs);
    cudaGetSymbolAddress((void**)&Ct,  g_Ct);
    cudaGetSymbolAddress((void**)&Cg,  g_Cg);
    cudaGetSymbolAddress((void**)&crow, g_cstrow);
    cudaGetSymbolAddress((void**)&ccol, g_cstcol);
    cudaGetSymbolAddress((void**)&dwd, g_dotwd);
    cudaGetSymbolAddress((void**)&dgw, g_dotgw);

    cudaFuncSetAttribute(cosmma_kernel,  cudaFuncAttributeMaxDynamicSharedMemorySize, COS_DSM);
    cudaFuncSetAttribute(gwfused_kernel, cudaFuncAttributeMaxDynamicSharedMemorySize, GWF_DSM);
    cudaFuncSetAttribute(gwmma2_kernel,  cudaFuncAttributeMaxDynamicSharedMemorySize, GW2_DSM);
    cudaFuncSetAttribute(ipot_kernel,    cudaFuncAttributeMaxDynamicSharedMemorySize, IPOT_DSM);

    init_kernel<<<1, 64>>>();
    normalize_kernel<<<B_*(N_IMG+M_TOK), 256>>>(img, tok, tokmask, xh, xl, yh, yl);

    cosmma_kernel<<<dim3(24,1,B_), 256, COS_DSM>>>(xh, xl, yh, yl, Cxy, Cs, Ct);

    fusedC_kernel<<<B_*(N_IMG+M_TOK), 256>>>(Cs, Ct, irm, tdm, csh, csl, cth, ctl,
                                             crow, ccol, th, tl);

    // iter0: tmp already = rowsum(Cs)/NM (from fusedC)
    gwmma2_kernel<<<dim3(2,4,B_), 256, GW2_DSM>>>(th, tl, cth, ctl, Cg, crow, ccol);

    // merged: WD ipot on Cxy (inline thresh) + gamma ipot on Cg
    ipot_kernel<<<dim3(4, 2*B_), 256, IPOT_DSM>>>(Cxy, Cg, B_, outTwd, nullptr, gh, gl, dwd);

    for (int it = 1; it < 6; ++it){
        const bool last = (it == 5);
        gwfused_kernel<<<dim3(4,1,B_), 256, GWF_DSM>>>(csh, csl, gh, gl, cth, ctl,
                                                       Cg, crow, ccol,
                                                       last ? outTgwd : nullptr, dgw);
        if (it < 5)
            ipot_kernel<<<dim3(4,B_), 256, IPOT_DSM>>>(nullptr, Cg, 0, nullptr,
                                             (it == 4) ? outTgwd : nullptr, gh, gl, nullptr);
    }

    final_kernel<<<1, 32>>>(out);
}

// round 14
// speedup vs baseline: 1.2066x; 1.0157x over previous
#include <cuda_runtime.h>
#include <cuda_bf16.h>
#include <cooperative_groups.h>
#include <math.h>

namespace cg = cooperative_groups;

#define B_    32
#define N_IMG 196
#define M_TOK 256
#define D_    1024
#define NM    (N_IMG*M_TOK)
#define KPAD  224

// ---------------- device scratch (allocation-free) ----------------
__device__ __nv_bfloat16 g_xh[B_*N_IMG*D_];
__device__ __nv_bfloat16 g_xl[B_*N_IMG*D_];
__device__ __nv_bfloat16 g_yh[B_*M_TOK*D_];
__device__ __nv_bfloat16 g_yl[B_*M_TOK*D_];
__device__ float g_Cxy[B_*NM];
__device__ float g_Cs [B_*N_IMG*N_IMG];
__device__ float g_Ct [B_*M_TOK*M_TOK];
__device__ __nv_bfloat16 g_Csh[B_*N_IMG*KPAD];
__device__ __nv_bfloat16 g_Csl[B_*N_IMG*KPAD];
__device__ __nv_bfloat16 g_Cth[B_*M_TOK*M_TOK];
__device__ __nv_bfloat16 g_Ctl[B_*M_TOK*M_TOK];
__device__ __nv_bfloat16 g_gamh[B_*NM];
__device__ __nv_bfloat16 g_gaml[B_*NM];
__device__ __nv_bfloat16 g_tmph[B_*NM];
__device__ __nv_bfloat16 g_tmpl[B_*NM];
__device__ float g_Cg[B_*NM];
__device__ float g_cstrow[B_*N_IMG];
__device__ float g_cstcol[B_*M_TOK];
__device__ unsigned g_minmax[6];
__device__ float g_dotwd[B_];
__device__ float g_dotgw[B_];

__device__ __forceinline__ unsigned enc_mono(float f){
    unsigned u = __float_as_uint(f);
    return (u & 0x80000000u) ? ~u : (u | 0x80000000u);
}
__device__ __forceinline__ float dec_mono(unsigned e){
    unsigned u = (e & 0x80000000u) ? (e ^ 0x80000000u) : ~e;
    return __uint_as_float(u);
}
__device__ __forceinline__ uint32_t smem_u32(const void* p){
    uint32_t a;
    asm("{ .reg .u64 t; cvta.to.shared.u64 t, %1; cvt.u32.u64 %0, t; }" : "=r"(a) : "l"(p));
    return a;
}
__device__ __forceinline__ void ldm_x4(unsigned* r, uint32_t addr){
    asm volatile("ldmatrix.sync.aligned.m8n8.x4.shared.b16 {%0,%1,%2,%3}, [%4];"
        : "=r"(r[0]), "=r"(r[1]), "=r"(r[2]), "=r"(r[3]) : "r"(addr));
}
__device__ __forceinline__ void ldm_x4_t(unsigned* r, uint32_t addr){
    asm volatile("ldmatrix.sync.aligned.m8n8.x4.trans.shared.b16 {%0,%1,%2,%3}, [%4];"
        : "=r"(r[0]), "=r"(r[1]), "=r"(r[2]), "=r"(r[3]) : "r"(addr));
}
__device__ __forceinline__ void mma_bf16(float* d, const unsigned* a, unsigned b0, unsigned b1){
    asm volatile("mma.sync.aligned.m16n8k16.row.col.f32.bf16.bf16.f32 "
        "{%0,%1,%2,%3}, {%4,%5,%6,%7}, {%8,%9}, {%0,%1,%2,%3};"
        : "+f"(d[0]), "+f"(d[1]), "+f"(d[2]), "+f"(d[3])
        : "r"(a[0]), "r"(a[1]), "r"(a[2]), "r"(a[3]), "r"(b0), "r"(b1));
}
__device__ __forceinline__ void split_bf16(float v, __nv_bfloat16& h, __nv_bfloat16& l){
    h = __float2bfloat16(v);
    l = __float2bfloat16(v - __bfloat162float(h));
}
__device__ __forceinline__ void cp16(uint32_t d, const void* s, bool v){
    int sz = v ? 16 : 0;
    asm volatile("cp.async.ca.shared.global [%0], [%1], 16, %2;" :: "r"(d), "l"(s), "r"(sz));
}
#define CP_COMMIT() asm volatile("cp.async.commit_group;" ::: "memory")
#define CP_WAIT1()  asm volatile("cp.async.wait_group 1;" ::: "memory")
#define CP_WAIT0()  asm volatile("cp.async.wait_group 0;" ::: "memory")

// ---------------- single-pass normalize (row in registers) + inlined init ----------------
__global__ void normalize_kernel(const float* __restrict__ img,
                                 const float* __restrict__ tok,
                                 const float* __restrict__ tokmask,
                                 __nv_bfloat16* __restrict__ xh, __nv_bfloat16* __restrict__ xl,
                                 __nv_bfloat16* __restrict__ yh, __nv_bfloat16* __restrict__ yl)
{
    const int gb = blockIdx.x;
    const int t  = threadIdx.x;

    if (gb == 0 && t < 64){
        if (t < 3){ g_minmax[2*t] = 0xFFFFFFFFu; g_minmax[2*t+1] = 0u; }
        if (t < B_) g_dotgw[t] = 0.f;
    }

    const bool isTok = gb >= B_*N_IMG;
    const int bp = isTok ? (gb - B_*N_IMG) : gb;
    const float* v = (isTok ? tok : img) + (size_t)bp * D_;
    float mk = 1.0f;
    if (isTok) mk = tokmask[bp];

    // one float4 per thread (256 * 4 = 1024 = D_)
    const float4 v4 = *reinterpret_cast<const float4*>(v + t*4);
    float t0 = v4.x * mk, t1 = v4.y * mk, t2 = v4.z * mk, t3 = v4.w * mk;

    float ss = t0*t0 + t1*t1 + t2*t2 + t3*t3;
    #pragma unroll
    for (int o = 16; o; o >>= 1) ss += __shfl_xor_sync(0xffffffffu, ss, o);
    __shared__ float sred[8];
    if ((t & 31) == 0) sred[t >> 5] = ss;
    __syncthreads();
    __shared__ float s_inv;
    if (t == 0){
        float a = 0.f;
        #pragma unroll
        for (int w = 0; w < 8; ++w) a += sred[w];
        s_inv = 1.0f / (sqrtf(a) + 1e-12f);
    }
    __syncthreads();
    const float scale = s_inv;

    __nv_bfloat16 h[4], l[4];
    split_bf16(t0*scale, h[0], l[0]);
    split_bf16(t1*scale, h[1], l[1]);
    split_bf16(t2*scale, h[2], l[2]);
    split_bf16(t3*scale, h[3], l[3]);

    __nv_bfloat16* oh = (isTok ? yh : xh) + (size_t)bp * D_ + t*4;
    __nv_bfloat16* ol = (isTok ? yl : xl) + (size_t)bp * D_ + t*4;
    *reinterpret_cast<uint2*>(oh) = *reinterpret_cast<const uint2*>(h);
    *reinterpret_cast<uint2*>(ol) = *reinterpret_cast<const uint2*>(l);
}

// ============ merged cosine GEMMs: CTA 64x128, occ 2, 3-stage ============
#define LDT 40
#define COS_DSM (3*30720)

__global__ void __launch_bounds__(256,2)
cosmma_kernel(const __nv_bfloat16* __restrict__ xh, const __nv_bfloat16* __restrict__ xl,
              const __nv_bfloat16* __restrict__ yh, const __nv_bfloat16* __restrict__ yl,
              float* __restrict__ Cxy, float* __restrict__ Cs, float* __restrict__ Ct)
{
    extern __shared__ char dyn[];
    const uint32_t sb = smem_u32(dyn);

    const int tile = blockIdx.x;
    const int which = tile >> 3;
    const int sub   = tile & 7;
    const int b     = blockIdx.z;
    const int m0    = (sub >> 1) * 64;
    const int j0    = (sub & 1) * 128;

    const __nv_bfloat16* Ah = (which == 2) ? yh : xh;
    const __nv_bfloat16* Al = (which == 2) ? yl : xl;
    const __nv_bfloat16* Bh = (which == 1) ? xh : yh;
    const __nv_bfloat16* Bl = (which == 1) ? xl : yl;
    const int Mz = (which == 2) ? M_TOK : N_IMG;
    const int Nz = (which == 1) ? N_IMG : M_TOK;
    float* Cout = (which == 0) ? Cxy : ((which == 1) ? Cs : Ct);

    const int tid  = threadIdx.x;
    const int lane = tid & 31;
    const int wid  = tid >> 5;
    const int wm   = wid >> 2;
    const int wn   = wid & 3;

    const size_t abase = (size_t)b * Mz * D_;
    const size_t bbase = (size_t)b * Nz * D_;

    const int a_row = tid >> 2, a_quad = tid & 3;
    const bool avalid = (m0 + a_row) < Mz;
    const uint32_t aoff = (uint32_t)((a_row*LDT + a_quad*8) * 2);

    const int arow_l = lane & 15, ahalf = lane >> 4;
    const int bg = lane >> 3;
    const int b_noff = ((bg >> 1) << 3) + (lane & 7);
    const int b_koff = (bg & 1) << 3;

    float acc[2][4][4];
    #pragma unroll
    for (int mt = 0; mt < 2; ++mt)
        #pragma unroll
        for (int nt = 0; nt < 4; ++nt)
            #pragma unroll
            for (int q = 0; q < 4; ++q) acc[mt][nt][q] = 0.f;

    auto issue_tile = [&](int kc, int buf){
        const uint32_t base = sb + (uint32_t)buf*30720u;
        {
            const size_t go = abase + (size_t)(m0 + a_row)*D_ + kc*32 + a_quad*8;
            const size_t gs = avalid ? go : abase;
            cp16(base + aoff, Ah + gs, avalid);
            cp16(base + 5120u + aoff, Al + gs, avalid);
        }
        #pragma unroll
        for (int p = 0; p < 2; ++p){
            int idx = tid + p*256;
            int row = idx >> 2, quad = idx & 3;
            const bool bv = (j0 + row) < Nz;
            const size_t go = bbase + (size_t)(j0 + row)*D_ + kc*32 + quad*8;
            const size_t gs = bv ? go : bbase;
            const uint32_t so = (uint32_t)((row*LDT + quad*8) * 2);
            cp16(base + 10240u + so, Bh + gs, bv);
            cp16(base + 20480u + so, Bl + gs, bv);
        }
        CP_COMMIT();
    };

    issue_tile(0, 0);
    issue_tile(1, 1);
    for (int kc = 0; kc < 32; ++kc){
        if (kc == 31){ CP_WAIT0(); } else { CP_WAIT1(); }
        __syncthreads();
        if (kc + 2 < 32) issue_tile(kc + 2, (kc + 2) % 3);

        const uint32_t base = sb + (uint32_t)(kc % 3)*30720u;
        const uint32_t baAh = base;
        const uint32_t baAl = base + 5120u;
        const uint32_t baBh = base + 10240u;
        const uint32_t baBl = base + 20480u;

        #pragma unroll
        for (int k16 = 0; k16 < 2; ++k16){
            unsigned ah[2][4], al[2][4], bh[2][4], bl[2][4];
            #pragma unroll
            for (int mt = 0; mt < 2; ++mt){
                uint32_t off = (uint32_t)(((wm*32 + mt*16 + arow_l)*LDT + k16*16 + ahalf*8) * 2);
                ldm_x4(ah[mt], baAh + off);
                ldm_x4(al[mt], baAl + off);
            }
            #pragma unroll
            for (int nt2 = 0; nt2 < 2; ++nt2){
                uint32_t off = (uint32_t)(((wn*32 + nt2*16 + b_noff)*LDT + k16*16 + b_koff) * 2);
                ldm_x4(bh[nt2], baBh + off);
                ldm_x4(bl[nt2], baBl + off);
            }
            #pragma unroll
            for (int mt = 0; mt < 2; ++mt)
                #pragma unroll
                for (int nt = 0; nt < 4; ++nt){
                    const int p2 = nt >> 1, s2 = (nt & 1) * 2;
                    mma_bf16(acc[mt][nt], ah[mt], bh[p2][s2], bh[p2][s2+1]);
                    mma_bf16(acc[mt][nt], ah[mt], bl[p2][s2], bl[p2][s2+1]);
                    mma_bf16(acc[mt][nt], al[mt], bh[p2][s2], bh[p2][s2+1]);
                }
        }
    }

    float lmin =  3.402823466e+38f;
    float lmax = -3.402823466e+38f;
    #pragma unroll
    for (int mt = 0; mt < 2; ++mt){
        #pragma unroll
        for (int nt = 0; nt < 4; ++nt){
            const int ibase = m0 + wm*32 + mt*16 + (lane >> 2);
            const int jbase = j0 + wn*32 + nt*8 + (lane & 3)*2;
            #pragma unroll
            for (int rr = 0; rr < 2; ++rr){
                int i = ibase + rr*8;
                if (i >= Mz) continue;
                float* crow = Cout + ((size_t)b*Mz + i)*Nz;
                #pragma unroll
                for (int cc = 0; cc < 2; ++cc){
                    int j = jbase + cc;
                    if (j >= Nz) continue;
                    float v = 1.0f - acc[mt][nt][rr*2 + cc];
                    crow[j] = v;
                    lmin = fminf(lmin, v);
                    lmax = fmaxf(lmax, v);
                }
            }
        }
    }
    #pragma unroll
    for (int o = 16; o; o >>= 1){
        lmin = fminf(lmin, __shfl_xor_sync(0xffffffffu, lmin, o));
        lmax = fmaxf(lmax, __shfl_xor_sync(0xffffffffu, lmax, o));
    }
    if (lane == 0){
        atomicMin(&g_minmax[2*which],   enc_mono(lmin));
        atomicMax(&g_minmax[2*which+1], enc_mono(lmax));
    }
}

// ============ FUSED GW chain ============
#define LDP 264
#define GWF_DSM 155648

__global__ void __launch_bounds__(256,1)
gwfused_kernel(const __nv_bfloat16* __restrict__ Csh, const __nv_bfloat16* __restrict__ Csl,
               const __nv_bfloat16* __restrict__ Gh,  const __nv_bfloat16* __restrict__ Gl,
               const __nv_bfloat16* __restrict__ Cth, const __nv_bfloat16* __restrict__ Ctl,
               float* __restrict__ Cout,
               const float* __restrict__ rowadd, const float* __restrict__ coladd,
               const float* __restrict__ gamF, float* __restrict__ dotOut)
{
    extern __shared__ char dyn[];
    const uint32_t sb = smem_u32(dyn);
    const uint32_t TMPH = sb + 88064u;
    const uint32_t TMPL = sb + 121856u;

    const int tid  = threadIdx.x;
    const int lane = tid & 31;
    const int wid  = tid >> 5;
    const int wm   = wid >> 2;
    const int wn   = wid & 3;
    const int b    = blockIdx.z;
    const int m0   = blockIdx.x * 64;

    const int a_row = tid >> 2, a_quad = tid & 3;
    const bool avalid = (m0 + a_row) < N_IMG;
    const uint32_t aoff = (uint32_t)((a_row*LDT + a_quad*8) * 2);

    const int arow_l = lane & 15, ahalf = lane >> 4;
    const int bg = lane >> 3;
    const int b_noff = ((bg >> 1) << 3) + (lane & 7);
    const int b_koff = (bg & 1) << 3;
    const int ktr = ((lane >> 3) & 1)*8 + (lane & 7);
    const int ntr = (lane >> 4)*8;

    float acc[2][8][4];
    #pragma unroll
    for (int mt = 0; mt < 2; ++mt)
        #pragma unroll
        for (int nt = 0; nt < 8; ++nt)
            #pragma unroll
            for (int q = 0; q < 4; ++q) acc[mt][nt][q] = 0.f;

    auto issue1 = [&](int kc, int buf){
        const int kbase = kc*32;
        {
            const size_t go = ((size_t)b*N_IMG + (m0 + a_row))*KPAD + kbase + a_quad*8;
            const size_t gs = avalid ? go : (size_t)b*N_IMG*KPAD;
            cp16(sb + buf*5120u + aoff, Csh + gs, avalid);
            cp16(sb + 10240u + buf*5120u + aoff, Csl + gs, avalid);
        }
        #pragma unroll
        for (int p = 0; p < 4; ++p){
            int idx = tid + p*256;
            int kk = idx >> 5, nn = (idx & 31)*8;
            const bool bv = (kbase + kk) < N_IMG;
            const size_t go = ((size_t)b*N_IMG + kbase + kk)*M_TOK + nn;
            const size_t gs = bv ? go : (size_t)b*NM;
            const uint32_t so = (uint32_t)((kk*LDP + nn) * 2);
            cp16(sb + 20480u + buf*16896u + so, Gh + gs, bv);
            cp16(sb + 54272u + buf*16896u + so, Gl + gs, bv);
        }
        CP_COMMIT();
    };

    issue1(0, 0);
    for (int kc = 0; kc < 7; ++kc){
        if (kc < 6){ issue1(kc+1, (kc+1)&1); CP_WAIT1(); }
        else       { CP_WAIT0(); }
        __syncthreads();

        const int buf = kc & 1;
        const uint32_t baAh = sb + buf*5120u;
        const uint32_t baAl = sb + 10240u + buf*5120u;
        const uint32_t baBh = sb + 20480u + buf*16896u;
        const uint32_t baBl = sb + 54272u + buf*16896u;

        #pragma unroll
        for (int k16 = 0; k16 < 2; ++k16){
            unsigned ah[2][4], al[2][4], bh[4][4], bl[4][4];
            #pragma unroll
            for (int mt = 0; mt < 2; ++mt){
                uint32_t off = (uint32_t)(((wm*32 + mt*16 + arow_l)*LDT + k16*16 + ahalf*8) * 2);
                ldm_x4(ah[mt], baAh + off);
                ldm_x4(al[mt], baAl + off);
            }
            #pragma unroll
            for (int nt2 = 0; nt2 < 4; ++nt2){
                uint32_t off = (uint32_t)(((k16*16 + ktr)*LDP + wn*64 + nt2*16 + ntr) * 2);
                ldm_x4_t(bh[nt2], baBh + off);
                ldm_x4_t(bl[nt2], baBl + off);
            }
            #pragma unroll
            for (int mt = 0; mt < 2; ++mt)
                #pragma unroll
                for (int nt = 0; nt < 8; ++nt){
                    const int p2 = nt >> 1, s2 = (nt & 1) * 2;
                    mma_bf16(acc[mt][nt], ah[mt], bh[p2][s2], bh[p2][s2+1]);
                    mma_bf16(acc[mt][nt], ah[mt], bl[p2][s2], bl[p2][s2+1]);
                    mma_bf16(acc[mt][nt], al[mt], bh[p2][s2], bh[p2][s2+1]);
                }
        }
        __syncthreads();
    }

    auto issue2 = [&](int kc, int buf){
        #pragma unroll
        for (int p = 0; p < 4; ++p){
            int idx = tid + p*256;
            int row = idx >> 2, quad = idx & 3;
            const size_t go = ((size_t)b*M_TOK + row)*M_TOK + kc*32 + quad*8;
            const uint32_t so = (uint32_t)((row*LDT + quad*8) * 2);
            cp16(sb + buf*20480u + so, Cth + go, true);
            cp16(sb + 40960u + buf*20480u + so, Ctl + go, true);
        }
        CP_COMMIT();
    };
    issue2(0, 0);

    #pragma unroll
    for (int mt = 0; mt < 2; ++mt){
        #pragma unroll
        for (int nt = 0; nt < 8; ++nt){
            const int il = wm*32 + mt*16 + (lane >> 2);
            const int jb = wn*64 + nt*8 + (lane & 3)*2;
            #pragma unroll
            for (int rr = 0; rr < 2; ++rr){
                const int i = il + rr*8;
                #pragma unroll
                for (int cc = 0; cc < 2; ++cc){
                    const int j = jb + cc;
                    __nv_bfloat16 h, l;
                    split_bf16(acc[mt][nt][rr*2 + cc], h, l);
                    *reinterpret_cast<__nv_bfloat16*>((char*)dyn + 88064u + (i*LDP + j)*2) = h;
                    *reinterpret_cast<__nv_bfloat16*>((char*)dyn + 121856u + (i*LDP + j)*2) = l;
                }
            }
        }
    }
    issue2(1, 1);
    __syncthreads();

    #pragma unroll
    for (int mt = 0; mt < 2; ++mt)
        #pragma unroll
        for (int nt = 0; nt < 8; ++nt)
            #pragma unroll
            for (int q = 0; q < 4; ++q) acc[mt][nt][q] = 0.f;

    for (int kc = 0; kc < 8; ++kc){
        if (kc < 7){ issue2(kc+1, (kc+1)&1); CP_WAIT1(); }
        else       { CP_WAIT0(); }
        __syncthreads();

        const int buf = kc & 1;
        const uint32_t baBh = sb + buf*20480u;
        const uint32_t baBl = sb + 40960u + buf*20480u;

        #pragma unroll
        for (int k16 = 0; k16 < 2; ++k16){
            unsigned ah[2][4], al[2][4], bh[4][4], bl[4][4];
            #pragma unroll
            for (int mt = 0; mt < 2; ++mt){
                uint32_t off = (uint32_t)(((wm*32 + mt*16 + arow_l)*LDP + kc*32 + k16*16 + ahalf*8) * 2);
                ldm_x4(ah[mt], TMPH + off);
                ldm_x4(al[mt], TMPL + off);
            }
            #pragma unroll
            for (int nt2 = 0; nt2 < 4; ++nt2){
                uint32_t off = (uint32_t)(((wn*64 + nt2*16 + b_noff)*LDT + k16*16 + b_koff) * 2);
                ldm_x4(bh[nt2], baBh + off);
                ldm_x4(bl[nt2], baBl + off);
            }
            #pragma unroll
            for (int mt = 0; mt < 2; ++mt)
                #pragma unroll
                for (int nt = 0; nt < 8; ++nt){
                    const int p2 = nt >> 1, s2 = (nt & 1) * 2;
                    mma_bf16(acc[mt][nt], ah[mt], bh[p2][s2], bh[p2][s2+1]);
                    mma_bf16(acc[mt][nt], ah[mt], bl[p2][s2], bl[p2][s2+1]);
                    mma_bf16(acc[mt][nt], al[mt], bh[p2][s2], bh[p2][s2+1]);
                }
        }
        __syncthreads();
    }

    float dot = 0.f;
    #pragma unroll
    for (int mt = 0; mt < 2; ++mt){
        #pragma unroll
        for (int nt = 0; nt < 8; ++nt){
            const int ibase = m0 + wm*32 + mt*16 + (lane >> 2);
            const int jbase = wn*64 + nt*8 + (lane & 3)*2;
            #pragma unroll
            for (int rr = 0; rr < 2; ++rr){
                int i = ibase + rr*8;
                if (i >= N_IMG) continue;
                const size_t ro = ((size_t)b*N_IMG + i)*M_TOK;
                const float ra = rowadd[b*N_IMG + i];
                #pragma unroll
                for (int cc = 0; cc < 2; ++cc){
                    int j = jbase + cc;
                    float r = ra + coladd[b*M_TOK + j] - 2.0f*acc[mt][nt][rr*2 + cc];
                    Cout[ro + j] = r;
                    if (gamF) dot += r * gamF[ro + j];
                }
            }
        }
    }
    if (gamF){
        #pragma unroll
        for (int o = 16; o; o >>= 1) dot += __shfl_xor_sync(0xffffffffu, dot, o);
        if (lane == 0) atomicAdd(&dotOut[b], dot);
    }
}

// ============ GW GEMM 2 standalone (iter0) ============
#define GW2_DSM 61440

__global__ void __launch_bounds__(256,1)
gwmma2_kernel(const __nv_bfloat16* __restrict__ Ah, const __nv_bfloat16* __restrict__ Al,
              const __nv_bfloat16* __restrict__ Bh, const __nv_bfloat16* __restrict__ Bl,
              float* __restrict__ Cout,
              const float* __restrict__ rowadd, const float* __restrict__ coladd)
{
    extern __shared__ char dyn[];
    const uint32_t sb = smem_u32(dyn);

    const int tid  = threadIdx.x;
    const int lane = tid & 31;
    const int wid  = tid >> 5;
    const int wm   = wid >> 2;
    const int wn   = wid & 3;
    const int b    = blockIdx.z;
    const int m0   = blockIdx.y * 64;
    const int j0   = blockIdx.x * 128;

    const int a_row = tid >> 2, a_quad = tid & 3;
    const bool avalid = (m0 + a_row) < N_IMG;
    const uint32_t aoff = (uint32_t)((a_row*LDT + a_quad*8) * 2);

    const int arow_l = lane & 15, ahalf = lane >> 4;
    const int bg = lane >> 3;
    const int b_noff = ((bg >> 1) << 3) + (lane & 7);
    const int b_koff = (bg & 1) << 3;

    float acc[2][4][4];
    #pragma unroll
    for (int mt = 0; mt < 2; ++mt)
        #pragma unroll
        for (int nt = 0; nt < 4; ++nt)
            #pragma unroll
            for (int q = 0; q < 4; ++q) acc[mt][nt][q] = 0.f;

    auto issue_tile = [&](int kc, int buf){
        const uint32_t ah = sb + buf*5120u;
        const uint32_t al = sb + 10240u + buf*5120u;
        const uint32_t bh = sb + 20480u + buf*10240u;
        const uint32_t bl = sb + 40960u + buf*10240u;
        {
            const size_t go = ((size_t)b*N_IMG + (m0 + a_row))*M_TOK + kc*32 + a_quad*8;
            const size_t gs = avalid ? go : (size_t)b*NM;
            cp16(ah + aoff, Ah + gs, avalid);
            cp16(al + aoff, Al + gs, avalid);
        }
        #pragma unroll
        for (int p = 0; p < 2; ++p){
            int idx = tid + p*256;
            int row = idx >> 2, quad = idx & 3;
            const size_t go = ((size_t)b*M_TOK + j0 + row)*M_TOK + kc*32 + quad*8;
            const uint32_t so = (uint32_t)((row*LDT + quad*8) * 2);
            cp16(bh + so, Bh + go, true);
            cp16(bl + so, Bl + go, true);
        }
        CP_COMMIT();
    };

    issue_tile(0, 0);
    for (int kc = 0; kc < 8; ++kc){
        if (kc < 7){ issue_tile(kc+1, (kc+1)&1); CP_WAIT1(); }
        else       { CP_WAIT0(); }
        __syncthreads();

        const int buf = kc & 1;
        const uint32_t baAh = sb + buf*5120u;
        const uint32_t baAl = sb + 10240u + buf*5120u;
        const uint32_t baBh = sb + 20480u + buf*10240u;
        const uint32_t baBl = sb + 40960u + buf*10240u;

        #pragma unroll
        for (int k16 = 0; k16 < 2; ++k16){
            unsigned ah[2][4], al[2][4], bh[2][4], bl[2][4];
            #pragma unroll
            for (int mt = 0; mt < 2; ++mt){
                uint32_t off = (uint32_t)(((wm*32 + mt*16 + arow_l)*LDT + k16*16 + ahalf*8) * 2);
                ldm_x4(ah[mt], baAh + off);
                ldm_x4(al[mt], baAl + off);
            }
            #pragma unroll
            for (int nt2 = 0; nt2 < 2; ++nt2){
                uint32_t off = (uint32_t)(((wn*32 + nt2*16 + b_noff)*LDT + k16*16 + b_koff) * 2);
                ldm_x4(bh[nt2], baBh + off);
                ldm_x4(bl[nt2], baBl + off);
            }
            #pragma unroll
            for (int mt = 0; mt < 2; ++mt)
                #pragma unroll
                for (int nt = 0; nt < 4; ++nt){
                    const int p2 = nt >> 1, s2 = (nt & 1) * 2;
                    mma_bf16(acc[mt][nt], ah[mt], bh[p2][s2], bh[p2][s2+1]);
                    mma_bf16(acc[mt][nt], ah[mt], bl[p2][s2], bl[p2][s2+1]);
                    mma_bf16(acc[mt][nt], al[mt], bh[p2][s2], bh[p2][s2+1]);
                }
        }
        __syncthreads();
    }

    #pragma unroll
    for (int mt = 0; mt < 2; ++mt){
        #pragma unroll
        for (int nt = 0; nt < 4; ++nt){
            const int ibase = m0 + wm*32 + mt*16 + (lane >> 2);
            const int jbase = j0 + wn*32 + nt*8 + (lane & 3)*2;
            #pragma unroll
            for (int rr = 0; rr < 2; ++rr){
                int i = ibase + rr*8;
                if (i >= N_IMG) continue;
                const size_t ro = ((size_t)b*N_IMG + i)*M_TOK;
                const float ra = rowadd[b*N_IMG + i];
                #pragma unroll
                for (int cc = 0; cc < 2; ++cc){
                    int j = jbase + cc;
                    Cout[ro + j] = ra + coladd[b*M_TOK + j] - 2.0f*acc[mt][nt][rr*2 + cc];
                }
            }
        }
    }
}

// ---------------- merged fused Cs + Ct elementwise pass ----------------
__global__ void fusedC_kernel(float* __restrict__ Cs, float* __restrict__ Ct,
                              const int* __restrict__ irm, const int* __restrict__ tdm,
                              __nv_bfloat16* __restrict__ csh, __nv_bfloat16* __restrict__ csl,
                              __nv_bfloat16* __restrict__ cth, __nv_bfloat16* __restrict__ ctl,
                              float* __restrict__ crow, float* __restrict__ ccol,
                              __nv_bfloat16* __restrict__ tmph, __nv_bfloat16* __restrict__ tmpl)
{
    const int gb = blockIdx.x;
    const int t = threadIdx.x;

    if (gb < B_*N_IMG){
        const float mn = dec_mono(g_minmax[2]);
        const float mx = dec_mono(g_minmax[3]);
        const float thr = mn + 0.1f*(mx - mn);
        const int r = gb;

        float v = 0.f;
        if (t < N_IMG){
            size_t si = (size_t)r*N_IMG + t;
            v = Cs[si] - thr;
            v = v > 0.f ? v : 0.f;
            v *= (irm[si] == 1 ? 1.0f : 1e-5f);
            Cs[si] = v;
        }
        if (t < KPAD){
            __nv_bfloat16 h, l; split_bf16(v, h, l);
            csh[(size_t)r*KPAD + t] = h;
            csl[(size_t)r*KPAD + t] = l;
        }
        float ss = v*v, s1 = v;
        #pragma unroll
        for (int o = 16; o; o >>= 1){
            ss += __shfl_xor_sync(0xffffffffu, ss, o);
            s1 += __shfl_xor_sync(0xffffffffu, s1, o);
        }
        __shared__ float sq[8], sm[8];
        if ((t & 31) == 0){ sq[t>>5] = ss; sm[t>>5] = s1; }
        __syncthreads();
        __shared__ float s_val;
        if (t == 0){
            float a = 0.f, c = 0.f;
            for (int w = 0; w < 8; ++w){ a += sq[w]; c += sm[w]; }
            crow[r] = a / (float)N_IMG;
            s_val = c / (float)NM;
        }
        __syncthreads();
        __nv_bfloat16 h, l; split_bf16(s_val, h, l);
        tmph[(size_t)r*M_TOK + t] = h;
        tmpl[(size_t)r*M_TOK + t] = l;
    } else {
        const float mn = dec_mono(g_minmax[4]);
        const float mx = dec_mono(g_minmax[5]);
        const float thr = mn + 0.1f*(mx - mn);
        const int r = gb - B_*N_IMG;

        size_t si = (size_t)r*M_TOK + t;
        float v = Ct[si] - thr;
        v = v > 0.f ? v : 0.f;
        v *= (tdm[si] == 1 ? 1.0f : 1e-5f);
        Ct[si] = v;
        __nv_bfloat16 h, l; split_bf16(v, h, l);
        cth[si] = h;
        ctl[si] = l;

        float ss = v*v;
        #pragma unroll
        for (int o = 16; o; o >>= 1) ss += __shfl_xor_sync(0xffffffffu, ss, o);
        __shared__ float sq2[8];
        if ((t & 31) == 0) sq2[t>>5] = ss;
        __syncthreads();
        if (t == 0){
            float a = 0.f;
            for (int w = 0; w < 8; ++w) a += sq2[w];
            ccol[r] = a / (float)M_TOK;
        }
    }
}

// ---------------- IPOT: 4-CTA cluster; dual-job; smem-transpose row reduction ----------------
#define IPOT_DSM (196*65*4)

__global__ void __cluster_dims__(4,1,1) __launch_bounds__(256,1)
ipot_kernel(const float* __restrict__ Cw, const float* __restrict__ Cg, int nbW,
            float* __restrict__ ToutW, float* __restrict__ ToutG,
            __nv_bfloat16* __restrict__ Gh, __nv_bfloat16* __restrict__ Gl,
            float* __restrict__ dotW)
{
    extern __shared__ float s_q[];   // [196][65]
    cg::cluster_group cluster = cg::this_cluster();
    const int rank = blockIdx.x;
    const int by   = blockIdx.y;
    const bool wdJob = by < nbW;
    const int b    = wdJob ? by : (by - nbW);
    const int tid  = threadIdx.x;
    const int jl   = tid & 63;
    const int rq   = tid >> 6;
    const int lane = tid & 31;
    const int wid  = tid >> 5;
    const int jg   = rank*64 + jl;
    const float* C = (wdJob ? Cw : Cg) + (size_t)b * NM;

    float thr = 0.f;
    if (wdJob){
        const float mn = dec_mono(g_minmax[0]);
        const float mx = dec_mono(g_minmax[1]);
        thr = mn + 0.1f*(mx - mn);
    }
    float* ToutF = wdJob ? (ToutW ? ToutW + (size_t)b*NM : nullptr)
                         : (ToutG ? ToutG + (size_t)b*NM : nullptr);

    __shared__ float s_delta[196];
    __shared__ float s_rowpart[2][196];
    __shared__ float s_col[4][64];
    __shared__ float s_dred[8];
    __shared__ float s_dotpart;

    float E[49], T[49];
    #pragma unroll
    for (int k = 0; k < 49; ++k){
        float c = fmaxf(C[(rq + 4*k)*M_TOK + jg] - thr, 0.f);
        E[k] = expf(-2.0f * c);
        T[k] = 1.0f;
    }
    float sig = 1.0f/256.0f;
    __syncthreads();

    for (int it = 0; it < 20; ++it){
        const int buf = it & 1;
        #pragma unroll
        for (int k = 0; k < 49; ++k)
            s_q[(rq + 4*k)*65 + jl] = E[k]*T[k]*sig;
        __syncthreads();
        if (tid < 196){
            const float* row = s_q + tid*65;
            float a0 = 0.f, a1 = 0.f, a2 = 0.f, a3 = 0.f;
            #pragma unroll
            for (int c = 0; c < 64; c += 4){
                a0 += row[c];
                a1 += row[c+1];
                a2 += row[c+2];
                a3 += row[c+3];
            }
            s_rowpart[buf][tid] = (a0 + a1) + (a2 + a3);
        }
        cluster.sync();
        if (tid < 196){
            float s = 0.f;
            #pragma unroll
            for (int r = 0; r < 4; ++r)
                s += *(cluster.map_shared_rank(&s_rowpart[buf][0], r) + tid);
            s_delta[tid] = 1.0f / (196.0f * s);
        }
        __syncthreads();
        float cs = 0.f;
        #pragma unroll
        for (int k = 0; k < 49; ++k)
            cs += E[k]*T[k]*s_delta[rq + 4*k];
        s_col[rq][jl] = cs;
        __syncthreads();
        {
            float c = s_col[0][jl] + s_col[1][jl] + s_col[2][jl] + s_col[3][jl];
            sig = 1.0f / (256.0f * c);
        }
        #pragma unroll
        for (int k = 0; k < 49; ++k)
            T[k] = s_delta[rq + 4*k] * E[k] * T[k] * sig;
    }

    if (ToutF){
        #pragma unroll
        for (int k = 0; k < 49; ++k)
            ToutF[(size_t)(rq + 4*k)*M_TOK + jg] = T[k];
    }
    if (!wdJob){
        const size_t base = (size_t)b * NM;
        #pragma unroll
        for (int k = 0; k < 49; ++k){
            __nv_bfloat16 h, l; split_bf16(T[k], h, l);
            const size_t o = base + (size_t)(rq + 4*k)*M_TOK + jg;
            Gh[o] = h; Gl[o] = l;
        }
    }

    if (wdJob && dotW){
        float dot = 0.f;
        #pragma unroll
        for (int k = 0; k < 49; ++k)
            dot += fmaxf(C[(rq + 4*k)*M_TOK + jg] - thr, 0.f) * T[k];
        #pragma unroll
        for (int o = 16; o; o >>= 1) dot += __shfl_xor_sync(0xffffffffu, dot, o);
        if (lane == 0) s_dred[wid] = dot;
        __syncthreads();
        if (tid == 0){
            float t = 0.f;
            for (int w = 0; w < 8; ++w) t += s_dred[w];
            s_dotpart = t;
        }
        cluster.sync();
        if (rank == 0 && tid == 0){
            float t = 0.f;
            #pragma unroll
            for (int r = 0; r < 4; ++r)
                t += *cluster.map_shared_rank(&s_dotpart, r);
            dotW[b] = t;
        }
    }
    cluster.sync();
}

__global__ void final_kernel(float* __restrict__ outp){
    int t = threadIdx.x;
    float wd = g_dotwd[t];
    float gw = g_dotgw[t];
    #pragma unroll
    for (int o = 16; o; o >>= 1){
        wd += __shfl_xor_sync(0xffffffffu, wd, o);
        gw += __shfl_xor_sync(0xffffffffu, gw, o);
    }
    if (t == 0)
        outp[0] = 0.1f*(gw * (1.0f/B_)) - 0.1f*(wd * (1.0f/B_));
}

// ---------------- host launcher ----------------
extern "C" void kernel_launch(void* const* d_in, const int* in_sizes, int n_in,
                              void* d_out, int out_size)
{
    const float* img     = (const float*)d_in[0];
    const float* tok     = (const float*)d_in[1];
    const float* tokmask = (const float*)d_in[2];
    const int*   tdm     = (const int*)d_in[3];
    const int*   irm     = (const int*)d_in[4];
    float* out = (float*)d_out;                    // [1 | T_wd | T_gwd]
    float* outTwd  = out + 1;
    float* outTgwd = out + 1 + (size_t)B_*NM;

    __nv_bfloat16 *xh, *xl, *yh, *yl, *csh, *csl, *cth, *ctl, *gh, *gl, *th, *tl;
    float *Cxy, *Cs, *Ct, *Cg, *crow, *ccol, *dwd, *dgw;
    cudaGetSymbolAddress((void**)&xh,  g_xh);
    cudaGetSymbolAddress((void**)&xl,  g_xl);
    cudaGetSymbolAddress((void**)&yh,  g_yh);
    cudaGetSymbolAddress((void**)&yl,  g_yl);
    cudaGetSymbolAddress((void**)&csh, g_Csh);
    cudaGetSymbolAddress((void**)&csl, g_Csl);
    cudaGetSymbolAddress((void**)&cth, g_Cth);
    cudaGetSymbolAddress((void**)&ctl, g_Ctl);
    cudaGetSymbolAddress((void**)&gh,  g_gamh);
    cudaGetSymbolAddress((void**)&gl,  g_gaml);
    cudaGetSymbolAddress((void**)&th,  g_tmph);
    cudaGetSymbolAddress((void**)&tl,  g_tmpl);
    cudaGetSymbolAddress((void**)&Cxy, g_Cxy);
    cudaGetSymbolAddress((void**)&Cs,  g_Cs);
    cudaGetSymbolAddress((void**)&Ct,  g_Ct);
    cudaGetSymbolAddress((void**)&Cg,  g_Cg);
    cudaGetSymbolAddress((void**)&crow, g_cstrow);
    cudaGetSymbolAddress((void**)&ccol, g_cstcol);
    cudaGetSymbolAddress((void**)&dwd, g_dotwd);
    cudaGetSymbolAddress((void**)&dgw, g_dotgw);

    cudaFuncSetAttribute(cosmma_kernel,  cudaFuncAttributeMaxDynamicSharedMemorySize, COS_DSM);
    cudaFuncSetAttribute(gwfused_kernel, cudaFuncAttributeMaxDynamicSharedMemorySize, GWF_DSM);
    cudaFuncSetAttribute(gwmma2_kernel,  cudaFuncAttributeMaxDynamicSharedMemorySize, GW2_DSM);
    cudaFuncSetAttribute(ipot_kernel,    cudaFuncAttributeMaxDynamicSharedMemorySize, IPOT_DSM);

    normalize_kernel<<<B_*(N_IMG+M_TOK), 256>>>(img, tok, tokmask, xh, xl, yh, yl);

    cosmma_kernel<<<dim3(24,1,B_), 256, COS_DSM>>>(xh, xl, yh, yl, Cxy, Cs, Ct);

    fusedC_kernel<<<B_*(N_IMG+M_TOK), 256>>>(Cs, Ct, irm, tdm, csh, csl, cth, ctl,
                                             crow, ccol, th, tl);

    // iter0: tmp already = rowsum(Cs)/NM (from fusedC)
    gwmma2_kernel<<<dim3(2,4,B_), 256, GW2_DSM>>>(th, tl, cth, ctl, Cg, crow, ccol);

    // merged: WD ipot on Cxy (inline thresh) + gamma ipot on Cg
    ipot_kernel<<<dim3(4, 2*B_), 256, IPOT_DSM>>>(Cxy, Cg, B_, outTwd, nullptr, gh, gl, dwd);

    for (int it = 1; it < 6; ++it){
        const bool last = (it == 5);
        gwfused_kernel<<<dim3(4,1,B_), 256, GWF_DSM>>>(csh, csl, gh, gl, cth, ctl,
                                                       Cg, crow, ccol,
                                                       last ? outTgwd : nullptr, dgw);
        if (it < 5)
            ipot_kernel<<<dim3(4,B_), 256, IPOT_DSM>>>(nullptr, Cg, 0, nullptr,
                                             (it == 4) ? outTgwd : nullptr, gh, gl, nullptr);
    }

    final_kernel<<<1, 32>>>(out);
}

// round 15
// speedup vs baseline: 1.2903x; 1.0693x over previous
#include <cuda_runtime.h>
#include <cuda_bf16.h>
#include <cuda_fp16.h>
#include <cooperative_groups.h>
#include <math.h>

namespace cg = cooperative_groups;

#define B_    32
#define N_IMG 196
#define M_TOK 256
#define D_    1024
#define NM    (N_IMG*M_TOK)
#define KPAD  224

// ---------------- device scratch (allocation-free) ----------------
__device__ __half g_xh[B_*N_IMG*D_];
__device__ __half g_xl[B_*N_IMG*D_];
__device__ __half g_yh[B_*M_TOK*D_];
__device__ __half g_yl[B_*M_TOK*D_];
__device__ float g_Cxy[B_*NM];
__device__ float g_Cs [B_*N_IMG*N_IMG];
__device__ float g_Ct [B_*M_TOK*M_TOK];
__device__ __nv_bfloat16 g_Csh[B_*N_IMG*KPAD];
__device__ __nv_bfloat16 g_Csl[B_*N_IMG*KPAD];
__device__ __nv_bfloat16 g_Cth[B_*M_TOK*M_TOK];
__device__ __nv_bfloat16 g_Ctl[B_*M_TOK*M_TOK];
__device__ __nv_bfloat16 g_gamh[B_*NM];
__device__ __nv_bfloat16 g_gaml[B_*NM];
__device__ __nv_bfloat16 g_tmph[B_*NM];
__device__ __nv_bfloat16 g_tmpl[B_*NM];
__device__ float g_Cg[B_*NM];
__device__ float g_cstrow[B_*N_IMG];
__device__ float g_cstcol[B_*M_TOK];
__device__ unsigned g_minmax[6];
__device__ float g_dotwd[B_];
__device__ float g_dotgw[B_];

__device__ __forceinline__ unsigned enc_mono(float f){
    unsigned u = __float_as_uint(f);
    return (u & 0x80000000u) ? ~u : (u | 0x80000000u);
}
__device__ __forceinline__ float dec_mono(unsigned e){
    unsigned u = (e & 0x80000000u) ? (e ^ 0x80000000u) : ~e;
    return __uint_as_float(u);
}
__device__ __forceinline__ uint32_t smem_u32(const void* p){
    uint32_t a;
    asm("{ .reg .u64 t; cvta.to.shared.u64 t, %1; cvt.u32.u64 %0, t; }" : "=r"(a) : "l"(p));
    return a;
}
__device__ __forceinline__ void ldm_x4(unsigned* r, uint32_t addr){
    asm volatile("ldmatrix.sync.aligned.m8n8.x4.shared.b16 {%0,%1,%2,%3}, [%4];"
        : "=r"(r[0]), "=r"(r[1]), "=r"(r[2]), "=r"(r[3]) : "r"(addr));
}
__device__ __forceinline__ void ldm_x4_t(unsigned* r, uint32_t addr){
    asm volatile("ldmatrix.sync.aligned.m8n8.x4.trans.shared.b16 {%0,%1,%2,%3}, [%4];"
        : "=r"(r[0]), "=r"(r[1]), "=r"(r[2]), "=r"(r[3]) : "r"(addr));
}
__device__ __forceinline__ void mma_bf16(float* d, const unsigned* a, unsigned b0, unsigned b1){
    asm volatile("mma.sync.aligned.m16n8k16.row.col.f32.bf16.bf16.f32 "
        "{%0,%1,%2,%3}, {%4,%5,%6,%7}, {%8,%9}, {%0,%1,%2,%3};"
        : "+f"(d[0]), "+f"(d[1]), "+f"(d[2]), "+f"(d[3])
        : "r"(a[0]), "r"(a[1]), "r"(a[2]), "r"(a[3]), "r"(b0), "r"(b1));
}
__device__ __forceinline__ void mma_f16(float* d, const unsigned* a, unsigned b0, unsigned b1){
    asm volatile("mma.sync.aligned.m16n8k16.row.col.f32.f16.f16.f32 "
        "{%0,%1,%2,%3}, {%4,%5,%6,%7}, {%8,%9}, {%0,%1,%2,%3};"
        : "+f"(d[0]), "+f"(d[1]), "+f"(d[2]), "+f"(d[3])
        : "r"(a[0]), "r"(a[1]), "r"(a[2]), "r"(a[3]), "r"(b0), "r"(b1));
}
__device__ __forceinline__ void split_bf16(float v, __nv_bfloat16& h, __nv_bfloat16& l){
    h = __float2bfloat16(v);
    l = __float2bfloat16(v - __bfloat162float(h));
}
__device__ __forceinline__ void split_f16(float v, __half& h, __half& l){
    h = __float2half(v);
    l = __float2half(v - __half2float(h));
}
__device__ __forceinline__ void cp16(uint32_t d, const void* s, bool v){
    int sz = v ? 16 : 0;
    asm volatile("cp.async.ca.shared.global [%0], [%1], 16, %2;" :: "r"(d), "l"(s), "r"(sz));
}
#define CP_COMMIT() asm volatile("cp.async.commit_group;" ::: "memory")
#define CP_WAIT1()  asm volatile("cp.async.wait_group 1;" ::: "memory")
#define CP_WAIT0()  asm volatile("cp.async.wait_group 0;" ::: "memory")

// ---------------- single-pass normalize (fp16 hi/lo) + inlined init ----------------
__global__ void normalize_kernel(const float* __restrict__ img,
                                 const float* __restrict__ tok,
                                 const float* __restrict__ tokmask,
                                 __half* __restrict__ xh, __half* __restrict__ xl,
                                 __half* __restrict__ yh, __half* __restrict__ yl)
{
    const int gb = blockIdx.x;
    const int t  = threadIdx.x;

    if (gb == 0 && t < 64){
        if (t < 3){ g_minmax[2*t] = 0xFFFFFFFFu; g_minmax[2*t+1] = 0u; }
        if (t < B_) g_dotgw[t] = 0.f;
    }

    const bool isTok = gb >= B_*N_IMG;
    const int bp = isTok ? (gb - B_*N_IMG) : gb;
    const float* v = (isTok ? tok : img) + (size_t)bp * D_;
    float mk = 1.0f;
    if (isTok) mk = tokmask[bp];

    const float4 v4 = *reinterpret_cast<const float4*>(v + t*4);
    float t0 = v4.x * mk, t1 = v4.y * mk, t2 = v4.z * mk, t3 = v4.w * mk;

    float ss = t0*t0 + t1*t1 + t2*t2 + t3*t3;
    #pragma unroll
    for (int o = 16; o; o >>= 1) ss += __shfl_xor_sync(0xffffffffu, ss, o);
    __shared__ float sred[8];
    if ((t & 31) == 0) sred[t >> 5] = ss;
    __syncthreads();
    __shared__ float s_inv;
    if (t == 0){
        float a = 0.f;
        #pragma unroll
        for (int w = 0; w < 8; ++w) a += sred[w];
        s_inv = 1.0f / (sqrtf(a) + 1e-12f);
    }
    __syncthreads();
    const float scale = s_inv;

    __half h[4], l[4];
    split_f16(t0*scale, h[0], l[0]);
    split_f16(t1*scale, h[1], l[1]);
    split_f16(t2*scale, h[2], l[2]);
    split_f16(t3*scale, h[3], l[3]);

    __half* oh = (isTok ? yh : xh) + (size_t)bp * D_ + t*4;
    __half* ol = (isTok ? yl : xl) + (size_t)bp * D_ + t*4;
    *reinterpret_cast<uint2*>(oh) = *reinterpret_cast<const uint2*>(h);
    *reinterpret_cast<uint2*>(ol) = *reinterpret_cast<const uint2*>(l);
}

// ============ merged cosine GEMMs: fp16 2-MMA split (hh + h*lo), occ 2, 3-stage ============
// per-buffer (25600 B): AH[0,5120) BH[5120,15360) BL[15360,25600)
#define LDT 40
#define COS_DSM (3*25600)

__global__ void __launch_bounds__(256,2)
cosmma_kernel(const __half* __restrict__ xh, const __half* __restrict__ xl,
              const __half* __restrict__ yh, const __half* __restrict__ yl,
              float* __restrict__ Cxy, float* __restrict__ Cs, float* __restrict__ Ct)
{
    extern __shared__ char dyn[];
    const uint32_t sb = smem_u32(dyn);

    const int tile = blockIdx.x;
    const int which = tile >> 3;
    const int sub   = tile & 7;
    const int b     = blockIdx.z;
    const int m0    = (sub >> 1) * 64;
    const int j0    = (sub & 1) * 128;

    const __half* Ah = (which == 2) ? yh : xh;
    const __half* Bh = (which == 1) ? xh : yh;
    const __half* Bl = (which == 1) ? xl : yl;
    const int Mz = (which == 2) ? M_TOK : N_IMG;
    const int Nz = (which == 1) ? N_IMG : M_TOK;
    float* Cout = (which == 0) ? Cxy : ((which == 1) ? Cs : Ct);

    const int tid  = threadIdx.x;
    const int lane = tid & 31;
    const int wid  = tid >> 5;
    const int wm   = wid >> 2;
    const int wn   = wid & 3;

    const size_t abase = (size_t)b * Mz * D_;
    const size_t bbase = (size_t)b * Nz * D_;

    const int a_row = tid >> 2, a_quad = tid & 3;
    const bool avalid = (m0 + a_row) < Mz;
    const uint32_t aoff = (uint32_t)((a_row*LDT + a_quad*8) * 2);

    const int arow_l = lane & 15, ahalf = lane >> 4;
    const int bg = lane >> 3;
    const int b_noff = ((bg >> 1) << 3) + (lane & 7);
    const int b_koff = (bg & 1) << 3;

    float acc[2][4][4];
    #pragma unroll
    for (int mt = 0; mt < 2; ++mt)
        #pragma unroll
        for (int nt = 0; nt < 4; ++nt)
            #pragma unroll
            for (int q = 0; q < 4; ++q) acc[mt][nt][q] = 0.f;

    auto issue_tile = [&](int kc, int buf){
        const uint32_t base = sb + (uint32_t)buf*25600u;
        {
            const size_t go = abase + (size_t)(m0 + a_row)*D_ + kc*32 + a_quad*8;
            const size_t gs = avalid ? go : abase;
            cp16(base + aoff, Ah + gs, avalid);
        }
        #pragma unroll
        for (int p = 0; p < 2; ++p){
            int idx = tid + p*256;
            int row = idx >> 2, quad = idx & 3;
            const bool bv = (j0 + row) < Nz;
            const size_t go = bbase + (size_t)(j0 + row)*D_ + kc*32 + quad*8;
            const size_t gs = bv ? go : bbase;
            const uint32_t so = (uint32_t)((row*LDT + quad*8) * 2);
            cp16(base + 5120u + so, Bh + gs, bv);
            cp16(base + 15360u + so, Bl + gs, bv);
        }
        CP_COMMIT();
    };

    issue_tile(0, 0);
    issue_tile(1, 1);
    for (int kc = 0; kc < 32; ++kc){
        if (kc == 31){ CP_WAIT0(); } else { CP_WAIT1(); }
        __syncthreads();
        if (kc + 2 < 32) issue_tile(kc + 2, (kc + 2) % 3);

        const uint32_t base = sb + (uint32_t)(kc % 3)*25600u;
        const uint32_t baAh = base;
        const uint32_t baBh = base + 5120u;
        const uint32_t baBl = base + 15360u;

        #pragma unroll
        for (int k16 = 0; k16 < 2; ++k16){
            unsigned ah[2][4], bh[2][4], bl[2][4];
            #pragma unroll
            for (int mt = 0; mt < 2; ++mt){
                uint32_t off = (uint32_t)(((wm*32 + mt*16 + arow_l)*LDT + k16*16 + ahalf*8) * 2);
                ldm_x4(ah[mt], baAh + off);
            }
            #pragma unroll
            for (int nt2 = 0; nt2 < 2; ++nt2){
                uint32_t off = (uint32_t)(((wn*32 + nt2*16 + b_noff)*LDT + k16*16 + b_koff) * 2);
                ldm_x4(bh[nt2], baBh + off);
                ldm_x4(bl[nt2], baBl + off);
            }
            #pragma unroll
            for (int mt = 0; mt < 2; ++mt)
                #pragma unroll
                for (int nt = 0; nt < 4; ++nt){
                    const int p2 = nt >> 1, s2 = (nt & 1) * 2;
                    mma_f16(acc[mt][nt], ah[mt], bh[p2][s2], bh[p2][s2+1]);
                    mma_f16(acc[mt][nt], ah[mt], bl[p2][s2], bl[p2][s2+1]);
                }
        }
    }

    float lmin =  3.402823466e+38f;
    float lmax = -3.402823466e+38f;
    #pragma unroll
    for (int mt = 0; mt < 2; ++mt){
        #pragma unroll
        for (int nt = 0; nt < 4; ++nt){
            const int ibase = m0 + wm*32 + mt*16 + (lane >> 2);
            const int jbase = j0 + wn*32 + nt*8 + (lane & 3)*2;
            #pragma unroll
            for (int rr = 0; rr < 2; ++rr){
                int i = ibase + rr*8;
                if (i >= Mz) continue;
                float* crow = Cout + ((size_t)b*Mz + i)*Nz;
                #pragma unroll
                for (int cc = 0; cc < 2; ++cc){
                    int j = jbase + cc;
                    if (j >= Nz) continue;
                    float v = 1.0f - acc[mt][nt][rr*2 + cc];
                    crow[j] = v;
                    lmin = fminf(lmin, v);
                    lmax = fmaxf(lmax, v);
                }
            }
        }
    }
    #pragma unroll
    for (int o = 16; o; o >>= 1){
        lmin = fminf(lmin, __shfl_xor_sync(0xffffffffu, lmin, o));
        lmax = fmaxf(lmax, __shfl_xor_sync(0xffffffffu, lmax, o));
    }
    if (lane == 0){
        atomicMin(&g_minmax[2*which],   enc_mono(lmin));
        atomicMax(&g_minmax[2*which+1], enc_mono(lmax));
    }
}

// ============ FUSED GW chain (bf16 3-MMA, unchanged) ============
#define LDP 264
#define GWF_DSM 155648

__global__ void __launch_bounds__(256,1)
gwfused_kernel(const __nv_bfloat16* __restrict__ Csh, const __nv_bfloat16* __restrict__ Csl,
               const __nv_bfloat16* __restrict__ Gh,  const __nv_bfloat16* __restrict__ Gl,
               const __nv_bfloat16* __restrict__ Cth, const __nv_bfloat16* __restrict__ Ctl,
               float* __restrict__ Cout,
               const float* __restrict__ rowadd, const float* __restrict__ coladd,
               const float* __restrict__ gamF, float* __restrict__ dotOut)
{
    extern __shared__ char dyn[];
    const uint32_t sb = smem_u32(dyn);
    const uint32_t TMPH = sb + 88064u;
    const uint32_t TMPL = sb + 121856u;

    const int tid  = threadIdx.x;
    const int lane = tid & 31;
    const int wid  = tid >> 5;
    const int wm   = wid >> 2;
    const int wn   = wid & 3;
    const int b    = blockIdx.z;
    const int m0   = blockIdx.x * 64;

    const int a_row = tid >> 2, a_quad = tid & 3;
    const bool avalid = (m0 + a_row) < N_IMG;
    const uint32_t aoff = (uint32_t)((a_row*LDT + a_quad*8) * 2);

    const int arow_l = lane & 15, ahalf = lane >> 4;
    const int bg = lane >> 3;
    const int b_noff = ((bg >> 1) << 3) + (lane & 7);
    const int b_koff = (bg & 1) << 3;
    const int ktr = ((lane >> 3) & 1)*8 + (lane & 7);
    const int ntr = (lane >> 4)*8;

    float acc[2][8][4];
    #pragma unroll
    for (int mt = 0; mt < 2; ++mt)
        #pragma unroll
        for (int nt = 0; nt < 8; ++nt)
            #pragma unroll
            for (int q = 0; q < 4; ++q) acc[mt][nt][q] = 0.f;

    auto issue1 = [&](int kc, int buf){
        const int kbase = kc*32;
        {
            const size_t go = ((size_t)b*N_IMG + (m0 + a_row))*KPAD + kbase + a_quad*8;
            const size_t gs = avalid ? go : (size_t)b*N_IMG*KPAD;
            cp16(sb + buf*5120u + aoff, Csh + gs, avalid);
            cp16(sb + 10240u + buf*5120u + aoff, Csl + gs, avalid);
        }
        #pragma unroll
        for (int p = 0; p < 4; ++p){
            int idx = tid + p*256;
            int kk = idx >> 5, nn = (idx & 31)*8;
            const bool bv = (kbase + kk) < N_IMG;
            const size_t go = ((size_t)b*N_IMG + kbase + kk)*M_TOK + nn;
            const size_t gs = bv ? go : (size_t)b*NM;
            const uint32_t so = (uint32_t)((kk*LDP + nn) * 2);
            cp16(sb + 20480u + buf*16896u + so, Gh + gs, bv);
            cp16(sb + 54272u + buf*16896u + so, Gl + gs, bv);
        }
        CP_COMMIT();
    };

    issue1(0, 0);
    for (int kc = 0; kc < 7; ++kc){
        if (kc < 6){ issue1(kc+1, (kc+1)&1); CP_WAIT1(); }
        else       { CP_WAIT0(); }
        __syncthreads();

        const int buf = kc & 1;
        const uint32_t baAh = sb + buf*5120u;
        const uint32_t baAl = sb + 10240u + buf*5120u;
        const uint32_t baBh = sb + 20480u + buf*16896u;
        const uint32_t baBl = sb + 54272u + buf*16896u;

        #pragma unroll
        for (int k16 = 0; k16 < 2; ++k16){
            unsigned ah[2][4], al[2][4], bh[4][4], bl[4][4];
            #pragma unroll
            for (int mt = 0; mt < 2; ++mt){
                uint32_t off = (uint32_t)(((wm*32 + mt*16 + arow_l)*LDT + k16*16 + ahalf*8) * 2);
                ldm_x4(ah[mt], baAh + off);
                ldm_x4(al[mt], baAl + off);
            }
            #pragma unroll
            for (int nt2 = 0; nt2 < 4; ++nt2){
                uint32_t off = (uint32_t)(((k16*16 + ktr)*LDP + wn*64 + nt2*16 + ntr) * 2);
                ldm_x4_t(bh[nt2], baBh + off);
                ldm_x4_t(bl[nt2], baBl + off);
            }
            #pragma unroll
            for (int mt = 0; mt < 2; ++mt)
                #pragma unroll
                for (int nt = 0; nt < 8; ++nt){
                    const int p2 = nt >> 1, s2 = (nt & 1) * 2;
                    mma_bf16(acc[mt][nt], ah[mt], bh[p2][s2], bh[p2][s2+1]);
                    mma_bf16(acc[mt][nt], ah[mt], bl[p2][s2], bl[p2][s2+1]);
                    mma_bf16(acc[mt][nt], al[mt], bh[p2][s2], bh[p2][s2+1]);
                }
        }
        __syncthreads();
    }

    auto issue2 = [&](int kc, int buf){
        #pragma unroll
        for (int p = 0; p < 4; ++p){
            int idx = tid + p*256;
            int row = idx >> 2, quad = idx & 3;
            const size_t go = ((size_t)b*M_TOK + row)*M_TOK + kc*32 + quad*8;
            const uint32_t so = (uint32_t)((row*LDT + quad*8) * 2);
            cp16(sb + buf*20480u + so, Cth + go, true);
            cp16(sb + 40960u + buf*20480u + so, Ctl + go, true);
        }
        CP_COMMIT();
    };
    issue2(0, 0);

    #pragma unroll
    for (int mt = 0; mt < 2; ++mt){
        #pragma unroll
        for (int nt = 0; nt < 8; ++nt){
            const int il = wm*32 + mt*16 + (lane >> 2);
            const int jb = wn*64 + nt*8 + (lane & 3)*2;
            #pragma unroll
            for (int rr = 0; rr < 2; ++rr){
                const int i = il + rr*8;
                #pragma unroll
                for (int cc = 0; cc < 2; ++cc){
                    const int j = jb + cc;
                    __nv_bfloat16 h, l;
                    split_bf16(acc[mt][nt][rr*2 + cc], h, l);
                    *reinterpret_cast<__nv_bfloat16*>((char*)dyn + 88064u + (i*LDP + j)*2) = h;
                    *reinterpret_cast<__nv_bfloat16*>((char*)dyn + 121856u + (i*LDP + j)*2) = l;
                }
            }
        }
    }
    issue2(1, 1);
    __syncthreads();

    #pragma unroll
    for (int mt = 0; mt < 2; ++mt)
        #pragma unroll
        for (int nt = 0; nt < 8; ++nt)
            #pragma unroll
            for (int q = 0; q < 4; ++q) acc[mt][nt][q] = 0.f;

    for (int kc = 0; kc < 8; ++kc){
        if (kc < 7){ issue2(kc+1, (kc+1)&1); CP_WAIT1(); }
        else       { CP_WAIT0(); }
        __syncthreads();

        const int buf = kc & 1;
        const uint32_t baBh = sb + buf*20480u;
        const uint32_t baBl = sb + 40960u + buf*20480u;

        #pragma unroll
        for (int k16 = 0; k16 < 2; ++k16){
            unsigned ah[2][4], al[2][4], bh[4][4], bl[4][4];
            #pragma unroll
            for (int mt = 0; mt < 2; ++mt){
                uint32_t off = (uint32_t)(((wm*32 + mt*16 + arow_l)*LDP + kc*32 + k16*16 + ahalf*8) * 2);
                ldm_x4(ah[mt], TMPH + off);
                ldm_x4(al[mt], TMPL + off);
            }
            #pragma unroll
            for (int nt2 = 0; nt2 < 4; ++nt2){
                uint32_t off = (uint32_t)(((wn*64 + nt2*16 + b_noff)*LDT + k16*16 + b_koff) * 2);
                ldm_x4(bh[nt2], baBh + off);
                ldm_x4(bl[nt2], baBl + off);
            }
            #pragma unroll
            for (int mt = 0; mt < 2; ++mt)
                #pragma unroll
                for (int nt = 0; nt < 8; ++nt){
                    const int p2 = nt >> 1, s2 = (nt & 1) * 2;
                    mma_bf16(acc[mt][nt], ah[mt], bh[p2][s2], bh[p2][s2+1]);
                    mma_bf16(acc[mt][nt], ah[mt], bl[p2][s2], bl[p2][s2+1]);
                    mma_bf16(acc[mt][nt], al[mt], bh[p2][s2], bh[p2][s2+1]);
                }
        }
        __syncthreads();
    }

    float dot = 0.f;
    #pragma unroll
    for (int mt = 0; mt < 2; ++mt){
        #pragma unroll
        for (int nt = 0; nt < 8; ++nt){
            const int ibase = m0 + wm*32 + mt*16 + (lane >> 2);
            const int jbase = wn*64 + nt*8 + (lane & 3)*2;
            #pragma unroll
            for (int rr = 0; rr < 2; ++rr){
                int i = ibase + rr*8;
                if (i >= N_IMG) continue;
                const size_t ro = ((size_t)b*N_IMG + i)*M_TOK;
                const float ra = rowadd[b*N_IMG + i];
                #pragma unroll
                for (int cc = 0; cc < 2; ++cc){
                    int j = jbase + cc;
                    float r = ra + coladd[b*M_TOK + j] - 2.0f*acc[mt][nt][rr*2 + cc];
                    Cout[ro + j] = r;
                    if (gamF) dot += r * gamF[ro + j];
                }
            }
        }
    }
    if (gamF){
        #pragma unroll
        for (int o = 16; o; o >>= 1) dot += __shfl_xor_sync(0xffffffffu, dot, o);
        if (lane == 0) atomicAdd(&dotOut[b], dot);
    }
}

// ============ GW GEMM 2 standalone (iter0, bf16, unchanged) ============
#define GW2_DSM 61440

__global__ void __launch_bounds__(256,1)
gwmma2_kernel(const __nv_bfloat16* __restrict__ Ah, const __nv_bfloat16* __restrict__ Al,
              const __nv_bfloat16* __restrict__ Bh, const __nv_bfloat16* __restrict__ Bl,
              float* __restrict__ Cout,
              const float* __restrict__ rowadd, const float* __restrict__ coladd)
{
    extern __shared__ char dyn[];
    const uint32_t sb = smem_u32(dyn);

    const int tid  = threadIdx.x;
    const int lane = tid & 31;
    const int wid  = tid >> 5;
    const int wm   = wid >> 2;
    const int wn   = wid & 3;
    const int b    = blockIdx.z;
    const int m0   = blockIdx.y * 64;
    const int j0   = blockIdx.x * 128;

    const int a_row = tid >> 2, a_quad = tid & 3;
    const bool avalid = (m0 + a_row) < N_IMG;
    const uint32_t aoff = (uint32_t)((a_row*LDT + a_quad*8) * 2);

    const int arow_l = lane & 15, ahalf = lane >> 4;
    const int bg = lane >> 3;
    const int b_noff = ((bg >> 1) << 3) + (lane & 7);
    const int b_koff = (bg & 1) << 3;

    float acc[2][4][4];
    #pragma unroll
    for (int mt = 0; mt < 2; ++mt)
        #pragma unroll
        for (int nt = 0; nt < 4; ++nt)
            #pragma unroll
            for (int q = 0; q < 4; ++q) acc[mt][nt][q] = 0.f;

    auto issue_tile = [&](int kc, int buf){
        const uint32_t ah = sb + buf*5120u;
        const uint32_t al = sb + 10240u + buf*5120u;
        const uint32_t bh = sb + 20480u + buf*10240u;
        const uint32_t bl = sb + 40960u + buf*10240u;
        {
            const size_t go = ((size_t)b*N_IMG + (m0 + a_row))*M_TOK + kc*32 + a_quad*8;
            const size_t gs = avalid ? go : (size_t)b*NM;
            cp16(ah + aoff, Ah + gs, avalid);
            cp16(al + aoff, Al + gs, avalid);
        }
        #pragma unroll
        for (int p = 0; p < 2; ++p){
            int idx = tid + p*256;
            int row = idx >> 2, quad = idx & 3;
            const size_t go = ((size_t)b*M_TOK + j0 + row)*M_TOK + kc*32 + quad*8;
            const uint32_t so = (uint32_t)((row*LDT + quad*8) * 2);
            cp16(bh + so, Bh + go, true);
            cp16(bl + so, Bl + go, true);
        }
        CP_COMMIT();
    };

    issue_tile(0, 0);
    for (int kc = 0; kc < 8; ++kc){
        if (kc < 7){ issue_tile(kc+1, (kc+1)&1); CP_WAIT1(); }
        else       { CP_WAIT0(); }
        __syncthreads();

        const int buf = kc & 1;
        const uint32_t baAh = sb + buf*5120u;
        const uint32_t baAl = sb + 10240u + buf*5120u;
        const uint32_t baBh = sb + 20480u + buf*10240u;
        const uint32_t baBl = sb + 40960u + buf*10240u;

        #pragma unroll
        for (int k16 = 0; k16 < 2; ++k16){
            unsigned ah[2][4], al[2][4], bh[2][4], bl[2][4];
            #pragma unroll
            for (int mt = 0; mt < 2; ++mt){
                uint32_t off = (uint32_t)(((wm*32 + mt*16 + arow_l)*LDT + k16*16 + ahalf*8) * 2);
                ldm_x4(ah[mt], baAh + off);
                ldm_x4(al[mt], baAl + off);
            }
            #pragma unroll
            for (int nt2 = 0; nt2 < 2; ++nt2){
                uint32_t off = (uint32_t)(((wn*32 + nt2*16 + b_noff)*LDT + k16*16 + b_koff) * 2);
                ldm_x4(bh[nt2], baBh + off);
                ldm_x4(bl[nt2], baBl + off);
            }
            #pragma unroll
            for (int mt = 0; mt < 2; ++mt)
                #pragma unroll
                for (int nt = 0; nt < 4; ++nt){
                    const int p2 = nt >> 1, s2 = (nt & 1) * 2;
                    mma_bf16(acc[mt][nt], ah[mt], bh[p2][s2], bh[p2][s2+1]);
                    mma_bf16(acc[mt][nt], ah[mt], bl[p2][s2], bl[p2][s2+1]);
                    mma_bf16(acc[mt][nt], al[mt], bh[p2][s2], bh[p2][s2+1]);
                }
        }
        __syncthreads();
    }

    #pragma unroll
    for (int mt = 0; mt < 2; ++mt){
        #pragma unroll
        for (int nt = 0; nt < 4; ++nt){
            const int ibase = m0 + wm*32 + mt*16 + (lane >> 2);
            const int jbase = j0 + wn*32 + nt*8 + (lane & 3)*2;
            #pragma unroll
            for (int rr = 0; rr < 2; ++rr){
                int i = ibase + rr*8;
                if (i >= N_IMG) continue;
                const size_t ro = ((size_t)b*N_IMG + i)*M_TOK;
                const float ra = rowadd[b*N_IMG + i];
                #pragma unroll
                for (int cc = 0; cc < 2; ++cc){
                    int j = jbase + cc;
                    Cout[ro + j] = ra + coladd[b*M_TOK + j] - 2.0f*acc[mt][nt][rr*2 + cc];
                }
            }
        }
    }
}

// ---------------- merged fused Cs + Ct elementwise pass ----------------
__global__ void fusedC_kernel(float* __restrict__ Cs, float* __restrict__ Ct,
                              const int* __restrict__ irm, const int* __restrict__ tdm,
                              __nv_bfloat16* __restrict__ csh, __nv_bfloat16* __restrict__ csl,
                              __nv_bfloat16* __restrict__ cth, __nv_bfloat16* __restrict__ ctl,
                              float* __restrict__ crow, float* __restrict__ ccol,
                              __nv_bfloat16* __restrict__ tmph, __nv_bfloat16* __restrict__ tmpl)
{
    const int gb = blockIdx.x;
    const int t = threadIdx.x;

    if (gb < B_*N_IMG){
        const float mn = dec_mono(g_minmax[2]);
        const float mx = dec_mono(g_minmax[3]);
        const float thr = mn + 0.1f*(mx - mn);
        const int r = gb;

        float v = 0.f;
        if (t < N_IMG){
            size_t si = (size_t)r*N_IMG + t;
            v = Cs[si] - thr;
            v = v > 0.f ? v : 0.f;
            v *= (irm[si] == 1 ? 1.0f : 1e-5f);
            Cs[si] = v;
        }
        if (t < KPAD){
            __nv_bfloat16 h, l; split_bf16(v, h, l);
            csh[(size_t)r*KPAD + t] = h;
            csl[(size_t)r*KPAD + t] = l;
        }
        float ss = v*v, s1 = v;
        #pragma unroll
        for (int o = 16; o; o >>= 1){
            ss += __shfl_xor_sync(0xffffffffu, ss, o);
            s1 += __shfl_xor_sync(0xffffffffu, s1, o);
        }
        __shared__ float sq[8], sm[8];
        if ((t & 31) == 0){ sq[t>>5] = ss; sm[t>>5] = s1; }
        __syncthreads();
        __shared__ float s_val;
        if (t == 0){
            float a = 0.f, c = 0.f;
            for (int w = 0; w < 8; ++w){ a += sq[w]; c += sm[w]; }
            crow[r] = a / (float)N_IMG;
            s_val = c / (float)NM;
        }
        __syncthreads();
        __nv_bfloat16 h, l; split_bf16(s_val, h, l);
        tmph[(size_t)r*M_TOK + t] = h;
        tmpl[(size_t)r*M_TOK + t] = l;
    } else {
        const float mn = dec_mono(g_minmax[4]);
        const float mx = dec_mono(g_minmax[5]);
        const float thr = mn + 0.1f*(mx - mn);
        const int r = gb - B_*N_IMG;

        size_t si = (size_t)r*M_TOK + t;
        float v = Ct[si] - thr;
        v = v > 0.f ? v : 0.f;
        v *= (tdm[si] == 1 ? 1.0f : 1e-5f);
        Ct[si] = v;
        __nv_bfloat16 h, l; split_bf16(v, h, l);
        cth[si] = h;
        ctl[si] = l;

        float ss = v*v;
        #pragma unroll
        for (int o = 16; o; o >>= 1) ss += __shfl_xor_sync(0xffffffffu, ss, o);
        __shared__ float sq2[8];
        if ((t & 31) == 0) sq2[t>>5] = ss;
        __syncthreads();
        if (t == 0){
            float a = 0.f;
            for (int w = 0; w < 8; ++w) a += sq2[w];
            ccol[r] = a / (float)M_TOK;
        }
    }
}

// ---------------- IPOT: 4-CTA cluster; dual-job; smem-transpose row reduction ----------------
#define IPOT_DSM (196*65*4)

__global__ void __cluster_dims__(4,1,1) __launch_bounds__(256,1)
ipot_kernel(const float* __restrict__ Cw, const float* __restrict__ Cg, int nbW,
            float* __restrict__ ToutW, float* __restrict__ ToutG,
            __nv_bfloat16* __restrict__ Gh, __nv_bfloat16* __restrict__ Gl,
            float* __restrict__ dotW)
{
    extern __shared__ float s_q[];   // [196][65]
    cg::cluster_group cluster = cg::this_cluster();
    const int rank = blockIdx.x;
    const int by   = blockIdx.y;
    const bool wdJob = by < nbW;
    const int b    = wdJob ? by : (by - nbW);
    const int tid  = threadIdx.x;
    const int jl   = tid & 63;
    const int rq   = tid >> 6;
    const int lane = tid & 31;
    const int wid  = tid >> 5;
    const int jg   = rank*64 + jl;
    const float* C = (wdJob ? Cw : Cg) + (size_t)b * NM;

    float thr = 0.f;
    if (wdJob){
        const float mn = dec_mono(g_minmax[0]);
        const float mx = dec_mono(g_minmax[1]);
        thr = mn + 0.1f*(mx - mn);
    }
    float* ToutF = wdJob ? (ToutW ? ToutW + (size_t)b*NM : nullptr)
                         : (ToutG ? ToutG + (size_t)b*NM : nullptr);

    __shared__ float s_delta[196];
    __shared__ float s_rowpart[2][196];
    __shared__ float s_col[4][64];
    __shared__ float s_dred[8];
    __shared__ float s_dotpart;

    float E[49], T[49];
    #pragma unroll
    for (int k = 0; k < 49; ++k){
        float c = fmaxf(C[(rq + 4*k)*M_TOK + jg] - thr, 0.f);
        E[k] = expf(-2.0f * c);
        T[k] = 1.0f;
    }
    float sig = 1.0f/256.0f;
    __syncthreads();

    for (int it = 0; it < 20; ++it){
        const int buf = it & 1;
        #pragma unroll
        for (int k = 0; k < 49; ++k)
            s_q[(rq + 4*k)*65 + jl] = E[k]*T[k]*sig;
        __syncthreads();
        if (tid < 196){
            const float* row = s_q + tid*65;
            float a0 = 0.f, a1 = 0.f, a2 = 0.f, a3 = 0.f;
            #pragma unroll
            for (int c = 0; c < 64; c += 4){
                a0 += row[c];
                a1 += row[c+1];
                a2 += row[c+2];
                a3 += row[c+3];
            }
            s_rowpart[buf][tid] = (a0 + a1) + (a2 + a3);
        }
        cluster.sync();
        if (tid < 196){
            float s = 0.f;
            #pragma unroll
            for (int r = 0; r < 4; ++r)
                s += *(cluster.map_shared_rank(&s_rowpart[buf][0], r) + tid);
            s_delta[tid] = 1.0f / (196.0f * s);
        }
        __syncthreads();
        float cs = 0.f;
        #pragma unroll
        for (int k = 0; k < 49; ++k)
            cs += E[k]*T[k]*s_delta[rq + 4*k];
        s_col[rq][jl] = cs;
        __syncthreads();
        {
            float c = s_col[0][jl] + s_col[1][jl] + s_col[2][jl] + s_col[3][jl];
            sig = 1.0f / (256.0f * c);
        }
        #pragma unroll
        for (int k = 0; k < 49; ++k)
            T[k] = s_delta[rq + 4*k] * E[k] * T[k] * sig;
    }

    if (ToutF){
        #pragma unroll
        for (int k = 0; k < 49; ++k)
            ToutF[(size_t)(rq + 4*k)*M_TOK + jg] = T[k];
    }
    if (!wdJob){
        const size_t base = (size_t)b * NM;
        #pragma unroll
        for (int k = 0; k < 49; ++k){
            __nv_bfloat16 h, l; split_bf16(T[k], h, l);
            const size_t o = base + (size_t)(rq + 4*k)*M_TOK + jg;
            Gh[o] = h; Gl[o] = l;
        }
    }

    if (wdJob && dotW){
        float dot = 0.f;
        #pragma unroll
        for (int k = 0; k < 49; ++k)
            dot += fmaxf(C[(rq + 4*k)*M_TOK + jg] - thr, 0.f) * T[k];
        #pragma unroll
        for (int o = 16; o; o >>= 1) dot += __shfl_xor_sync(0xffffffffu, dot, o);
        if (lane == 0) s_dred[wid] = dot;
        __syncthreads();
        if (tid == 0){
            float t = 0.f;
            for (int w = 0; w < 8; ++w) t += s_dred[w];
            s_dotpart = t;
        }
        cluster.sync();
        if (rank == 0 && tid == 0){
            float t = 0.f;
            #pragma unroll
            for (int r = 0; r < 4; ++r)
                t += *cluster.map_shared_rank(&s_dotpart, r);
            dotW[b] = t;
        }
    }
    cluster.sync();
}

__global__ void final_kernel(float* __restrict__ outp){
    int t = threadIdx.x;
    float wd = g_dotwd[t];
    float gw = g_dotgw[t];
    #pragma unroll
    for (int o = 16; o; o >>= 1){
        wd += __shfl_xor_sync(0xffffffffu, wd, o);
        gw += __shfl_xor_sync(0xffffffffu, gw, o);
    }
    if (t == 0)
        outp[0] = 0.1f*(gw * (1.0f/B_)) - 0.1f*(wd * (1.0f/B_));
}

// ---------------- host launcher ----------------
extern "C" void kernel_launch(void* const* d_in, const int* in_sizes, int n_in,
                              void* d_out, int out_size)
{
    const float* img     = (const float*)d_in[0];
    const float* tok     = (const float*)d_in[1];
    const float* tokmask = (const float*)d_in[2];
    const int*   tdm     = (const int*)d_in[3];
    const int*   irm     = (const int*)d_in[4];
    float* out = (float*)d_out;                    // [1 | T_wd | T_gwd]
    float* outTwd  = out + 1;
    float* outTgwd = out + 1 + (size_t)B_*NM;

    __half *xh, *xl, *yh, *yl;
    __nv_bfloat16 *csh, *csl, *cth, *ctl, *gh, *gl, *th, *tl;
    float *Cxy, *Cs, *Ct, *Cg, *crow, *ccol, *dwd, *dgw;
    cudaGetSymbolAddress((void**)&xh,  g_xh);
    cudaGetSymbolAddress((void**)&xl,  g_xl);
    cudaGetSymbolAddress((void**)&yh,  g_yh);
    cudaGetSymbolAddress((void**)&yl,  g_yl);
    cudaGetSymbolAddress((void**)&csh, g_Csh);
    cudaGetSymbolAddress((void**)&csl, g_Csl);
    cudaGetSymbolAddress((void**)&cth, g_Cth);
    cudaGetSymbolAddress((void**)&ctl, g_Ctl);
    cudaGetSymbolAddress((void**)&gh,  g_gamh);
    cudaGetSymbolAddress((void**)&gl,  g_gaml);
    cudaGetSymbolAddress((void**)&th,  g_tmph);
    cudaGetSymbolAddress((void**)&tl,  g_tmpl);
    cudaGetSymbolAddress((void**)&Cxy, g_Cxy);
    cudaGetSymbolAddress((void**)&Cs,  g_Cs);
    cudaGetSymbolAddress((void**)&Ct,  g_Ct);
    cudaGetSymbolAddress((void**)&Cg,  g_Cg);
    cudaGetSymbolAddress((void**)&crow, g_cstrow);
    cudaGetSymbolAddress((void**)&ccol, g_cstcol);
    cudaGetSymbolAddress((void**)&dwd, g_dotwd);
    cudaGetSymbolAddress((void**)&dgw, g_dotgw);

    cudaFuncSetAttribute(cosmma_kernel,  cudaFuncAttributeMaxDynamicSharedMemorySize, COS_DSM);
    cudaFuncSetAttribute(gwfused_kernel, cudaFuncAttributeMaxDynamicSharedMemorySize, GWF_DSM);
    cudaFuncSetAttribute(gwmma2_kernel,  cudaFuncAttributeMaxDynamicSharedMemorySize, GW2_DSM);
    cudaFuncSetAttribute(ipot_kernel,    cudaFuncAttributeMaxDynamicSharedMemorySize, IPOT_DSM);

    normalize_kernel<<<B_*(N_IMG+M_TOK), 256>>>(img, tok, tokmask, xh, xl, yh, yl);

    cosmma_kernel<<<dim3(24,1,B_), 256, COS_DSM>>>(xh, xl, yh, yl, Cxy, Cs, Ct);

    fusedC_kernel<<<B_*(N_IMG+M_TOK), 256>>>(Cs, Ct, irm, tdm, csh, csl, cth, ctl,
                                             crow, ccol, th, tl);

    // iter0: tmp already = rowsum(Cs)/NM (from fusedC)
    gwmma2_kernel<<<dim3(2,4,B_), 256, GW2_DSM>>>(th, tl, cth, ctl, Cg, crow, ccol);

    // merged: WD ipot on Cxy (inline thresh) + gamma ipot on Cg
    ipot_kernel<<<dim3(4, 2*B_), 256, IPOT_DSM>>>(Cxy, Cg, B_, outTwd, nullptr, gh, gl, dwd);

    for (int it = 1; it < 6; ++it){
        const bool last = (it == 5);
        gwfused_kernel<<<dim3(4,1,B_), 256, GWF_DSM>>>(csh, csl, gh, gl, cth, ctl,
                                                       Cg, crow, ccol,
                                                       last ? outTgwd : nullptr, dgw);
        if (it < 5)
            ipot_kernel<<<dim3(4,B_), 256, IPOT_DSM>>>(nullptr, Cg, 0, nullptr,
                                             (it == 4) ? outTgwd : nullptr, gh, gl, nullptr);
    }

    final_kernel<<<1, 32>>>(out);
}